// round 1
// baseline (speedup 1.0000x reference)
#include <cuda_runtime.h>
#include <cstddef>

#define B_   8
#define T_   1024
#define C_   1024
#define H_   16
#define HD_  64
#define BH_  (B_ * H_)          // 128
#define C3_  (3 * C_)           // 3072

// Scratch (static device globals — no allocation at kernel_launch time)
__device__ float g_qkv[(size_t)B_ * T_ * C3_];    // 96 MB
__device__ float g_S[(size_t)BH_ * T_ * T_];      // 512 MB
__device__ float g_Y[(size_t)B_ * T_ * C_];       // 32 MB

// ---------------------------------------------------------------------------
// Generic SGEMM: C[M,N] = A[M,K] * B[K,N] + bias[N]
// BM=128, BN=128, BK=16, 256 threads, 8x8 per-thread (2x2 quads of 4x4)
// ---------------------------------------------------------------------------
__global__ __launch_bounds__(256) void sgemm_bias_kernel(
    const float* __restrict__ A, const float* __restrict__ Bm,
    const float* __restrict__ bias, float* __restrict__ Cm,
    int M, int N, int K)
{
    __shared__ float As[16][128];   // transposed A tile: As[k][m]
    __shared__ float Bs[16][128];   // Bs[k][n]

    const int tid = threadIdx.x;
    const int tx  = tid & 15;       // 0..15 -> column quads
    const int ty  = tid >> 4;       // 0..15 -> row quads
    const int brow = blockIdx.y << 7;
    const int bcol = blockIdx.x << 7;

    float acc[8][8];
    #pragma unroll
    for (int i = 0; i < 8; i++)
        #pragma unroll
        for (int j = 0; j < 8; j++) acc[i][j] = 0.0f;

    for (int k0 = 0; k0 < K; k0 += 16) {
        // Load A tile (128x16) -> transposed smem. 512 float4 total, 2/thread.
        #pragma unroll
        for (int l = 0; l < 2; ++l) {
            int idx = tid + l * 256;
            int r   = idx >> 2;            // 0..127
            int c   = (idx & 3) << 2;      // 0,4,8,12
            float4 v = *(const float4*)(A + (size_t)(brow + r) * K + k0 + c);
            As[c + 0][r] = v.x; As[c + 1][r] = v.y;
            As[c + 2][r] = v.z; As[c + 3][r] = v.w;
        }
        // Load B tile (16x128). 512 float4 total, 2/thread.
        #pragma unroll
        for (int l = 0; l < 2; ++l) {
            int idx = tid + l * 256;
            int r   = idx >> 5;            // 0..15
            int c   = (idx & 31) << 2;     // 0..124
            *(float4*)&Bs[r][c] =
                *(const float4*)(Bm + (size_t)(k0 + r) * N + bcol + c);
        }
        __syncthreads();

        #pragma unroll
        for (int k = 0; k < 16; ++k) {
            float a[8], b[8];
            float4 a0 = *(const float4*)&As[k][ty << 2];
            float4 a1 = *(const float4*)&As[k][(ty << 2) + 64];
            float4 b0 = *(const float4*)&Bs[k][tx << 2];
            float4 b1 = *(const float4*)&Bs[k][(tx << 2) + 64];
            a[0]=a0.x; a[1]=a0.y; a[2]=a0.z; a[3]=a0.w;
            a[4]=a1.x; a[5]=a1.y; a[6]=a1.z; a[7]=a1.w;
            b[0]=b0.x; b[1]=b0.y; b[2]=b0.z; b[3]=b0.w;
            b[4]=b1.x; b[5]=b1.y; b[6]=b1.z; b[7]=b1.w;
            #pragma unroll
            for (int i = 0; i < 8; i++)
                #pragma unroll
                for (int j = 0; j < 8; j++)
                    acc[i][j] = fmaf(a[i], b[j], acc[i][j]);
        }
        __syncthreads();
    }

    // Epilogue: bias + vectorized stores
    float bi[8];
    {
        float4 bb0 = *(const float4*)(bias + bcol + (tx << 2));
        float4 bb1 = *(const float4*)(bias + bcol + (tx << 2) + 64);
        bi[0]=bb0.x; bi[1]=bb0.y; bi[2]=bb0.z; bi[3]=bb0.w;
        bi[4]=bb1.x; bi[5]=bb1.y; bi[6]=bb1.z; bi[7]=bb1.w;
    }
    #pragma unroll
    for (int i = 0; i < 8; i++) {
        int r = brow + (ty << 2) + ((i < 4) ? i : 60 + i);
        float4 o0, o1;
        o0.x = acc[i][0] + bi[0]; o0.y = acc[i][1] + bi[1];
        o0.z = acc[i][2] + bi[2]; o0.w = acc[i][3] + bi[3];
        o1.x = acc[i][4] + bi[4]; o1.y = acc[i][5] + bi[5];
        o1.z = acc[i][6] + bi[6]; o1.w = acc[i][7] + bi[7];
        *(float4*)&Cm[(size_t)r * N + bcol + (tx << 2)]      = o0;
        *(float4*)&Cm[(size_t)r * N + bcol + (tx << 2) + 64] = o1;
    }
}

// ---------------------------------------------------------------------------
// Scores: S[bh][q][k] = (1/8) * dot(Q[bh][q], K[bh][k]) over hd=64
// Block: 64x64 output tile, 256 threads, 4x4 per thread. Smem K-transposed.
// ---------------------------------------------------------------------------
__global__ __launch_bounds__(256) void scores_kernel(
    const float* __restrict__ qkv, float* __restrict__ S)
{
    __shared__ float Qt[HD_][68];   // Qt[d][q]   (68*4B stride: 16B aligned)
    __shared__ float Kt[HD_][68];   // Kt[d][k]

    const int bh = blockIdx.z;
    const int b  = bh >> 4;
    const int h  = bh & 15;
    const float* qbase = qkv + (size_t)b * T_ * C3_ + h * HD_;
    const float* kbase = qbase + C_;

    const int tid = threadIdx.x;
    const int tx  = tid & 15, ty = tid >> 4;
    const int q0  = blockIdx.y << 6;
    const int k0  = blockIdx.x << 6;

    #pragma unroll
    for (int l = 0; l < 4; ++l) {
        int idx = tid + l * 256;
        int r   = idx >> 4;          // 0..63
        int c   = (idx & 15) << 2;   // 0..60
        float4 q = *(const float4*)(qbase + (size_t)(q0 + r) * C3_ + c);
        float4 k = *(const float4*)(kbase + (size_t)(k0 + r) * C3_ + c);
        Qt[c + 0][r] = q.x; Qt[c + 1][r] = q.y; Qt[c + 2][r] = q.z; Qt[c + 3][r] = q.w;
        Kt[c + 0][r] = k.x; Kt[c + 1][r] = k.y; Kt[c + 2][r] = k.z; Kt[c + 3][r] = k.w;
    }
    __syncthreads();

    float acc[4][4];
    #pragma unroll
    for (int i = 0; i < 4; i++)
        #pragma unroll
        for (int j = 0; j < 4; j++) acc[i][j] = 0.0f;

    #pragma unroll
    for (int k = 0; k < HD_; ++k) {
        float4 qv = *(const float4*)&Qt[k][ty << 2];
        float4 kv = *(const float4*)&Kt[k][tx << 2];
        float q[4] = {qv.x, qv.y, qv.z, qv.w};
        float kk[4] = {kv.x, kv.y, kv.z, kv.w};
        #pragma unroll
        for (int i = 0; i < 4; i++)
            #pragma unroll
            for (int j = 0; j < 4; j++)
                acc[i][j] = fmaf(q[i], kk[j], acc[i][j]);
    }

    float* Sr = S + (size_t)bh * T_ * T_;
    #pragma unroll
    for (int i = 0; i < 4; i++) {
        float4 o;
        o.x = acc[i][0] * 0.125f; o.y = acc[i][1] * 0.125f;
        o.z = acc[i][2] * 0.125f; o.w = acc[i][3] * 0.125f;
        *(float4*)&Sr[(size_t)(q0 + (ty << 2) + i) * T_ + k0 + (tx << 2)] = o;
    }
}

// ---------------------------------------------------------------------------
// Row softmax + relu(p - 0.001), in place on S. One block per row.
// ---------------------------------------------------------------------------
__global__ __launch_bounds__(256) void softmax_thresh_kernel(float* __restrict__ S)
{
    const size_t row = (size_t)blockIdx.y * T_ + blockIdx.x;
    float* p = S + row * T_;
    const int tid = threadIdx.x;

    float4 v = ((const float4*)p)[tid];
    float m = fmaxf(fmaxf(v.x, v.y), fmaxf(v.z, v.w));
    #pragma unroll
    for (int o = 16; o > 0; o >>= 1)
        m = fmaxf(m, __shfl_xor_sync(0xFFFFFFFFu, m, o));

    __shared__ float redm[8], reds[8];
    if ((tid & 31) == 0) redm[tid >> 5] = m;
    __syncthreads();
    m = redm[0];
    #pragma unroll
    for (int i = 1; i < 8; i++) m = fmaxf(m, redm[i]);

    float4 e;
    e.x = __expf(v.x - m); e.y = __expf(v.y - m);
    e.z = __expf(v.z - m); e.w = __expf(v.w - m);
    float s = e.x + e.y + e.z + e.w;
    #pragma unroll
    for (int o = 16; o > 0; o >>= 1)
        s += __shfl_xor_sync(0xFFFFFFFFu, s, o);
    if ((tid & 31) == 0) reds[tid >> 5] = s;
    __syncthreads();
    s = reds[0];
    #pragma unroll
    for (int i = 1; i < 8; i++) s += reds[i];

    const float inv = 1.0f / s;
    e.x = fmaxf(e.x * inv - 0.001f, 0.0f);
    e.y = fmaxf(e.y * inv - 0.001f, 0.0f);
    e.z = fmaxf(e.z * inv - 0.001f, 0.0f);
    e.w = fmaxf(e.w * inv - 0.001f, 0.0f);
    ((float4*)p)[tid] = e;
}

// ---------------------------------------------------------------------------
// AV: Y[b][q][h*64+d] = sum_k Att[bh][q][k] * V[bh][k][d]
// Block: 64 q-rows x 64 d-cols (full hd), loop K in chunks of 64.
// ---------------------------------------------------------------------------
__global__ __launch_bounds__(256) void av_kernel(
    const float* __restrict__ S, const float* __restrict__ qkv,
    float* __restrict__ Y)
{
    __shared__ float At[64][68];    // At[k][q] (transposed att tile)
    __shared__ float Vs[64][68];    // Vs[k][d]

    const int bh = blockIdx.y;
    const int b  = bh >> 4;
    const int h  = bh & 15;
    const int q0 = blockIdx.x << 6;
    const float* Sr    = S + (size_t)bh * T_ * T_;
    const float* vbase = qkv + (size_t)b * T_ * C3_ + 2 * C_ + h * HD_;

    const int tid = threadIdx.x;
    const int tx  = tid & 15, ty = tid >> 4;

    float acc[4][4];
    #pragma unroll
    for (int i = 0; i < 4; i++)
        #pragma unroll
        for (int j = 0; j < 4; j++) acc[i][j] = 0.0f;

    for (int k0 = 0; k0 < T_; k0 += 64) {
        #pragma unroll
        for (int l = 0; l < 4; ++l) {
            int idx = tid + l * 256;
            int r   = idx >> 4;          // 0..63
            int c   = (idx & 15) << 2;   // 0..60
            float4 a = *(const float4*)(Sr + (size_t)(q0 + r) * T_ + k0 + c);
            At[c + 0][r] = a.x; At[c + 1][r] = a.y;
            At[c + 2][r] = a.z; At[c + 3][r] = a.w;
            *(float4*)&Vs[r][c] =
                *(const float4*)(vbase + (size_t)(k0 + r) * C3_ + c);
        }
        __syncthreads();

        #pragma unroll
        for (int k = 0; k < 64; ++k) {
            float4 av = *(const float4*)&At[k][ty << 2];
            float4 vv = *(const float4*)&Vs[k][tx << 2];
            float a[4] = {av.x, av.y, av.z, av.w};
            float v[4] = {vv.x, vv.y, vv.z, vv.w};
            #pragma unroll
            for (int i = 0; i < 4; i++)
                #pragma unroll
                for (int j = 0; j < 4; j++)
                    acc[i][j] = fmaf(a[i], v[j], acc[i][j]);
        }
        __syncthreads();
    }

    float* yb = Y + (size_t)b * T_ * C_ + h * HD_;
    #pragma unroll
    for (int i = 0; i < 4; i++) {
        float4 o;
        o.x = acc[i][0]; o.y = acc[i][1]; o.z = acc[i][2]; o.w = acc[i][3];
        *(float4*)&yb[(size_t)(q0 + (ty << 2) + i) * C_ + (tx << 2)] = o;
    }
}

// ---------------------------------------------------------------------------
extern "C" void kernel_launch(void* const* d_in, const int* in_sizes, int n_in,
                              void* d_out, int out_size)
{
    const float* x      = (const float*)d_in[0];   // (8,1024,4,256) == (8192,1024)
    const float* w_attn = (const float*)d_in[1];   // (1024,3072)
    const float* b_attn = (const float*)d_in[2];   // (3072,)
    const float* w_proj = (const float*)d_in[3];   // (1024,1024)
    const float* b_proj = (const float*)d_in[4];   // (1024,)
    float* out = (float*)d_out;                    // (8192,1024)

    float *qkv, *S, *Y;
    cudaGetSymbolAddress((void**)&qkv, g_qkv);
    cudaGetSymbolAddress((void**)&S,   g_S);
    cudaGetSymbolAddress((void**)&Y,   g_Y);

    // 1) QKV projection: (8192,1024)x(1024,3072)+b
    sgemm_bias_kernel<<<dim3(C3_ / 128, (B_ * T_) / 128), 256>>>(
        x, w_attn, b_attn, qkv, B_ * T_, C3_, C_);

    // 2) Scores: per (b,h) 1024x1024, tiles 64x64
    scores_kernel<<<dim3(T_ / 64, T_ / 64, BH_), 256>>>(qkv, S);

    // 3) Softmax + threshold (in place)
    softmax_thresh_kernel<<<dim3(T_, BH_), 256>>>(S);

    // 4) Att @ V -> Y in (B,T,C) layout
    av_kernel<<<dim3(T_ / 64, BH_), 256>>>(S, qkv, Y);

    // 5) Output projection: (8192,1024)x(1024,1024)+b -> out
    sgemm_bias_kernel<<<dim3(C_ / 128, (B_ * T_) / 128), 256>>>(
        Y, w_proj, b_proj, out, B_ * T_, C_, C_);
}

// round 2
// speedup vs baseline: 1.0524x; 1.0524x over previous
#include <cuda_runtime.h>
#include <cstddef>

#define B_   8
#define T_   1024
#define C_   1024
#define H_   16
#define HD_  64
#define BH_  (B_ * H_)          // 128
#define C3_  (3 * C_)           // 3072
#define TH_  0.001f

// Scratch (static device globals — no allocation at kernel_launch time)
__device__ float g_qkv[(size_t)B_ * T_ * C3_];    // 96 MB
__device__ float g_S[(size_t)BH_ * T_ * T_];      // 512 MB (exp scratch)
__device__ float g_Y[(size_t)B_ * T_ * C_];       // 32 MB

// ---------------------------------------------------------------------------
// Generic SGEMM: C[M,N] = A[M,K] * B[K,N] + bias[N]
// BM=128, BN=128, BK=16, 256 threads, 8x8 per-thread (2x2 quads of 4x4)
// ---------------------------------------------------------------------------
__global__ __launch_bounds__(256) void sgemm_bias_kernel(
    const float* __restrict__ A, const float* __restrict__ Bm,
    const float* __restrict__ bias, float* __restrict__ Cm,
    int M, int N, int K)
{
    __shared__ float As[16][128];   // transposed A tile: As[k][m]
    __shared__ float Bs[16][128];   // Bs[k][n]

    const int tid = threadIdx.x;
    const int tx  = tid & 15;
    const int ty  = tid >> 4;
    const int brow = blockIdx.y << 7;
    const int bcol = blockIdx.x << 7;

    float acc[8][8];
    #pragma unroll
    for (int i = 0; i < 8; i++)
        #pragma unroll
        for (int j = 0; j < 8; j++) acc[i][j] = 0.0f;

    for (int k0 = 0; k0 < K; k0 += 16) {
        #pragma unroll
        for (int l = 0; l < 2; ++l) {
            int idx = tid + l * 256;
            int r   = idx >> 2;
            int c   = (idx & 3) << 2;
            float4 v = *(const float4*)(A + (size_t)(brow + r) * K + k0 + c);
            As[c + 0][r] = v.x; As[c + 1][r] = v.y;
            As[c + 2][r] = v.z; As[c + 3][r] = v.w;
        }
        #pragma unroll
        for (int l = 0; l < 2; ++l) {
            int idx = tid + l * 256;
            int r   = idx >> 5;
            int c   = (idx & 31) << 2;
            *(float4*)&Bs[r][c] =
                *(const float4*)(Bm + (size_t)(k0 + r) * N + bcol + c);
        }
        __syncthreads();

        #pragma unroll
        for (int k = 0; k < 16; ++k) {
            float a[8], b[8];
            float4 a0 = *(const float4*)&As[k][ty << 2];
            float4 a1 = *(const float4*)&As[k][(ty << 2) + 64];
            float4 b0 = *(const float4*)&Bs[k][tx << 2];
            float4 b1 = *(const float4*)&Bs[k][(tx << 2) + 64];
            a[0]=a0.x; a[1]=a0.y; a[2]=a0.z; a[3]=a0.w;
            a[4]=a1.x; a[5]=a1.y; a[6]=a1.z; a[7]=a1.w;
            b[0]=b0.x; b[1]=b0.y; b[2]=b0.z; b[3]=b0.w;
            b[4]=b1.x; b[5]=b1.y; b[6]=b1.z; b[7]=b1.w;
            #pragma unroll
            for (int i = 0; i < 8; i++)
                #pragma unroll
                for (int j = 0; j < 8; j++)
                    acc[i][j] = fmaf(a[i], b[j], acc[i][j]);
        }
        __syncthreads();
    }

    float bi[8];
    {
        float4 bb0 = *(const float4*)(bias + bcol + (tx << 2));
        float4 bb1 = *(const float4*)(bias + bcol + (tx << 2) + 64);
        bi[0]=bb0.x; bi[1]=bb0.y; bi[2]=bb0.z; bi[3]=bb0.w;
        bi[4]=bb1.x; bi[5]=bb1.y; bi[6]=bb1.z; bi[7]=bb1.w;
    }
    #pragma unroll
    for (int i = 0; i < 8; i++) {
        int r = brow + (ty << 2) + ((i < 4) ? i : 60 + i);
        float4 o0, o1;
        o0.x = acc[i][0] + bi[0]; o0.y = acc[i][1] + bi[1];
        o0.z = acc[i][2] + bi[2]; o0.w = acc[i][3] + bi[3];
        o1.x = acc[i][4] + bi[4]; o1.y = acc[i][5] + bi[5];
        o1.z = acc[i][6] + bi[6]; o1.w = acc[i][7] + bi[7];
        *(float4*)&Cm[(size_t)r * N + bcol + (tx << 2)]      = o0;
        *(float4*)&Cm[(size_t)r * N + bcol + (tx << 2) + 64] = o1;
    }
}

// ---------------------------------------------------------------------------
// Fused attention: per (bh, 128-row q-block):
//  pass1: S = exp((Q K^T)/8) streamed tile-by-tile to scratch (L2-hot),
//         per-row sum l accumulated in registers (no max: scores ~N(0,1)).
//  pass2: P = relu(S * l^-1 - TH), Y = P V.
// ---------------------------------------------------------------------------
struct SmemAttn {
    float l_inv[128];
    union {
        struct { float Qt[64][132]; float Kt[64][132]; } p1;
        struct { float At[64][132]; float Vs[64][72];  } p2;
    } u;
};

__global__ __launch_bounds__(256, 1) void fused_attn_kernel(
    const float* __restrict__ qkv, float* __restrict__ scratch,
    float* __restrict__ Y)
{
    extern __shared__ char smem_raw[];
    SmemAttn& sm = *reinterpret_cast<SmemAttn*>(smem_raw);

    const int qb = blockIdx.x;       // 0..7
    const int bh = blockIdx.y;       // 0..127
    const int b  = bh >> 4;
    const int h  = bh & 15;
    const float* qbase = qkv + (size_t)b * T_ * C3_ + h * HD_;
    const float* kbase = qbase + C_;
    const float* vbase = qbase + 2 * C_;
    float* sc = scratch + (((size_t)bh * 8 + qb) << 17);   // [1024 k][128 q]

    const int tid = threadIdx.x;
    const int tx  = tid & 15;
    const int ty  = tid >> 4;
    const int q0  = qb << 7;

    // ---- load Q tile (128 q x 64 d), transposed -> Qt[d][q]
    #pragma unroll
    for (int l = 0; l < 8; ++l) {
        int idx = tid + (l << 8);
        int r   = idx >> 4;            // 0..127 (q)
        int c   = (idx & 15) << 2;     // 0..60 (d)
        float4 v = *(const float4*)(qbase + (size_t)(q0 + r) * C3_ + c);
        sm.u.p1.Qt[c + 0][r] = v.x; sm.u.p1.Qt[c + 1][r] = v.y;
        sm.u.p1.Qt[c + 2][r] = v.z; sm.u.p1.Qt[c + 3][r] = v.w;
    }

    float lsum[8];
    #pragma unroll
    for (int i = 0; i < 8; i++) lsum[i] = 0.0f;

    // ---- pass 1: k-tiles of 128
    for (int k0 = 0; k0 < T_; k0 += 128) {
        __syncthreads();   // prior-tile Kt reads done (also covers Qt on iter 0)
        #pragma unroll
        for (int l = 0; l < 8; ++l) {
            int idx = tid + (l << 8);
            int r   = idx >> 4;
            int c   = (idx & 15) << 2;
            float4 v = *(const float4*)(kbase + (size_t)(k0 + r) * C3_ + c);
            sm.u.p1.Kt[c + 0][r] = v.x; sm.u.p1.Kt[c + 1][r] = v.y;
            sm.u.p1.Kt[c + 2][r] = v.z; sm.u.p1.Kt[c + 3][r] = v.w;
        }
        __syncthreads();

        float acc[8][8];
        #pragma unroll
        for (int i = 0; i < 8; i++)
            #pragma unroll
            for (int j = 0; j < 8; j++) acc[i][j] = 0.0f;

        #pragma unroll 8
        for (int d = 0; d < HD_; ++d) {
            float a[8], bb[8];
            float4 a0 = *(const float4*)&sm.u.p1.Qt[d][ty << 2];
            float4 a1 = *(const float4*)&sm.u.p1.Qt[d][(ty << 2) + 64];
            float4 b0 = *(const float4*)&sm.u.p1.Kt[d][tx << 2];
            float4 b1 = *(const float4*)&sm.u.p1.Kt[d][(tx << 2) + 64];
            a[0]=a0.x; a[1]=a0.y; a[2]=a0.z; a[3]=a0.w;
            a[4]=a1.x; a[5]=a1.y; a[6]=a1.z; a[7]=a1.w;
            bb[0]=b0.x; bb[1]=b0.y; bb[2]=b0.z; bb[3]=b0.w;
            bb[4]=b1.x; bb[5]=b1.y; bb[6]=b1.z; bb[7]=b1.w;
            #pragma unroll
            for (int i = 0; i < 8; i++)
                #pragma unroll
                for (int j = 0; j < 8; j++)
                    acc[i][j] = fmaf(a[i], bb[j], acc[i][j]);
        }

        // exp, accumulate row sums, store transposed [k][q] to scratch
        #pragma unroll
        for (int j = 0; j < 8; ++j) {
            int kk = k0 + (tx << 2) + ((j < 4) ? j : 60 + j);
            float4 e0, e1;
            e0.x = __expf(acc[0][j] * 0.125f);
            e0.y = __expf(acc[1][j] * 0.125f);
            e0.z = __expf(acc[2][j] * 0.125f);
            e0.w = __expf(acc[3][j] * 0.125f);
            e1.x = __expf(acc[4][j] * 0.125f);
            e1.y = __expf(acc[5][j] * 0.125f);
            e1.z = __expf(acc[6][j] * 0.125f);
            e1.w = __expf(acc[7][j] * 0.125f);
            lsum[0] += e0.x; lsum[1] += e0.y; lsum[2] += e0.z; lsum[3] += e0.w;
            lsum[4] += e1.x; lsum[5] += e1.y; lsum[6] += e1.z; lsum[7] += e1.w;
            *(float4*)(sc + (size_t)kk * 128 + (ty << 2))      = e0;
            *(float4*)(sc + (size_t)kk * 128 + 64 + (ty << 2)) = e1;
        }
    }

    // ---- reduce lsum over the 16 tx lanes (half-warp butterflies)
    #pragma unroll
    for (int off = 8; off > 0; off >>= 1)
        #pragma unroll
        for (int i = 0; i < 8; i++)
            lsum[i] += __shfl_xor_sync(0xFFFFFFFFu, lsum[i], off);

    if (tx == 0) {
        #pragma unroll
        for (int i = 0; i < 8; i++) {
            int q = (ty << 2) + ((i < 4) ? i : 60 + i);
            sm.l_inv[q] = 1.0f / lsum[i];
        }
    }
    __syncthreads();   // l_inv visible; pass1 smem free to overwrite

    // ---- pass 2: Y[128 q][64 d] = relu(S*linv - TH) @ V, k-chunks of 64
    const int oty = tid >> 3;    // 0..31 -> q = oty*4
    const int otx = tid & 7;     // 0..7  -> d = otx*8
    float acc2[4][8];
    #pragma unroll
    for (int i = 0; i < 4; i++)
        #pragma unroll
        for (int j = 0; j < 8; j++) acc2[i][j] = 0.0f;

    for (int k0 = 0; k0 < T_; k0 += 64) {
        #pragma unroll
        for (int l = 0; l < 8; ++l) {
            int idx = tid + (l << 8);
            int r   = idx >> 5;            // 0..63 (k)
            int c   = (idx & 31) << 2;     // 0..124 (q)
            float4 e  = *(const float4*)(sc + (size_t)(k0 + r) * 128 + c);
            float4 iv = *(const float4*)&sm.l_inv[c];
            float4 p;
            p.x = fmaxf(e.x * iv.x - TH_, 0.0f);
            p.y = fmaxf(e.y * iv.y - TH_, 0.0f);
            p.z = fmaxf(e.z * iv.z - TH_, 0.0f);
            p.w = fmaxf(e.w * iv.w - TH_, 0.0f);
            *(float4*)&sm.u.p2.At[r][c] = p;
        }
        #pragma unroll
        for (int l = 0; l < 4; ++l) {
            int idx = tid + (l << 8);
            int r   = idx >> 4;            // 0..63 (k)
            int c   = (idx & 15) << 2;     // 0..60 (d)
            *(float4*)&sm.u.p2.Vs[r][c] =
                *(const float4*)(vbase + (size_t)(k0 + r) * C3_ + c);
        }
        __syncthreads();

        #pragma unroll 16
        for (int k = 0; k < 64; ++k) {
            float4 av = *(const float4*)&sm.u.p2.At[k][oty << 2];
            float4 v0 = *(const float4*)&sm.u.p2.Vs[k][otx << 3];
            float4 v1 = *(const float4*)&sm.u.p2.Vs[k][(otx << 3) + 4];
            float a[4] = {av.x, av.y, av.z, av.w};
            float v[8] = {v0.x, v0.y, v0.z, v0.w, v1.x, v1.y, v1.z, v1.w};
            #pragma unroll
            for (int i = 0; i < 4; i++)
                #pragma unroll
                for (int j = 0; j < 8; j++)
                    acc2[i][j] = fmaf(a[i], v[j], acc2[i][j]);
        }
        __syncthreads();
    }

    float* yb = Y + (size_t)b * T_ * C_ + h * HD_;
    #pragma unroll
    for (int i = 0; i < 4; i++) {
        int q = q0 + (oty << 2) + i;
        float4 o0, o1;
        o0.x = acc2[i][0]; o0.y = acc2[i][1]; o0.z = acc2[i][2]; o0.w = acc2[i][3];
        o1.x = acc2[i][4]; o1.y = acc2[i][5]; o1.z = acc2[i][6]; o1.w = acc2[i][7];
        *(float4*)&yb[(size_t)q * C_ + (otx << 3)]     = o0;
        *(float4*)&yb[(size_t)q * C_ + (otx << 3) + 4] = o1;
    }
}

// ---------------------------------------------------------------------------
extern "C" void kernel_launch(void* const* d_in, const int* in_sizes, int n_in,
                              void* d_out, int out_size)
{
    const float* x      = (const float*)d_in[0];   // (8192,1024)
    const float* w_attn = (const float*)d_in[1];   // (1024,3072)
    const float* b_attn = (const float*)d_in[2];   // (3072,)
    const float* w_proj = (const float*)d_in[3];   // (1024,1024)
    const float* b_proj = (const float*)d_in[4];   // (1024,)
    float* out = (float*)d_out;                    // (8192,1024)

    float *qkv, *S, *Y;
    cudaGetSymbolAddress((void**)&qkv, g_qkv);
    cudaGetSymbolAddress((void**)&S,   g_S);
    cudaGetSymbolAddress((void**)&Y,   g_Y);

    static_assert(sizeof(SmemAttn) <= 96 * 1024, "smem too big");
    cudaFuncSetAttribute(fused_attn_kernel,
                         cudaFuncAttributeMaxDynamicSharedMemorySize,
                         (int)sizeof(SmemAttn));

    // 1) QKV projection
    sgemm_bias_kernel<<<dim3(C3_ / 128, (B_ * T_) / 128), 256>>>(
        x, w_attn, b_attn, qkv, B_ * T_, C3_, C_);

    // 2+3+4) Fused scores/softmax-threshold/AV
    fused_attn_kernel<<<dim3(T_ / 128, BH_), 256, sizeof(SmemAttn)>>>(qkv, S, Y);

    // 5) Output projection
    sgemm_bias_kernel<<<dim3(C_ / 128, (B_ * T_) / 128), 256>>>(
        Y, w_proj, b_proj, out, B_ * T_, C_, C_);
}

// round 3
// speedup vs baseline: 1.1559x; 1.0984x over previous
#include <cuda_runtime.h>
#include <cstddef>

#define B_   8
#define T_   1024
#define C_   1024
#define H_   16
#define HD_  64
#define BH_  (B_ * H_)          // 128
#define C3_  (3 * C_)           // 3072
#define TH_  0.001f

using u64 = unsigned long long;

// Scratch (static device globals — no allocation at kernel_launch time)
__device__ float g_qkv[(size_t)B_ * T_ * C3_];    // 96 MB
__device__ float g_S[(size_t)BH_ * T_ * T_];      // 512 MB (exp scratch, [q][k] per block)
__device__ float g_Y[(size_t)B_ * T_ * C_];       // 32 MB

// ---------------- packed f32x2 helpers ----------------
__device__ __forceinline__ u64 fdup(float x) {
    u64 r; unsigned xi = __float_as_uint(x);
    asm("mov.b64 %0, {%1, %2};" : "=l"(r) : "r"(xi), "r"(xi));
    return r;
}
__device__ __forceinline__ u64 fpack(float x, float y) {
    u64 r;
    asm("mov.b64 %0, {%1, %2};" : "=l"(r)
        : "r"(__float_as_uint(x)), "r"(__float_as_uint(y)));
    return r;
}
__device__ __forceinline__ void ffma2(u64 &d, u64 a, u64 b) {
    asm("fma.rn.f32x2 %0, %1, %2, %0;" : "+l"(d) : "l"(a), "l"(b));
}
__device__ __forceinline__ u64 fadd2(u64 a, u64 b) {
    u64 r; asm("add.rn.f32x2 %0, %1, %2;" : "=l"(r) : "l"(a), "l"(b));
    return r;
}
__device__ __forceinline__ float2 funpack(u64 p) {
    unsigned lo, hi;
    asm("mov.b64 {%0, %1}, %2;" : "=r"(lo), "=r"(hi) : "l"(p));
    return make_float2(__uint_as_float(lo), __uint_as_float(hi));
}

// ---------------------------------------------------------------------------
// SGEMM: C[M,N] = A[M,K] * B[K,N] + bias[N]
// BM=128, BN=128, BK=16, 256 threads, 8x8 per thread via f32x2 pairs (acc 8x4).
// Register double-buffered global loads.
// ---------------------------------------------------------------------------
__global__ __launch_bounds__(256) void sgemm_bias_kernel(
    const float* __restrict__ A, const float* __restrict__ Bm,
    const float* __restrict__ bias, float* __restrict__ Cm,
    int M, int N, int K)
{
    __shared__ float As[16][132];   // transposed A tile: As[k][m] (padded)
    __shared__ float Bs[16][128];   // Bs[k][n]

    const int tid = threadIdx.x;
    const int tx  = tid & 15;
    const int ty  = tid >> 4;
    const int brow = blockIdx.y << 7;
    const int bcol = blockIdx.x << 7;

    u64 acc[8][4];
    #pragma unroll
    for (int i = 0; i < 8; i++)
        #pragma unroll
        for (int j = 0; j < 4; j++) acc[i][j] = 0ull;

    // per-thread load coords
    const int ar0 = tid >> 2;               // 0..63
    const int ar1 = ar0 + 64;               // 64..127
    const int ac  = (tid & 3) << 2;         // 0,4,8,12
    const int br0 = tid >> 5;               // 0..7
    const int br1 = br0 + 8;                // 8..15
    const int bc  = (tid & 31) << 2;        // 0..124

    float4 pa0, pa1, pb0, pb1;
    pa0 = *(const float4*)(A + (size_t)(brow + ar0) * K + ac);
    pa1 = *(const float4*)(A + (size_t)(brow + ar1) * K + ac);
    pb0 = *(const float4*)(Bm + (size_t)br0 * N + bcol + bc);
    pb1 = *(const float4*)(Bm + (size_t)br1 * N + bcol + bc);

    const int NT = K >> 4;
    for (int kt = 0; kt < NT; ++kt) {
        As[ac + 0][ar0] = pa0.x; As[ac + 1][ar0] = pa0.y;
        As[ac + 2][ar0] = pa0.z; As[ac + 3][ar0] = pa0.w;
        As[ac + 0][ar1] = pa1.x; As[ac + 1][ar1] = pa1.y;
        As[ac + 2][ar1] = pa1.z; As[ac + 3][ar1] = pa1.w;
        *(float4*)&Bs[br0][bc] = pb0;
        *(float4*)&Bs[br1][bc] = pb1;
        __syncthreads();

        if (kt + 1 < NT) {
            const int k0 = (kt + 1) << 4;
            pa0 = *(const float4*)(A + (size_t)(brow + ar0) * K + k0 + ac);
            pa1 = *(const float4*)(A + (size_t)(brow + ar1) * K + k0 + ac);
            pb0 = *(const float4*)(Bm + (size_t)(k0 + br0) * N + bcol + bc);
            pb1 = *(const float4*)(Bm + (size_t)(k0 + br1) * N + bcol + bc);
        }

        #pragma unroll
        for (int k = 0; k < 16; ++k) {
            float4 a0 = *(const float4*)&As[k][ty << 2];
            float4 a1 = *(const float4*)&As[k][(ty << 2) + 64];
            ulonglong2 b0 = *(const ulonglong2*)&Bs[k][tx << 2];
            ulonglong2 b1 = *(const ulonglong2*)&Bs[k][(tx << 2) + 64];
            u64 bp[4] = {b0.x, b0.y, b1.x, b1.y};
            u64 ad[8] = {fdup(a0.x), fdup(a0.y), fdup(a0.z), fdup(a0.w),
                         fdup(a1.x), fdup(a1.y), fdup(a1.z), fdup(a1.w)};
            #pragma unroll
            for (int i = 0; i < 8; i++)
                #pragma unroll
                for (int j = 0; j < 4; j++)
                    ffma2(acc[i][j], ad[i], bp[j]);
        }
        __syncthreads();
    }

    // epilogue: packed bias add + 16B stores
    ulonglong2 bb0 = *(const ulonglong2*)(bias + bcol + (tx << 2));
    ulonglong2 bb1 = *(const ulonglong2*)(bias + bcol + (tx << 2) + 64);
    u64 bp[4] = {bb0.x, bb0.y, bb1.x, bb1.y};
    #pragma unroll
    for (int i = 0; i < 8; i++) {
        int r = brow + (ty << 2) + ((i < 4) ? i : 60 + i);
        ulonglong2 o0, o1;
        o0.x = fadd2(acc[i][0], bp[0]); o0.y = fadd2(acc[i][1], bp[1]);
        o1.x = fadd2(acc[i][2], bp[2]); o1.y = fadd2(acc[i][3], bp[3]);
        *(ulonglong2*)&Cm[(size_t)r * N + bcol + (tx << 2)]      = o0;
        *(ulonglong2*)&Cm[(size_t)r * N + bcol + (tx << 2) + 64] = o1;
    }
}

// ---------------------------------------------------------------------------
// Fused attention, f32x2 math.
// pass1: E = exp((Q K^T)/8) -> scratch [q][k] (coalesced), row sums in regs.
// pass2: P = relu(E * l^-1 - TH), Y = P V  (At transpose in smem, pitch 130).
// ---------------------------------------------------------------------------
struct SmemAttn {
    float l_inv[128];
    union {
        struct { float Qt[64][132]; float Kt[64][132]; } p1;
        struct { float At[64][130]; float Vs[64][72];  } p2;
    } u;
};

__global__ __launch_bounds__(256, 1) void fused_attn_kernel(
    const float* __restrict__ qkv, float* __restrict__ scratch,
    float* __restrict__ Y)
{
    extern __shared__ char smem_raw[];
    SmemAttn& sm = *reinterpret_cast<SmemAttn*>(smem_raw);

    const int qb = blockIdx.x;       // 0..7
    const int bh = blockIdx.y;       // 0..127
    const int b  = bh >> 4;
    const int h  = bh & 15;
    const float* qbase = qkv + (size_t)b * T_ * C3_ + h * HD_;
    const float* kbase = qbase + C_;
    const float* vbase = qbase + 2 * C_;
    float* sc = scratch + (((size_t)bh * 8 + qb) << 17);   // [128 q][1024 k]

    const int tid = threadIdx.x;
    const int tx  = tid & 15;
    const int ty  = tid >> 4;
    const int q0  = qb << 7;

    // ---- load Q tile (128 q x 64 d), transposed -> Qt[d][q]
    #pragma unroll
    for (int l = 0; l < 8; ++l) {
        int idx = tid + (l << 8);
        int r   = idx >> 4;            // 0..127 (q)
        int c   = (idx & 15) << 2;     // 0..60 (d)
        float4 v = *(const float4*)(qbase + (size_t)(q0 + r) * C3_ + c);
        sm.u.p1.Qt[c + 0][r] = v.x; sm.u.p1.Qt[c + 1][r] = v.y;
        sm.u.p1.Qt[c + 2][r] = v.z; sm.u.p1.Qt[c + 3][r] = v.w;
    }

    float lsum[8];
    #pragma unroll
    for (int i = 0; i < 8; i++) lsum[i] = 0.0f;

    // ---- pass 1: k-tiles of 128
    for (int k0 = 0; k0 < T_; k0 += 128) {
        __syncthreads();
        #pragma unroll
        for (int l = 0; l < 8; ++l) {
            int idx = tid + (l << 8);
            int r   = idx >> 4;
            int c   = (idx & 15) << 2;
            float4 v = *(const float4*)(kbase + (size_t)(k0 + r) * C3_ + c);
            sm.u.p1.Kt[c + 0][r] = v.x; sm.u.p1.Kt[c + 1][r] = v.y;
            sm.u.p1.Kt[c + 2][r] = v.z; sm.u.p1.Kt[c + 3][r] = v.w;
        }
        __syncthreads();

        u64 acc[8][4];
        #pragma unroll
        for (int i = 0; i < 8; i++)
            #pragma unroll
            for (int j = 0; j < 4; j++) acc[i][j] = 0ull;

        #pragma unroll 8
        for (int d = 0; d < HD_; ++d) {
            float4 a0 = *(const float4*)&sm.u.p1.Qt[d][ty << 2];
            float4 a1 = *(const float4*)&sm.u.p1.Qt[d][(ty << 2) + 64];
            ulonglong2 b0 = *(const ulonglong2*)&sm.u.p1.Kt[d][tx << 2];
            ulonglong2 b1 = *(const ulonglong2*)&sm.u.p1.Kt[d][(tx << 2) + 64];
            u64 bp[4] = {b0.x, b0.y, b1.x, b1.y};
            u64 ad[8] = {fdup(a0.x), fdup(a0.y), fdup(a0.z), fdup(a0.w),
                         fdup(a1.x), fdup(a1.y), fdup(a1.z), fdup(a1.w)};
            #pragma unroll
            for (int i = 0; i < 8; i++)
                #pragma unroll
                for (int j = 0; j < 4; j++)
                    ffma2(acc[i][j], ad[i], bp[j]);
        }

        // exp epilogue: unpack, exp, row-sum, repack, coalesced store [q][k]
        #pragma unroll
        for (int i = 0; i < 8; ++i) {
            int q = q0 + (ty << 2) + ((i < 4) ? i : 60 + i);
            float2 t0 = funpack(acc[i][0]);
            float2 t1 = funpack(acc[i][1]);
            float2 t2 = funpack(acc[i][2]);
            float2 t3 = funpack(acc[i][3]);
            t0.x = __expf(t0.x * 0.125f); t0.y = __expf(t0.y * 0.125f);
            t1.x = __expf(t1.x * 0.125f); t1.y = __expf(t1.y * 0.125f);
            t2.x = __expf(t2.x * 0.125f); t2.y = __expf(t2.y * 0.125f);
            t3.x = __expf(t3.x * 0.125f); t3.y = __expf(t3.y * 0.125f);
            lsum[i] += (t0.x + t0.y) + (t1.x + t1.y)
                     + (t2.x + t2.y) + (t3.x + t3.y);
            ulonglong2 s0, s1;
            s0.x = fpack(t0.x, t0.y); s0.y = fpack(t1.x, t1.y);
            s1.x = fpack(t2.x, t2.y); s1.y = fpack(t3.x, t3.y);
            float* row = sc + ((size_t)(q - q0) << 10) + k0;
            *(ulonglong2*)(row + (tx << 2))      = s0;
            *(ulonglong2*)(row + (tx << 2) + 64) = s1;
        }
    }

    // ---- reduce lsum over the 16 tx lanes
    #pragma unroll
    for (int off = 8; off > 0; off >>= 1)
        #pragma unroll
        for (int i = 0; i < 8; i++)
            lsum[i] += __shfl_xor_sync(0xFFFFFFFFu, lsum[i], off);

    if (tx == 0) {
        #pragma unroll
        for (int i = 0; i < 8; i++) {
            int q = (ty << 2) + ((i < 4) ? i : 60 + i);
            sm.l_inv[q] = 1.0f / lsum[i];
        }
    }
    __syncthreads();   // l_inv visible; pass1 smem free to overwrite

    // ---- pass 2: Y[128 q][64 d] = relu(E*linv - TH) @ V, k-chunks of 64
    const int oty = tid >> 3;    // 0..31 -> q quad
    const int otx = tid & 7;     // 0..7  -> d octet
    u64 acc2[4][4];
    #pragma unroll
    for (int i = 0; i < 4; i++)
        #pragma unroll
        for (int j = 0; j < 4; j++) acc2[i][j] = 0ull;

    for (int k0 = 0; k0 < T_; k0 += 64) {
        // fill At[k][q] (transpose from [q][k] scratch) with threshold applied
        #pragma unroll
        for (int l = 0; l < 8; ++l) {
            int idx = tid + (l << 8);
            int q   = idx >> 4;            // 0..127
            int k4  = (idx & 15) << 2;     // 0..60
            float4 e = *(const float4*)(sc + ((size_t)q << 10) + k0 + k4);
            float iv = sm.l_inv[q];
            sm.u.p2.At[k4 + 0][q] = fmaxf(e.x * iv - TH_, 0.0f);
            sm.u.p2.At[k4 + 1][q] = fmaxf(e.y * iv - TH_, 0.0f);
            sm.u.p2.At[k4 + 2][q] = fmaxf(e.z * iv - TH_, 0.0f);
            sm.u.p2.At[k4 + 3][q] = fmaxf(e.w * iv - TH_, 0.0f);
        }
        #pragma unroll
        for (int l = 0; l < 4; ++l) {
            int idx = tid + (l << 8);
            int r   = idx >> 4;            // 0..63 (k)
            int c   = (idx & 15) << 2;     // 0..60 (d)
            *(float4*)&sm.u.p2.Vs[r][c] =
                *(const float4*)(vbase + (size_t)(k0 + r) * C3_ + c);
        }
        __syncthreads();

        #pragma unroll 8
        for (int k = 0; k < 64; ++k) {
            float2 a01 = *(const float2*)&sm.u.p2.At[k][oty << 2];
            float2 a23 = *(const float2*)&sm.u.p2.At[k][(oty << 2) + 2];
            ulonglong2 w0 = *(const ulonglong2*)&sm.u.p2.Vs[k][otx << 3];
            ulonglong2 w1 = *(const ulonglong2*)&sm.u.p2.Vs[k][(otx << 3) + 4];
            u64 vp[4] = {w0.x, w0.y, w1.x, w1.y};
            u64 ad[4] = {fdup(a01.x), fdup(a01.y), fdup(a23.x), fdup(a23.y)};
            #pragma unroll
            for (int i = 0; i < 4; i++)
                #pragma unroll
                for (int j = 0; j < 4; j++)
                    ffma2(acc2[i][j], ad[i], vp[j]);
        }
        __syncthreads();
    }

    float* yb = Y + (size_t)b * T_ * C_ + h * HD_;
    #pragma unroll
    for (int i = 0; i < 4; i++) {
        int q = q0 + (oty << 2) + i;
        float* base = yb + (size_t)q * C_ + (otx << 3);
        ulonglong2 o0, o1;
        o0.x = acc2[i][0]; o0.y = acc2[i][1];
        o1.x = acc2[i][2]; o1.y = acc2[i][3];
        *(ulonglong2*)base       = o0;
        *(ulonglong2*)(base + 4) = o1;
    }
}

// ---------------------------------------------------------------------------
extern "C" void kernel_launch(void* const* d_in, const int* in_sizes, int n_in,
                              void* d_out, int out_size)
{
    const float* x      = (const float*)d_in[0];   // (8192,1024)
    const float* w_attn = (const float*)d_in[1];   // (1024,3072)
    const float* b_attn = (const float*)d_in[2];   // (3072,)
    const float* w_proj = (const float*)d_in[3];   // (1024,1024)
    const float* b_proj = (const float*)d_in[4];   // (1024,)
    float* out = (float*)d_out;                    // (8192,1024)

    float *qkv, *S, *Y;
    cudaGetSymbolAddress((void**)&qkv, g_qkv);
    cudaGetSymbolAddress((void**)&S,   g_S);
    cudaGetSymbolAddress((void**)&Y,   g_Y);

    static_assert(sizeof(SmemAttn) <= 96 * 1024, "smem too big");
    cudaFuncSetAttribute(fused_attn_kernel,
                         cudaFuncAttributeMaxDynamicSharedMemorySize,
                         (int)sizeof(SmemAttn));

    // 1) QKV projection
    sgemm_bias_kernel<<<dim3(C3_ / 128, (B_ * T_) / 128), 256>>>(
        x, w_attn, b_attn, qkv, B_ * T_, C3_, C_);

    // 2+3+4) Fused scores/softmax-threshold/AV
    fused_attn_kernel<<<dim3(T_ / 128, BH_), 256, sizeof(SmemAttn)>>>(qkv, S, Y);

    // 5) Output projection
    sgemm_bias_kernel<<<dim3(C_ / 128, (B_ * T_) / 128), 256>>>(
        Y, w_proj, b_proj, out, B_ * T_, C_, C_);
}

// round 5
// speedup vs baseline: 1.4992x; 1.2970x over previous
#include <cuda_runtime.h>
#include <cuda_bf16.h>
#include <cstddef>
#include <cstdint>

#define B_   8
#define T_   1024
#define C_   1024
#define H_   16
#define HD_  64
#define BH_  (B_ * H_)          // 128
#define C3_  (3 * C_)           // 3072
#define KSP_ 3072               // split-K' = 3*1024
#define TH_  0.001f

using u64 = unsigned long long;

// ---------------- scratch (static device globals) ----------------
__device__ __align__(16) float g_qkv[(size_t)B_ * T_ * C3_];            // 96 MB
__device__ __align__(16) float g_S[(size_t)BH_ * T_ * T_];              // 512 MB
__device__ __align__(16) float g_Y[(size_t)B_ * T_ * C_];               // 32 MB
__device__ __align__(16) unsigned short g_xs[(size_t)B_ * T_ * KSP_];   // x split bf16
__device__ __align__(16) unsigned short g_ys[(size_t)B_ * T_ * KSP_];   // Y split bf16
__device__ __align__(16) unsigned short g_wa[(size_t)C3_ * KSP_];       // w_attn^T split
__device__ __align__(16) unsigned short g_wp[(size_t)C_ * KSP_];        // w_proj^T split

// ---------------- f32x2 helpers (attention kernel) ----------------
__device__ __forceinline__ u64 fdup(float x) {
    u64 r; unsigned xi = __float_as_uint(x);
    asm("mov.b64 %0, {%1, %2};" : "=l"(r) : "r"(xi), "r"(xi));
    return r;
}
__device__ __forceinline__ u64 fpack(float x, float y) {
    u64 r;
    asm("mov.b64 %0, {%1, %2};" : "=l"(r)
        : "r"(__float_as_uint(x)), "r"(__float_as_uint(y)));
    return r;
}
__device__ __forceinline__ void ffma2(u64 &d, u64 a, u64 b) {
    asm("fma.rn.f32x2 %0, %1, %2, %0;" : "+l"(d) : "l"(a), "l"(b));
}
__device__ __forceinline__ float2 funpack(u64 p) {
    unsigned lo, hi;
    asm("mov.b64 {%0, %1}, %2;" : "=r"(lo), "=r"(hi) : "l"(p));
    return make_float2(__uint_as_float(lo), __uint_as_float(hi));
}

// ---------------- warp-mma helpers (baseline PTX, no 'a' features) ----------
__device__ __forceinline__ uint32_t smem_u32(const void* p) {
    uint32_t a;
    asm("{ .reg .u64 t; cvta.to.shared.u64 t, %1; cvt.u32.u64 %0, t; }"
        : "=r"(a) : "l"(p));
    return a;
}
__device__ __forceinline__ void ldsm4(uint32_t (&r)[4], uint32_t addr) {
    asm volatile("ldmatrix.sync.aligned.m8n8.x4.shared.b16 {%0,%1,%2,%3}, [%4];"
        : "=r"(r[0]), "=r"(r[1]), "=r"(r[2]), "=r"(r[3]) : "r"(addr));
}
__device__ __forceinline__ void mma16816(float (&d)[4], const uint32_t (&a)[4],
                                         uint32_t b0, uint32_t b1) {
    asm volatile(
        "mma.sync.aligned.m16n8k16.row.col.f32.bf16.bf16.f32 "
        "{%0,%1,%2,%3}, {%4,%5,%6,%7}, {%8,%9}, {%0,%1,%2,%3};"
        : "+f"(d[0]), "+f"(d[1]), "+f"(d[2]), "+f"(d[3])
        : "r"(a[0]), "r"(a[1]), "r"(a[2]), "r"(a[3]), "r"(b0), "r"(b1));
}

// ---------------------------------------------------------------------------
// prep: split fp32 row-major [M][1024] -> bf16 [M][3072] blocks [hi | lo | hi]
// ---------------------------------------------------------------------------
__global__ __launch_bounds__(256) void prep_split_kernel(
    const float* __restrict__ X, unsigned short* __restrict__ Xs)
{
    const size_t r = blockIdx.x;
    const int c4 = threadIdx.x << 2;
    float4 v = *(const float4*)(X + r * 1024 + c4);
    __nv_bfloat16 h0 = __float2bfloat16(v.x);
    __nv_bfloat16 h1 = __float2bfloat16(v.y);
    __nv_bfloat16 h2 = __float2bfloat16(v.z);
    __nv_bfloat16 h3 = __float2bfloat16(v.w);
    __nv_bfloat16 l0 = __float2bfloat16(v.x - __bfloat162float(h0));
    __nv_bfloat16 l1 = __float2bfloat16(v.y - __bfloat162float(h1));
    __nv_bfloat16 l2 = __float2bfloat16(v.z - __bfloat162float(h2));
    __nv_bfloat16 l3 = __float2bfloat16(v.w - __bfloat162float(h3));
    ushort4 hv = make_ushort4(__bfloat16_as_ushort(h0), __bfloat16_as_ushort(h1),
                              __bfloat16_as_ushort(h2), __bfloat16_as_ushort(h3));
    ushort4 lv = make_ushort4(__bfloat16_as_ushort(l0), __bfloat16_as_ushort(l1),
                              __bfloat16_as_ushort(l2), __bfloat16_as_ushort(l3));
    unsigned short* row = Xs + r * KSP_;
    *(ushort4*)(row + c4)        = hv;
    *(ushort4*)(row + 1024 + c4) = lv;
    *(ushort4*)(row + 2048 + c4) = hv;
}

// ---------------------------------------------------------------------------
// prep: W [1024 k][N] fp32 -> Wt [N][3072 k'] bf16 blocks [hi | hi | lo]
// ---------------------------------------------------------------------------
__global__ __launch_bounds__(256) void prep_wt_kernel(
    const float* __restrict__ W, unsigned short* __restrict__ Wt, int N)
{
    __shared__ float t[32][33];
    const int n0 = blockIdx.x << 5;
    const int k0 = blockIdx.y << 5;
    const int row = threadIdx.x >> 5;
    const int col = threadIdx.x & 31;
    #pragma unroll
    for (int p = 0; p < 4; ++p)
        t[row + p * 8][col] = W[(size_t)(k0 + row + p * 8) * N + n0 + col];
    __syncthreads();
    #pragma unroll
    for (int p = 0; p < 4; ++p) {
        int n = row + p * 8, k = col;
        float v = t[k][n];
        __nv_bfloat16 h = __float2bfloat16(v);
        __nv_bfloat16 l = __float2bfloat16(v - __bfloat162float(h));
        unsigned short hu = __bfloat16_as_ushort(h);
        unsigned short lu = __bfloat16_as_ushort(l);
        size_t base = (size_t)(n0 + n) * KSP_ + k0 + k;
        Wt[base]        = hu;
        Wt[base + 1024] = hu;
        Wt[base + 2048] = lu;
    }
}

// ---------------------------------------------------------------------------
// HMMA GEMM: C[M][N] = A'[M][3072] x Bt'[N][3072]^T + bias
// 128x128 tile, BK=32, 8 warps (warp = 64x32), double-buffered smem.
// ---------------------------------------------------------------------------
#define BK_   32
#define NCH_  (KSP_ / BK_)      // 96
#define PITCH 40                // halves per smem row (80 B)
#define BUFH  (128 * PITCH)     // halves per buffer

__global__ __launch_bounds__(256, 2) void gemm_mma_kernel(
    const unsigned short* __restrict__ A, const unsigned short* __restrict__ Bt,
    const float* __restrict__ bias, float* __restrict__ C, int N)
{
    __shared__ __align__(16) unsigned short As[2][BUFH];
    __shared__ __align__(16) unsigned short Bs[2][BUFH];

    const int tid  = threadIdx.x;
    const int lane = tid & 31, wid = tid >> 5;
    const int m0 = blockIdx.y << 7, n0 = blockIdx.x << 7;
    const int wm = (wid & 1) << 6;      // 0 / 64
    const int wn = (wid >> 1) << 5;     // 0 / 32 / 64 / 96

    float acc[4][4][4];
    #pragma unroll
    for (int i = 0; i < 4; i++)
        #pragma unroll
        for (int j = 0; j < 4; j++)
            #pragma unroll
            for (int k = 0; k < 4; k++) acc[i][j][k] = 0.0f;

    // global load coords: each thread 16B at (row, kgroup), rows lr and lr+64
    const int lr = tid >> 2;
    const int lk = (tid & 3) << 3;
    const unsigned short* gA0 = A  + (size_t)(m0 + lr) * KSP_ + lk;
    const unsigned short* gA1 = A  + (size_t)(m0 + lr + 64) * KSP_ + lk;
    const unsigned short* gB0 = Bt + (size_t)(n0 + lr) * KSP_ + lk;
    const unsigned short* gB1 = Bt + (size_t)(n0 + lr + 64) * KSP_ + lk;
    const int soff0 = lr * PITCH + lk;
    const int soff1 = (lr + 64) * PITCH + lk;

    const uint32_t sA = smem_u32(As);
    const uint32_t sB = smem_u32(Bs);
    // ldmatrix lane addresses (bytes from buffer base)
    const uint32_t aoff = (uint32_t)((wm + (lane & 15)) * PITCH + (lane >> 4) * 8) * 2;
    const int brow = wn + (lane & 7) + ((lane >> 4) << 3);
    const uint32_t boff = (uint32_t)(brow * PITCH + ((lane >> 3) & 1) * 8) * 2;

    uint4 pa0 = *(const uint4*)gA0;
    uint4 pa1 = *(const uint4*)gA1;
    uint4 pb0 = *(const uint4*)gB0;
    uint4 pb1 = *(const uint4*)gB1;
    *(uint4*)&As[0][soff0] = pa0; *(uint4*)&As[0][soff1] = pa1;
    *(uint4*)&Bs[0][soff0] = pb0; *(uint4*)&Bs[0][soff1] = pb1;
    __syncthreads();

    for (int c = 0; c < NCH_; ++c) {
        const int buf = c & 1;
        if (c + 1 < NCH_) {
            const int kc = (c + 1) << 5;
            pa0 = *(const uint4*)(gA0 + kc);
            pa1 = *(const uint4*)(gA1 + kc);
            pb0 = *(const uint4*)(gB0 + kc);
            pb1 = *(const uint4*)(gB1 + kc);
        }
        const uint32_t aB = sA + buf * (BUFH * 2) + aoff;
        const uint32_t bB = sB + buf * (BUFH * 2) + boff;
        #pragma unroll
        for (int ks = 0; ks < 2; ++ks) {
            uint32_t af[4][4], bf[2][4];
            #pragma unroll
            for (int mi = 0; mi < 4; ++mi)
                ldsm4(af[mi], aB + mi * (16 * PITCH * 2) + ks * 32);
            #pragma unroll
            for (int np = 0; np < 2; ++np)
                ldsm4(bf[np], bB + np * (16 * PITCH * 2) + ks * 32);
            #pragma unroll
            for (int mi = 0; mi < 4; ++mi) {
                mma16816(acc[mi][0], af[mi], bf[0][0], bf[0][1]);
                mma16816(acc[mi][1], af[mi], bf[0][2], bf[0][3]);
                mma16816(acc[mi][2], af[mi], bf[1][0], bf[1][1]);
                mma16816(acc[mi][3], af[mi], bf[1][2], bf[1][3]);
            }
        }
        if (c + 1 < NCH_) {
            __syncthreads();
            const int nb = (c + 1) & 1;
            *(uint4*)&As[nb][soff0] = pa0; *(uint4*)&As[nb][soff1] = pa1;
            *(uint4*)&Bs[nb][soff0] = pb0; *(uint4*)&Bs[nb][soff1] = pb1;
            __syncthreads();
        }
    }

    // epilogue: direct stores + bias
    const int g  = lane >> 2;
    const int tg = (lane & 3) << 1;
    #pragma unroll
    for (int ni = 0; ni < 4; ++ni) {
        int col = n0 + wn + ni * 8 + tg;
        float2 bv = *(const float2*)(bias + col);
        #pragma unroll
        for (int mi = 0; mi < 4; ++mi) {
            int r0 = m0 + wm + mi * 16 + g;
            float2 v0 = make_float2(acc[mi][ni][0] + bv.x, acc[mi][ni][1] + bv.y);
            float2 v1 = make_float2(acc[mi][ni][2] + bv.x, acc[mi][ni][3] + bv.y);
            *(float2*)&C[(size_t)r0 * N + col]       = v0;
            *(float2*)&C[(size_t)(r0 + 8) * N + col] = v1;
        }
    }
}

// ---------------------------------------------------------------------------
// Fused attention (R3 f32x2 version, unchanged)
// ---------------------------------------------------------------------------
struct SmemAttn {
    float l_inv[128];
    union {
        struct { float Qt[64][132]; float Kt[64][132]; } p1;
        struct { float At[64][130]; float Vs[64][72];  } p2;
    } u;
};

__global__ __launch_bounds__(256, 1) void fused_attn_kernel(
    const float* __restrict__ qkv, float* __restrict__ scratch,
    float* __restrict__ Y)
{
    extern __shared__ char smem_raw[];
    SmemAttn& sm = *reinterpret_cast<SmemAttn*>(smem_raw);

    const int qb = blockIdx.x;
    const int bh = blockIdx.y;
    const int b  = bh >> 4;
    const int h  = bh & 15;
    const float* qbase = qkv + (size_t)b * T_ * C3_ + h * HD_;
    const float* kbase = qbase + C_;
    const float* vbase = qbase + 2 * C_;
    float* sc = scratch + (((size_t)bh * 8 + qb) << 17);

    const int tid = threadIdx.x;
    const int tx  = tid & 15;
    const int ty  = tid >> 4;
    const int q0  = qb << 7;

    #pragma unroll
    for (int l = 0; l < 8; ++l) {
        int idx = tid + (l << 8);
        int r   = idx >> 4;
        int c   = (idx & 15) << 2;
        float4 v = *(const float4*)(qbase + (size_t)(q0 + r) * C3_ + c);
        sm.u.p1.Qt[c + 0][r] = v.x; sm.u.p1.Qt[c + 1][r] = v.y;
        sm.u.p1.Qt[c + 2][r] = v.z; sm.u.p1.Qt[c + 3][r] = v.w;
    }

    float lsum[8];
    #pragma unroll
    for (int i = 0; i < 8; i++) lsum[i] = 0.0f;

    for (int k0 = 0; k0 < T_; k0 += 128) {
        __syncthreads();
        #pragma unroll
        for (int l = 0; l < 8; ++l) {
            int idx = tid + (l << 8);
            int r   = idx >> 4;
            int c   = (idx & 15) << 2;
            float4 v = *(const float4*)(kbase + (size_t)(k0 + r) * C3_ + c);
            sm.u.p1.Kt[c + 0][r] = v.x; sm.u.p1.Kt[c + 1][r] = v.y;
            sm.u.p1.Kt[c + 2][r] = v.z; sm.u.p1.Kt[c + 3][r] = v.w;
        }
        __syncthreads();

        u64 acc[8][4];
        #pragma unroll
        for (int i = 0; i < 8; i++)
            #pragma unroll
            for (int j = 0; j < 4; j++) acc[i][j] = 0ull;

        #pragma unroll 8
        for (int d = 0; d < HD_; ++d) {
            float4 a0 = *(const float4*)&sm.u.p1.Qt[d][ty << 2];
            float4 a1 = *(const float4*)&sm.u.p1.Qt[d][(ty << 2) + 64];
            ulonglong2 b0 = *(const ulonglong2*)&sm.u.p1.Kt[d][tx << 2];
            ulonglong2 b1 = *(const ulonglong2*)&sm.u.p1.Kt[d][(tx << 2) + 64];
            u64 bp[4] = {b0.x, b0.y, b1.x, b1.y};
            u64 ad[8] = {fdup(a0.x), fdup(a0.y), fdup(a0.z), fdup(a0.w),
                         fdup(a1.x), fdup(a1.y), fdup(a1.z), fdup(a1.w)};
            #pragma unroll
            for (int i = 0; i < 8; i++)
                #pragma unroll
                for (int j = 0; j < 4; j++)
                    ffma2(acc[i][j], ad[i], bp[j]);
        }

        #pragma unroll
        for (int i = 0; i < 8; ++i) {
            int q = q0 + (ty << 2) + ((i < 4) ? i : 60 + i);
            float2 t0 = funpack(acc[i][0]);
            float2 t1 = funpack(acc[i][1]);
            float2 t2 = funpack(acc[i][2]);
            float2 t3 = funpack(acc[i][3]);
            t0.x = __expf(t0.x * 0.125f); t0.y = __expf(t0.y * 0.125f);
            t1.x = __expf(t1.x * 0.125f); t1.y = __expf(t1.y * 0.125f);
            t2.x = __expf(t2.x * 0.125f); t2.y = __expf(t2.y * 0.125f);
            t3.x = __expf(t3.x * 0.125f); t3.y = __expf(t3.y * 0.125f);
            lsum[i] += (t0.x + t0.y) + (t1.x + t1.y)
                     + (t2.x + t2.y) + (t3.x + t3.y);
            ulonglong2 s0, s1;
            s0.x = fpack(t0.x, t0.y); s0.y = fpack(t1.x, t1.y);
            s1.x = fpack(t2.x, t2.y); s1.y = fpack(t3.x, t3.y);
            float* row = sc + ((size_t)(q - q0) << 10) + k0;
            *(ulonglong2*)(row + (tx << 2))      = s0;
            *(ulonglong2*)(row + (tx << 2) + 64) = s1;
        }
    }

    #pragma unroll
    for (int off = 8; off > 0; off >>= 1)
        #pragma unroll
        for (int i = 0; i < 8; i++)
            lsum[i] += __shfl_xor_sync(0xFFFFFFFFu, lsum[i], off);

    if (tx == 0) {
        #pragma unroll
        for (int i = 0; i < 8; i++) {
            int q = (ty << 2) + ((i < 4) ? i : 60 + i);
            sm.l_inv[q] = 1.0f / lsum[i];
        }
    }
    __syncthreads();

    const int oty = tid >> 3;
    const int otx = tid & 7;
    u64 acc2[4][4];
    #pragma unroll
    for (int i = 0; i < 4; i++)
        #pragma unroll
        for (int j = 0; j < 4; j++) acc2[i][j] = 0ull;

    for (int k0 = 0; k0 < T_; k0 += 64) {
        #pragma unroll
        for (int l = 0; l < 8; ++l) {
            int idx = tid + (l << 8);
            int q   = idx >> 4;
            int k4  = (idx & 15) << 2;
            float4 e = *(const float4*)(sc + ((size_t)q << 10) + k0 + k4);
            float iv = sm.l_inv[q];
            sm.u.p2.At[k4 + 0][q] = fmaxf(e.x * iv - TH_, 0.0f);
            sm.u.p2.At[k4 + 1][q] = fmaxf(e.y * iv - TH_, 0.0f);
            sm.u.p2.At[k4 + 2][q] = fmaxf(e.z * iv - TH_, 0.0f);
            sm.u.p2.At[k4 + 3][q] = fmaxf(e.w * iv - TH_, 0.0f);
        }
        #pragma unroll
        for (int l = 0; l < 4; ++l) {
            int idx = tid + (l << 8);
            int r   = idx >> 4;
            int c   = (idx & 15) << 2;
            *(float4*)&sm.u.p2.Vs[r][c] =
                *(const float4*)(vbase + (size_t)(k0 + r) * C3_ + c);
        }
        __syncthreads();

        #pragma unroll 8
        for (int k = 0; k < 64; ++k) {
            float2 a01 = *(const float2*)&sm.u.p2.At[k][oty << 2];
            float2 a23 = *(const float2*)&sm.u.p2.At[k][(oty << 2) + 2];
            ulonglong2 w0 = *(const ulonglong2*)&sm.u.p2.Vs[k][otx << 3];
            ulonglong2 w1 = *(const ulonglong2*)&sm.u.p2.Vs[k][(otx << 3) + 4];
            u64 vp[4] = {w0.x, w0.y, w1.x, w1.y};
            u64 ad[4] = {fdup(a01.x), fdup(a01.y), fdup(a23.x), fdup(a23.y)};
            #pragma unroll
            for (int i = 0; i < 4; i++)
                #pragma unroll
                for (int j = 0; j < 4; j++)
                    ffma2(acc2[i][j], ad[i], vp[j]);
        }
        __syncthreads();
    }

    float* yb = Y + (size_t)b * T_ * C_ + h * HD_;
    #pragma unroll
    for (int i = 0; i < 4; i++) {
        int q = q0 + (oty << 2) + i;
        float* base = yb + (size_t)q * C_ + (otx << 3);
        ulonglong2 o0, o1;
        o0.x = acc2[i][0]; o0.y = acc2[i][1];
        o1.x = acc2[i][2]; o1.y = acc2[i][3];
        *(ulonglong2*)base       = o0;
        *(ulonglong2*)(base + 4) = o1;
    }
}

// ---------------------------------------------------------------------------
extern "C" void kernel_launch(void* const* d_in, const int* in_sizes, int n_in,
                              void* d_out, int out_size)
{
    const float* x      = (const float*)d_in[0];
    const float* w_attn = (const float*)d_in[1];
    const float* b_attn = (const float*)d_in[2];
    const float* w_proj = (const float*)d_in[3];
    const float* b_proj = (const float*)d_in[4];
    float* out = (float*)d_out;

    float *qkv, *S, *Y;
    unsigned short *xs, *ys, *wa, *wp;
    cudaGetSymbolAddress((void**)&qkv, g_qkv);
    cudaGetSymbolAddress((void**)&S,   g_S);
    cudaGetSymbolAddress((void**)&Y,   g_Y);
    cudaGetSymbolAddress((void**)&xs,  g_xs);
    cudaGetSymbolAddress((void**)&ys,  g_ys);
    cudaGetSymbolAddress((void**)&wa,  g_wa);
    cudaGetSymbolAddress((void**)&wp,  g_wp);

    static_assert(sizeof(SmemAttn) <= 96 * 1024, "smem too big");
    cudaFuncSetAttribute(fused_attn_kernel,
                         cudaFuncAttributeMaxDynamicSharedMemorySize,
                         (int)sizeof(SmemAttn));

    // prep: bf16 splits
    prep_split_kernel<<<B_ * T_, 256>>>(x, xs);
    prep_wt_kernel<<<dim3(C3_ / 32, C_ / 32), 256>>>(w_attn, wa, C3_);
    prep_wt_kernel<<<dim3(C_ / 32, C_ / 32), 256>>>(w_proj, wp, C_);

    // 1) QKV projection (HMMA)
    gemm_mma_kernel<<<dim3(C3_ / 128, (B_ * T_) / 128), 256>>>(
        xs, wa, b_attn, qkv, C3_);

    // 2) fused attention
    fused_attn_kernel<<<dim3(T_ / 128, BH_), 256, sizeof(SmemAttn)>>>(qkv, S, Y);

    // 3) output projection (HMMA)
    prep_split_kernel<<<B_ * T_, 256>>>(Y, ys);
    gemm_mma_kernel<<<dim3(C_ / 128, (B_ * T_) / 128), 256>>>(
        ys, wp, b_proj, out, C_);
}

// round 6
// speedup vs baseline: 2.0703x; 1.3810x over previous
#include <cuda_runtime.h>
#include <cuda_bf16.h>
#include <cstddef>
#include <cstdint>

#define B_   8
#define T_   1024
#define C_   1024
#define H_   16
#define HD_  64
#define BH_  (B_ * H_)          // 128
#define C3_  (3 * C_)           // 3072
#define KSP_ 3072               // split-K' = 3*1024
#define TH_  0.001f
#define PQ_  72                 // smem pitch in halves (144B rows: ldmatrix conflict-free)

using u64 = unsigned long long;
using ushort_t = unsigned short;

// ---------------- scratch (static device globals) ----------------
__device__ __align__(16) float g_qkv[(size_t)B_ * T_ * C3_];            // 96 MB
__device__ __align__(16) float g_S[(size_t)BH_ * T_ * T_];              // 512 MB exp scratch
__device__ __align__(16) ushort_t g_xs[(size_t)B_ * T_ * KSP_];         // x split bf16
__device__ __align__(16) ushort_t g_ys[(size_t)B_ * T_ * KSP_];         // Y split bf16
__device__ __align__(16) ushort_t g_wa[(size_t)C3_ * KSP_];             // w_attn^T split
__device__ __align__(16) ushort_t g_wp[(size_t)C_ * KSP_];              // w_proj^T split

// ---------------- warp-mma helpers ----------------
__device__ __forceinline__ uint32_t smem_u32(const void* p) {
    uint32_t a;
    asm("{ .reg .u64 t; cvta.to.shared.u64 t, %1; cvt.u32.u64 %0, t; }"
        : "=r"(a) : "l"(p));
    return a;
}
__device__ __forceinline__ void ldsm4(uint32_t (&r)[4], uint32_t addr) {
    asm volatile("ldmatrix.sync.aligned.m8n8.x4.shared.b16 {%0,%1,%2,%3}, [%4];"
        : "=r"(r[0]), "=r"(r[1]), "=r"(r[2]), "=r"(r[3]) : "r"(addr));
}
__device__ __forceinline__ void mma16816(float (&d)[4], const uint32_t (&a)[4],
                                         uint32_t b0, uint32_t b1) {
    asm volatile(
        "mma.sync.aligned.m16n8k16.row.col.f32.bf16.bf16.f32 "
        "{%0,%1,%2,%3}, {%4,%5,%6,%7}, {%8,%9}, {%0,%1,%2,%3};"
        : "+f"(d[0]), "+f"(d[1]), "+f"(d[2]), "+f"(d[3])
        : "r"(a[0]), "r"(a[1]), "r"(a[2]), "r"(a[3]), "r"(b0), "r"(b1));
}
__device__ __forceinline__ void bf16split(float v, ushort_t &h, ushort_t &l) {
    __nv_bfloat16 hb = __float2bfloat16(v);
    __nv_bfloat16 lb = __float2bfloat16(v - __bfloat162float(hb));
    h = __bfloat16_as_ushort(hb);
    l = __bfloat16_as_ushort(lb);
}

// ---------------------------------------------------------------------------
// prep: split fp32 row-major [M][1024] -> bf16 [M][3072] blocks [hi | lo | hi]
// ---------------------------------------------------------------------------
__global__ __launch_bounds__(256) void prep_split_kernel(
    const float* __restrict__ X, ushort_t* __restrict__ Xs)
{
    const size_t r = blockIdx.x;
    const int c4 = threadIdx.x << 2;
    float4 v = *(const float4*)(X + r * 1024 + c4);
    ushort4 hv, lv;
    bf16split(v.x, hv.x, lv.x); bf16split(v.y, hv.y, lv.y);
    bf16split(v.z, hv.z, lv.z); bf16split(v.w, hv.w, lv.w);
    ushort_t* row = Xs + r * KSP_;
    *(ushort4*)(row + c4)        = hv;
    *(ushort4*)(row + 1024 + c4) = lv;
    *(ushort4*)(row + 2048 + c4) = hv;
}

// ---------------------------------------------------------------------------
// prep: W [1024 k][N] fp32 -> Wt [N][3072 k'] bf16 blocks [hi | hi | lo]
// ---------------------------------------------------------------------------
__global__ __launch_bounds__(256) void prep_wt_kernel(
    const float* __restrict__ W, ushort_t* __restrict__ Wt, int N)
{
    __shared__ float t[32][33];
    const int n0 = blockIdx.x << 5;
    const int k0 = blockIdx.y << 5;
    const int row = threadIdx.x >> 5;
    const int col = threadIdx.x & 31;
    #pragma unroll
    for (int p = 0; p < 4; ++p)
        t[row + p * 8][col] = W[(size_t)(k0 + row + p * 8) * N + n0 + col];
    __syncthreads();
    #pragma unroll
    for (int p = 0; p < 4; ++p) {
        int n = row + p * 8, k = col;
        ushort_t hu, lu;
        bf16split(t[k][n], hu, lu);
        size_t base = (size_t)(n0 + n) * KSP_ + k0 + k;
        Wt[base]        = hu;
        Wt[base + 1024] = hu;
        Wt[base + 2048] = lu;
    }
}

// ---------------------------------------------------------------------------
// HMMA GEMM (unchanged from R5): C = A'[M][3072] x Bt'[N][3072]^T + bias
// ---------------------------------------------------------------------------
#define BK_   32
#define NCH_  (KSP_ / BK_)      // 96
#define PITCH 40
#define BUFH  (128 * PITCH)

__global__ __launch_bounds__(256, 2) void gemm_mma_kernel(
    const ushort_t* __restrict__ A, const ushort_t* __restrict__ Bt,
    const float* __restrict__ bias, float* __restrict__ C, int N)
{
    __shared__ __align__(16) ushort_t As[2][BUFH];
    __shared__ __align__(16) ushort_t Bs[2][BUFH];

    const int tid  = threadIdx.x;
    const int lane = tid & 31, wid = tid >> 5;
    const int m0 = blockIdx.y << 7, n0 = blockIdx.x << 7;
    const int wm = (wid & 1) << 6;
    const int wn = (wid >> 1) << 5;

    float acc[4][4][4];
    #pragma unroll
    for (int i = 0; i < 4; i++)
        #pragma unroll
        for (int j = 0; j < 4; j++)
            #pragma unroll
            for (int k = 0; k < 4; k++) acc[i][j][k] = 0.0f;

    const int lr = tid >> 2;
    const int lk = (tid & 3) << 3;
    const ushort_t* gA0 = A  + (size_t)(m0 + lr) * KSP_ + lk;
    const ushort_t* gA1 = A  + (size_t)(m0 + lr + 64) * KSP_ + lk;
    const ushort_t* gB0 = Bt + (size_t)(n0 + lr) * KSP_ + lk;
    const ushort_t* gB1 = Bt + (size_t)(n0 + lr + 64) * KSP_ + lk;
    const int soff0 = lr * PITCH + lk;
    const int soff1 = (lr + 64) * PITCH + lk;

    const uint32_t sA = smem_u32(As);
    const uint32_t sB = smem_u32(Bs);
    const uint32_t aoff = (uint32_t)((wm + (lane & 15)) * PITCH + (lane >> 4) * 8) * 2;
    const int brow = wn + (lane & 7) + ((lane >> 4) << 3);
    const uint32_t boff = (uint32_t)(brow * PITCH + ((lane >> 3) & 1) * 8) * 2;

    uint4 pa0 = *(const uint4*)gA0;
    uint4 pa1 = *(const uint4*)gA1;
    uint4 pb0 = *(const uint4*)gB0;
    uint4 pb1 = *(const uint4*)gB1;
    *(uint4*)&As[0][soff0] = pa0; *(uint4*)&As[0][soff1] = pa1;
    *(uint4*)&Bs[0][soff0] = pb0; *(uint4*)&Bs[0][soff1] = pb1;
    __syncthreads();

    for (int c = 0; c < NCH_; ++c) {
        const int buf = c & 1;
        if (c + 1 < NCH_) {
            const int kc = (c + 1) << 5;
            pa0 = *(const uint4*)(gA0 + kc);
            pa1 = *(const uint4*)(gA1 + kc);
            pb0 = *(const uint4*)(gB0 + kc);
            pb1 = *(const uint4*)(gB1 + kc);
        }
        const uint32_t aB = sA + buf * (BUFH * 2) + aoff;
        const uint32_t bB = sB + buf * (BUFH * 2) + boff;
        #pragma unroll
        for (int ks = 0; ks < 2; ++ks) {
            uint32_t af[4][4], bf[2][4];
            #pragma unroll
            for (int mi = 0; mi < 4; ++mi)
                ldsm4(af[mi], aB + mi * (16 * PITCH * 2) + ks * 32);
            #pragma unroll
            for (int np = 0; np < 2; ++np)
                ldsm4(bf[np], bB + np * (16 * PITCH * 2) + ks * 32);
            #pragma unroll
            for (int mi = 0; mi < 4; ++mi) {
                mma16816(acc[mi][0], af[mi], bf[0][0], bf[0][1]);
                mma16816(acc[mi][1], af[mi], bf[0][2], bf[0][3]);
                mma16816(acc[mi][2], af[mi], bf[1][0], bf[1][1]);
                mma16816(acc[mi][3], af[mi], bf[1][2], bf[1][3]);
            }
        }
        if (c + 1 < NCH_) {
            __syncthreads();
            const int nb = (c + 1) & 1;
            *(uint4*)&As[nb][soff0] = pa0; *(uint4*)&As[nb][soff1] = pa1;
            *(uint4*)&Bs[nb][soff0] = pb0; *(uint4*)&Bs[nb][soff1] = pb1;
            __syncthreads();
        }
    }

    const int g  = lane >> 2;
    const int tg = (lane & 3) << 1;
    #pragma unroll
    for (int ni = 0; ni < 4; ++ni) {
        int col = n0 + wn + ni * 8 + tg;
        float2 bv = *(const float2*)(bias + col);
        #pragma unroll
        for (int mi = 0; mi < 4; ++mi) {
            int r0 = m0 + wm + mi * 16 + g;
            float2 v0 = make_float2(acc[mi][ni][0] + bv.x, acc[mi][ni][1] + bv.y);
            float2 v1 = make_float2(acc[mi][ni][2] + bv.x, acc[mi][ni][3] + bv.y);
            *(float2*)&C[(size_t)r0 * N + col]       = v0;
            *(float2*)&C[(size_t)(r0 + 8) * N + col] = v1;
        }
    }
}

// ---------------------------------------------------------------------------
// Fused attention on HMMA.
// pass1: S-tiles 128x128 via 3-term split bf16 QK; exp epilogue; e->scratch fp32
// pass2: k-chunks of 64: P=relu(e*linv-TH) split bf16; AV 3-term; Y -> g_ys split
// ---------------------------------------------------------------------------
struct SmemAttnMma {
    float l_red[128];
    float l_inv[128];
    union {
        struct { ushort_t Qh[128 * PQ_], Ql[128 * PQ_],
                          Kh[128 * PQ_], Kl[128 * PQ_]; } p1;        // 72 KB
        struct { ushort_t Ph[128 * PQ_], Pl[128 * PQ_],
                          Vh[64 * PQ_],  Vl[64 * PQ_]; } p2;         // 54 KB
    } u;
};

__global__ __launch_bounds__(256, 2) void fused_attn_mma_kernel(
    const float* __restrict__ qkv, float* __restrict__ scratch,
    ushort_t* __restrict__ Ys)
{
    extern __shared__ char smem_raw[];
    SmemAttnMma& sm = *reinterpret_cast<SmemAttnMma*>(smem_raw);

    const int qb = blockIdx.x;       // 0..7
    const int bh = blockIdx.y;       // 0..127
    const int b  = bh >> 4;
    const int h  = bh & 15;
    const float* qbase = qkv + (size_t)b * T_ * C3_ + h * HD_;
    const float* kbase = qbase + C_;
    const float* vbase = qbase + 2 * C_;
    float* sc = scratch + (((size_t)bh * 8 + qb) << 17);   // [128 q][1024 k]

    const int tid  = threadIdx.x;
    const int lane = tid & 31, wid = tid >> 5;
    const int q0   = qb << 7;
    const int g    = lane >> 2;

    if (tid < 128) sm.l_red[tid] = 0.0f;

    // ---- stage Q (128 x 64) -> Qh/Ql
    #pragma unroll
    for (int l = 0; l < 8; ++l) {
        int idx = tid + (l << 8);
        int r   = idx >> 4;
        int c4  = (idx & 15) << 2;
        float4 v = *(const float4*)(qbase + (size_t)(q0 + r) * C3_ + c4);
        ushort4 hv, lv;
        bf16split(v.x, hv.x, lv.x); bf16split(v.y, hv.y, lv.y);
        bf16split(v.z, hv.z, lv.z); bf16split(v.w, hv.w, lv.w);
        *(ushort4*)&sm.u.p1.Qh[r * PQ_ + c4] = hv;
        *(ushort4*)&sm.u.p1.Ql[r * PQ_ + c4] = lv;
    }

    // ---- pass 1: warps 2(m) x 4(n-keys), warp tile 64x32, k-tiles of 128 keys
    const int wm = (wid & 1) << 6;
    const int wn = (wid >> 1) << 5;
    const uint32_t sQh = smem_u32(sm.u.p1.Qh), sQl = smem_u32(sm.u.p1.Ql);
    const uint32_t sKh = smem_u32(sm.u.p1.Kh), sKl = smem_u32(sm.u.p1.Kl);
    const uint32_t aoff = (uint32_t)((wm + (lane & 15)) * PQ_ + (lane >> 4) * 8) * 2;
    const uint32_t boff = (uint32_t)((wn + (lane & 7) + ((lane >> 4) << 3)) * PQ_
                                     + ((lane >> 3) & 1) * 8) * 2;

    float lsum[8];
    #pragma unroll
    for (int i = 0; i < 8; i++) lsum[i] = 0.0f;

    for (int k0 = 0; k0 < T_; k0 += 128) {
        __syncthreads();   // prior-tile K reads done (and l_red zeroing on iter 0)
        #pragma unroll
        for (int l = 0; l < 8; ++l) {
            int idx = tid + (l << 8);
            int r   = idx >> 4;
            int c4  = (idx & 15) << 2;
            float4 v = *(const float4*)(kbase + (size_t)(k0 + r) * C3_ + c4);
            ushort4 hv, lv;
            bf16split(v.x, hv.x, lv.x); bf16split(v.y, hv.y, lv.y);
            bf16split(v.z, hv.z, lv.z); bf16split(v.w, hv.w, lv.w);
            *(ushort4*)&sm.u.p1.Kh[r * PQ_ + c4] = hv;
            *(ushort4*)&sm.u.p1.Kl[r * PQ_ + c4] = lv;
        }
        __syncthreads();

        float acc[4][4][4];
        #pragma unroll
        for (int i = 0; i < 4; i++)
            #pragma unroll
            for (int j = 0; j < 4; j++)
                #pragma unroll
                for (int k = 0; k < 4; k++) acc[i][j][k] = 0.0f;

        #pragma unroll
        for (int t = 0; t < 3; ++t) {
            const uint32_t aB = (t == 1 ? sQl : sQh) + aoff;
            const uint32_t bB = (t == 2 ? sKl : sKh) + boff;
            #pragma unroll
            for (int ks = 0; ks < 4; ++ks) {
                uint32_t af[4][4], bf[2][4];
                #pragma unroll
                for (int mi = 0; mi < 4; ++mi)
                    ldsm4(af[mi], aB + mi * (16 * PQ_ * 2) + ks * 32);
                #pragma unroll
                for (int np = 0; np < 2; ++np)
                    ldsm4(bf[np], bB + np * (16 * PQ_ * 2) + ks * 32);
                #pragma unroll
                for (int mi = 0; mi < 4; ++mi) {
                    mma16816(acc[mi][0], af[mi], bf[0][0], bf[0][1]);
                    mma16816(acc[mi][1], af[mi], bf[0][2], bf[0][3]);
                    mma16816(acc[mi][2], af[mi], bf[1][0], bf[1][1]);
                    mma16816(acc[mi][3], af[mi], bf[1][2], bf[1][3]);
                }
            }
        }

        // exp epilogue -> scratch (32B-sector stores), row sums
        #pragma unroll
        for (int mi = 0; mi < 4; ++mi) {
            #pragma unroll
            for (int ni = 0; ni < 4; ++ni) {
                float e0 = __expf(acc[mi][ni][0] * 0.125f);
                float e1 = __expf(acc[mi][ni][1] * 0.125f);
                float e2 = __expf(acc[mi][ni][2] * 0.125f);
                float e3 = __expf(acc[mi][ni][3] * 0.125f);
                lsum[mi * 2 + 0] += e0 + e1;
                lsum[mi * 2 + 1] += e2 + e3;
                int col = k0 + wn + ni * 8 + ((lane & 3) << 1);
                int r0  = wm + mi * 16 + g;
                *(float2*)(sc + (size_t)r0 * 1024 + col)        = make_float2(e0, e1);
                *(float2*)(sc + (size_t)(r0 + 8) * 1024 + col)  = make_float2(e2, e3);
            }
        }
    }

    // reduce lsum over quad lanes, then across warps via smem atomics
    #pragma unroll
    for (int i = 0; i < 8; i++) {
        float v = lsum[i];
        v += __shfl_xor_sync(0xFFFFFFFFu, v, 1);
        v += __shfl_xor_sync(0xFFFFFFFFu, v, 2);
        if ((lane & 3) == 0) {
            int row = wm + (i >> 1) * 16 + g + (i & 1) * 8;
            atomicAdd(&sm.l_red[row], v);
        }
    }
    __syncthreads();
    if (tid < 128) sm.l_inv[tid] = 1.0f / sm.l_red[tid];

    // ---- pass 2: warps 2(m) x 4(n-dims), warp tile 64x16, k-chunks of 64 keys
    const int wm2 = (wid & 1) << 6;
    const int wn2 = (wid >> 1) << 4;
    const uint32_t sPh = smem_u32(sm.u.p2.Ph), sPl = smem_u32(sm.u.p2.Pl);
    const uint32_t sVh = smem_u32(sm.u.p2.Vh), sVl = smem_u32(sm.u.p2.Vl);
    const uint32_t aoff2 = (uint32_t)((wm2 + (lane & 15)) * PQ_ + (lane >> 4) * 8) * 2;
    const uint32_t boff2 = (uint32_t)((wn2 + (lane & 7) + ((lane >> 4) << 3)) * PQ_
                                      + ((lane >> 3) & 1) * 8) * 2;

    float accy[4][2][4];
    #pragma unroll
    for (int i = 0; i < 4; i++)
        #pragma unroll
        for (int j = 0; j < 2; j++)
            #pragma unroll
            for (int k = 0; k < 4; k++) accy[i][j][k] = 0.0f;

    for (int kc = 0; kc < T_; kc += 64) {
        __syncthreads();   // prior chunk P/V reads done (covers l_inv on iter 0)
        // stage P = relu(e * linv - TH) split  (128 q x 64 k)
        #pragma unroll
        for (int l = 0; l < 8; ++l) {
            int idx = tid + (l << 8);
            int r   = idx >> 4;
            int c4  = (idx & 15) << 2;
            float4 e = *(const float4*)(sc + (size_t)r * 1024 + kc + c4);
            float iv = sm.l_inv[r];
            float p0 = fmaxf(fmaf(e.x, iv, -TH_), 0.0f);
            float p1 = fmaxf(fmaf(e.y, iv, -TH_), 0.0f);
            float p2 = fmaxf(fmaf(e.z, iv, -TH_), 0.0f);
            float p3 = fmaxf(fmaf(e.w, iv, -TH_), 0.0f);
            ushort4 hv, lv;
            bf16split(p0, hv.x, lv.x); bf16split(p1, hv.y, lv.y);
            bf16split(p2, hv.z, lv.z); bf16split(p3, hv.w, lv.w);
            *(ushort4*)&sm.u.p2.Ph[r * PQ_ + c4] = hv;
            *(ushort4*)&sm.u.p2.Pl[r * PQ_ + c4] = lv;
        }
        // stage V transposed: Vh[d][k] (64 x 64)
        #pragma unroll
        for (int l = 0; l < 4; ++l) {
            int idx = tid + (l << 8);
            int r   = idx >> 4;            // key within chunk
            int c4  = (idx & 15) << 2;     // d
            float4 v = *(const float4*)(vbase + (size_t)(kc + r) * C3_ + c4);
            ushort_t hu, lu;
            bf16split(v.x, hu, lu);
            sm.u.p2.Vh[(c4 + 0) * PQ_ + r] = hu; sm.u.p2.Vl[(c4 + 0) * PQ_ + r] = lu;
            bf16split(v.y, hu, lu);
            sm.u.p2.Vh[(c4 + 1) * PQ_ + r] = hu; sm.u.p2.Vl[(c4 + 1) * PQ_ + r] = lu;
            bf16split(v.z, hu, lu);
            sm.u.p2.Vh[(c4 + 2) * PQ_ + r] = hu; sm.u.p2.Vl[(c4 + 2) * PQ_ + r] = lu;
            bf16split(v.w, hu, lu);
            sm.u.p2.Vh[(c4 + 3) * PQ_ + r] = hu; sm.u.p2.Vl[(c4 + 3) * PQ_ + r] = lu;
        }
        __syncthreads();

        #pragma unroll
        for (int t = 0; t < 3; ++t) {
            const uint32_t aB = (t == 1 ? sPl : sPh) + aoff2;
            const uint32_t bB = (t == 2 ? sVl : sVh) + boff2;
            #pragma unroll
            for (int ks = 0; ks < 4; ++ks) {
                uint32_t af[4][4], bf[4];
                #pragma unroll
                for (int mi = 0; mi < 4; ++mi)
                    ldsm4(af[mi], aB + mi * (16 * PQ_ * 2) + ks * 32);
                ldsm4(bf, bB + ks * 32);
                #pragma unroll
                for (int mi = 0; mi < 4; ++mi) {
                    mma16816(accy[mi][0], af[mi], bf[0], bf[1]);
                    mma16816(accy[mi][1], af[mi], bf[2], bf[3]);
                }
            }
        }
    }

    // epilogue: write Y directly in split [hi | lo | hi] layout
    #pragma unroll
    for (int mi = 0; mi < 4; ++mi) {
        #pragma unroll
        for (int ni = 0; ni < 2; ++ni) {
            int ch = h * HD_ + wn2 + ni * 8 + ((lane & 3) << 1);
            #pragma unroll
            for (int hv = 0; hv < 2; ++hv) {
                int rq = q0 + wm2 + mi * 16 + g + hv * 8;
                size_t rg = ((size_t)b * T_ + rq) * KSP_;
                float v0 = accy[mi][ni][hv * 2 + 0];
                float v1 = accy[mi][ni][hv * 2 + 1];
                ushort2 hp, lp;
                bf16split(v0, hp.x, lp.x);
                bf16split(v1, hp.y, lp.y);
                *(ushort2*)&Ys[rg + ch]        = hp;
                *(ushort2*)&Ys[rg + 1024 + ch] = lp;
                *(ushort2*)&Ys[rg + 2048 + ch] = hp;
            }
        }
    }
}

// ---------------------------------------------------------------------------
extern "C" void kernel_launch(void* const* d_in, const int* in_sizes, int n_in,
                              void* d_out, int out_size)
{
    const float* x      = (const float*)d_in[0];
    const float* w_attn = (const float*)d_in[1];
    const float* b_attn = (const float*)d_in[2];
    const float* w_proj = (const float*)d_in[3];
    const float* b_proj = (const float*)d_in[4];
    float* out = (float*)d_out;

    float *qkv, *S;
    ushort_t *xs, *ys, *wa, *wp;
    cudaGetSymbolAddress((void**)&qkv, g_qkv);
    cudaGetSymbolAddress((void**)&S,   g_S);
    cudaGetSymbolAddress((void**)&xs,  g_xs);
    cudaGetSymbolAddress((void**)&ys,  g_ys);
    cudaGetSymbolAddress((void**)&wa,  g_wa);
    cudaGetSymbolAddress((void**)&wp,  g_wp);

    cudaFuncSetAttribute(fused_attn_mma_kernel,
                         cudaFuncAttributeMaxDynamicSharedMemorySize,
                         (int)sizeof(SmemAttnMma));

    // prep: bf16 splits
    prep_split_kernel<<<B_ * T_, 256>>>(x, xs);
    prep_wt_kernel<<<dim3(C3_ / 32, C_ / 32), 256>>>(w_attn, wa, C3_);
    prep_wt_kernel<<<dim3(C_ / 32, C_ / 32), 256>>>(w_proj, wp, C_);

    // 1) QKV projection (HMMA)
    gemm_mma_kernel<<<dim3(C3_ / 128, (B_ * T_) / 128), 256>>>(
        xs, wa, b_attn, qkv, C3_);

    // 2) fused attention (HMMA), writes Y split directly
    fused_attn_mma_kernel<<<dim3(T_ / 128, BH_), 256, sizeof(SmemAttnMma)>>>(
        qkv, S, ys);

    // 3) output projection (HMMA)
    gemm_mma_kernel<<<dim3(C_ / 128, (B_ * T_) / 128), 256>>>(
        ys, wp, b_proj, out, C_);
}

// round 7
// speedup vs baseline: 3.4033x; 1.6438x over previous
#include <cuda_runtime.h>
#include <cuda_fp16.h>
#include <cstddef>
#include <cstdint>

#define B_   8
#define T_   1024
#define C_   1024
#define H_   16
#define HD_  64
#define BH_  (B_ * H_)          // 128
#define C3_  (3 * C_)           // 3072
#define KSP_ 2048               // split-K' = 2*1024 ([hi | lo])
#define KW_  1024               // weight hi-only K
#define TH_  0.001f
#define PQ_  72                 // attn smem pitch (halves): 144B rows, ldsm conflict-free

using ushort_t = unsigned short;

// ---------------- scratch (static device globals) ----------------
__device__ __align__(16) float g_qkv[(size_t)B_ * T_ * C3_];            // 96 MB
__device__ __align__(16) float g_S[(size_t)BH_ * T_ * T_];              // 512 MB exp scratch
__device__ __align__(16) ushort_t g_xs[(size_t)B_ * T_ * KSP_];         // x  [hi|lo] fp16
__device__ __align__(16) ushort_t g_ys[(size_t)B_ * T_ * KSP_];         // Y  [hi|lo] fp16
__device__ __align__(16) ushort_t g_wa[(size_t)C3_ * KW_];              // w_attn^T hi
__device__ __align__(16) ushort_t g_wp[(size_t)C_ * KW_];               // w_proj^T hi

// ---------------- helpers ----------------
__device__ __forceinline__ uint32_t smem_u32(const void* p) {
    uint32_t a;
    asm("{ .reg .u64 t; cvta.to.shared.u64 t, %1; cvt.u32.u64 %0, t; }"
        : "=r"(a) : "l"(p));
    return a;
}
__device__ __forceinline__ void ldsm4(uint32_t (&r)[4], uint32_t addr) {
    asm volatile("ldmatrix.sync.aligned.m8n8.x4.shared.b16 {%0,%1,%2,%3}, [%4];"
        : "=r"(r[0]), "=r"(r[1]), "=r"(r[2]), "=r"(r[3]) : "r"(addr));
}
__device__ __forceinline__ void mma16816(float (&d)[4], const uint32_t (&a)[4],
                                         uint32_t b0, uint32_t b1) {
    asm volatile(
        "mma.sync.aligned.m16n8k16.row.col.f32.f16.f16.f32 "
        "{%0,%1,%2,%3}, {%4,%5,%6,%7}, {%8,%9}, {%0,%1,%2,%3};"
        : "+f"(d[0]), "+f"(d[1]), "+f"(d[2]), "+f"(d[3])
        : "r"(a[0]), "r"(a[1]), "r"(a[2]), "r"(a[3]), "r"(b0), "r"(b1));
}
__device__ __forceinline__ void fp16split(float v, ushort_t &h, ushort_t &l) {
    __half hb = __float2half_rn(v);
    __half lb = __float2half_rn(v - __half2float(hb));
    h = __half_as_ushort(hb);
    l = __half_as_ushort(lb);
}
__device__ __forceinline__ ushort_t fp16hi(float v) {
    return __half_as_ushort(__float2half_rn(v));
}

// ---------------------------------------------------------------------------
// prep: fp32 [M][1024] -> fp16 [M][2048] = [hi | lo]
// ---------------------------------------------------------------------------
__global__ __launch_bounds__(256) void prep_split_kernel(
    const float* __restrict__ X, ushort_t* __restrict__ Xs)
{
    const size_t r = blockIdx.x;
    const int c4 = threadIdx.x << 2;
    float4 v = *(const float4*)(X + r * 1024 + c4);
    ushort4 hv, lv;
    fp16split(v.x, hv.x, lv.x); fp16split(v.y, hv.y, lv.y);
    fp16split(v.z, hv.z, lv.z); fp16split(v.w, hv.w, lv.w);
    ushort_t* row = Xs + r * KSP_;
    *(ushort4*)(row + c4)        = hv;
    *(ushort4*)(row + 1024 + c4) = lv;
}

// ---------------------------------------------------------------------------
// prep: W [1024 k][N] fp32 -> Wh [N][1024] fp16 (hi only, transposed)
// ---------------------------------------------------------------------------
__global__ __launch_bounds__(256) void prep_wt_kernel(
    const float* __restrict__ W, ushort_t* __restrict__ Wt, int N)
{
    __shared__ float t[32][33];
    const int n0 = blockIdx.x << 5;
    const int k0 = blockIdx.y << 5;
    const int row = threadIdx.x >> 5;
    const int col = threadIdx.x & 31;
    #pragma unroll
    for (int p = 0; p < 4; ++p)
        t[row + p * 8][col] = W[(size_t)(k0 + row + p * 8) * N + n0 + col];
    __syncthreads();
    #pragma unroll
    for (int p = 0; p < 4; ++p) {
        int n = row + p * 8, k = col;
        Wt[(size_t)(n0 + n) * KW_ + k0 + k] = fp16hi(t[k][n]);
    }
}

// ---------------------------------------------------------------------------
// HMMA GEMM: C[M][N] = (Ah+Al)[M][1024] x Wh[N][1024]^T + bias
// Block 128x128, BK=32, 8 warps (64x32), double-buffered; B frags reused
// across both A terms (ldsm 10 : mma 32 per k16-step).
// ---------------------------------------------------------------------------
#define PITCH 40
#define ABUF  (128 * PITCH)     // 5120 halves per array buffer

__global__ __launch_bounds__(256, 2) void gemm_mma_kernel(
    const ushort_t* __restrict__ A,   // [M][2048] = [hi|lo]
    const ushort_t* __restrict__ Bh,  // [N][1024] hi
    const float* __restrict__ bias, float* __restrict__ C, int N)
{
    extern __shared__ ushort_t gs[];
    ushort_t* sAh = gs;                 // [2][ABUF]
    ushort_t* sAl = gs + 2 * ABUF;      // [2][ABUF]
    ushort_t* sBs = gs + 4 * ABUF;      // [2][ABUF]

    const int tid  = threadIdx.x;
    const int lane = tid & 31, wid = tid >> 5;
    const int m0 = blockIdx.y << 7, n0 = blockIdx.x << 7;
    const int wm = (wid & 1) << 6;
    const int wn = (wid >> 1) << 5;

    float acc[4][4][4];
    #pragma unroll
    for (int i = 0; i < 4; i++)
        #pragma unroll
        for (int j = 0; j < 4; j++)
            #pragma unroll
            for (int k = 0; k < 4; k++) acc[i][j][k] = 0.0f;

    // staging coords: 512 16B-chunks per array, 2 per thread
    const int r0s = tid >> 2;            // 0..63
    const int r1s = r0s + 64;            // 64..127
    const int js  = (tid & 3) << 3;      // 0,8,16,24 halves
    const ushort_t* gAh0 = A + (size_t)(m0 + r0s) * KSP_ + js;
    const ushort_t* gAh1 = A + (size_t)(m0 + r1s) * KSP_ + js;
    const ushort_t* gB0  = Bh + (size_t)(n0 + r0s) * KW_ + js;
    const ushort_t* gB1  = Bh + (size_t)(n0 + r1s) * KW_ + js;
    const int so0 = r0s * PITCH + js;
    const int so1 = r1s * PITCH + js;

    const uint32_t uAh = smem_u32(sAh), uAl = smem_u32(sAl), uBs = smem_u32(sBs);
    const uint32_t aoff = (uint32_t)((wm + (lane & 15)) * PITCH + (lane >> 4) * 8) * 2;
    const uint32_t boff = (uint32_t)((wn + (lane & 7) + ((lane >> 4) << 3)) * PITCH
                                     + ((lane >> 3) & 1) * 8) * 2;

    uint4 ph0 = *(const uint4*)gAh0;
    uint4 ph1 = *(const uint4*)gAh1;
    uint4 pl0 = *(const uint4*)(gAh0 + 1024);
    uint4 pl1 = *(const uint4*)(gAh1 + 1024);
    uint4 pb0 = *(const uint4*)gB0;
    uint4 pb1 = *(const uint4*)gB1;
    *(uint4*)&sAh[so0] = ph0; *(uint4*)&sAh[so1] = ph1;
    *(uint4*)&sAl[so0] = pl0; *(uint4*)&sAl[so1] = pl1;
    *(uint4*)&sBs[so0] = pb0; *(uint4*)&sBs[so1] = pb1;
    __syncthreads();

    for (int c = 0; c < 32; ++c) {
        const int buf = c & 1;
        if (c + 1 < 32) {
            const int kc = (c + 1) << 5;
            ph0 = *(const uint4*)(gAh0 + kc);
            ph1 = *(const uint4*)(gAh1 + kc);
            pl0 = *(const uint4*)(gAh0 + 1024 + kc);
            pl1 = *(const uint4*)(gAh1 + 1024 + kc);
            pb0 = *(const uint4*)(gB0 + kc);
            pb1 = *(const uint4*)(gB1 + kc);
        }
        const uint32_t aHB = uAh + buf * (ABUF * 2) + aoff;
        const uint32_t aLB = uAl + buf * (ABUF * 2) + aoff;
        const uint32_t bBB = uBs + buf * (ABUF * 2) + boff;
        #pragma unroll
        for (int ks = 0; ks < 2; ++ks) {
            uint32_t bf[2][4];
            ldsm4(bf[0], bBB + ks * 32);
            ldsm4(bf[1], bBB + (16 * PITCH * 2) + ks * 32);
            uint32_t af[4][4];
            #pragma unroll
            for (int mi = 0; mi < 4; ++mi)
                ldsm4(af[mi], aHB + mi * (16 * PITCH * 2) + ks * 32);
            #pragma unroll
            for (int mi = 0; mi < 4; ++mi) {
                mma16816(acc[mi][0], af[mi], bf[0][0], bf[0][1]);
                mma16816(acc[mi][1], af[mi], bf[0][2], bf[0][3]);
                mma16816(acc[mi][2], af[mi], bf[1][0], bf[1][1]);
                mma16816(acc[mi][3], af[mi], bf[1][2], bf[1][3]);
            }
            #pragma unroll
            for (int mi = 0; mi < 4; ++mi)
                ldsm4(af[mi], aLB + mi * (16 * PITCH * 2) + ks * 32);
            #pragma unroll
            for (int mi = 0; mi < 4; ++mi) {
                mma16816(acc[mi][0], af[mi], bf[0][0], bf[0][1]);
                mma16816(acc[mi][1], af[mi], bf[0][2], bf[0][3]);
                mma16816(acc[mi][2], af[mi], bf[1][0], bf[1][1]);
                mma16816(acc[mi][3], af[mi], bf[1][2], bf[1][3]);
            }
        }
        if (c + 1 < 32) {
            __syncthreads();
            *(uint4*)&sAh[(1 - buf) * ABUF + so0] = ph0;
            *(uint4*)&sAh[(1 - buf) * ABUF + so1] = ph1;
            *(uint4*)&sAl[(1 - buf) * ABUF + so0] = pl0;
            *(uint4*)&sAl[(1 - buf) * ABUF + so1] = pl1;
            *(uint4*)&sBs[(1 - buf) * ABUF + so0] = pb0;
            *(uint4*)&sBs[(1 - buf) * ABUF + so1] = pb1;
            __syncthreads();
        }
    }

    const int g  = lane >> 2;
    const int tg = (lane & 3) << 1;
    #pragma unroll
    for (int ni = 0; ni < 4; ++ni) {
        int col = n0 + wn + ni * 8 + tg;
        float2 bv = *(const float2*)(bias + col);
        #pragma unroll
        for (int mi = 0; mi < 4; ++mi) {
            int r0 = m0 + wm + mi * 16 + g;
            float2 v0 = make_float2(acc[mi][ni][0] + bv.x, acc[mi][ni][1] + bv.y);
            float2 v1 = make_float2(acc[mi][ni][2] + bv.x, acc[mi][ni][3] + bv.y);
            *(float2*)&C[(size_t)r0 * N + col]       = v0;
            *(float2*)&C[(size_t)(r0 + 8) * N + col] = v1;
        }
    }
}

// ---------------------------------------------------------------------------
// Fused attention (fp16 2-term split).
// pass1: S = exp((Qh+Ql)·Kh /8) -> scratch fp32; row sums.
// pass2: P=relu(e*linv-TH) split; Y = (Ph+Pl)·Vh -> g_ys [hi|lo].
// ---------------------------------------------------------------------------
struct SmemAttn2 {
    float l_red[128];
    float l_inv[128];
    union {
        struct { ushort_t Qh[128 * PQ_], Ql[128 * PQ_], Kh[128 * PQ_]; } p1; // 54 KB
        struct { ushort_t Ph[128 * PQ_], Pl[128 * PQ_], Vh[64 * PQ_];  } p2; // 45 KB
    } u;
};

__global__ __launch_bounds__(256, 2) void fused_attn_mma_kernel(
    const float* __restrict__ qkv, float* __restrict__ scratch,
    ushort_t* __restrict__ Ys)
{
    extern __shared__ char smem_raw[];
    SmemAttn2& sm = *reinterpret_cast<SmemAttn2*>(smem_raw);

    const int qb = blockIdx.x;       // 0..7
    const int bh = blockIdx.y;       // 0..127
    const int b  = bh >> 4;
    const int h  = bh & 15;
    const float* qbase = qkv + (size_t)b * T_ * C3_ + h * HD_;
    const float* kbase = qbase + C_;
    const float* vbase = qbase + 2 * C_;
    float* sc = scratch + (((size_t)bh * 8 + qb) << 17);   // [128 q][1024 k]

    const int tid  = threadIdx.x;
    const int lane = tid & 31, wid = tid >> 5;
    const int q0   = qb << 7;
    const int g    = lane >> 2;

    if (tid < 128) sm.l_red[tid] = 0.0f;

    // ---- stage Q (128 x 64) split
    #pragma unroll
    for (int l = 0; l < 8; ++l) {
        int idx = tid + (l << 8);
        int r   = idx >> 4;
        int c4  = (idx & 15) << 2;
        float4 v = *(const float4*)(qbase + (size_t)(q0 + r) * C3_ + c4);
        ushort4 hv, lv;
        fp16split(v.x, hv.x, lv.x); fp16split(v.y, hv.y, lv.y);
        fp16split(v.z, hv.z, lv.z); fp16split(v.w, hv.w, lv.w);
        *(ushort4*)&sm.u.p1.Qh[r * PQ_ + c4] = hv;
        *(ushort4*)&sm.u.p1.Ql[r * PQ_ + c4] = lv;
    }

    const int wm = (wid & 1) << 6;
    const int wn = (wid >> 1) << 5;
    const uint32_t sQh = smem_u32(sm.u.p1.Qh), sQl = smem_u32(sm.u.p1.Ql);
    const uint32_t sKh = smem_u32(sm.u.p1.Kh);
    const uint32_t aoff = (uint32_t)((wm + (lane & 15)) * PQ_ + (lane >> 4) * 8) * 2;
    const uint32_t boff = (uint32_t)((wn + (lane & 7) + ((lane >> 4) << 3)) * PQ_
                                     + ((lane >> 3) & 1) * 8) * 2;

    float lsum[8];
    #pragma unroll
    for (int i = 0; i < 8; i++) lsum[i] = 0.0f;

    for (int k0 = 0; k0 < T_; k0 += 128) {
        __syncthreads();
        #pragma unroll
        for (int l = 0; l < 8; ++l) {
            int idx = tid + (l << 8);
            int r   = idx >> 4;
            int c4  = (idx & 15) << 2;
            float4 v = *(const float4*)(kbase + (size_t)(k0 + r) * C3_ + c4);
            ushort4 hv;
            hv.x = fp16hi(v.x); hv.y = fp16hi(v.y);
            hv.z = fp16hi(v.z); hv.w = fp16hi(v.w);
            *(ushort4*)&sm.u.p1.Kh[r * PQ_ + c4] = hv;
        }
        __syncthreads();

        float acc[4][4][4];
        #pragma unroll
        for (int i = 0; i < 4; i++)
            #pragma unroll
            for (int j = 0; j < 4; j++)
                #pragma unroll
                for (int k = 0; k < 4; k++) acc[i][j][k] = 0.0f;

        #pragma unroll
        for (int ks = 0; ks < 4; ++ks) {
            uint32_t bf[2][4];
            ldsm4(bf[0], sKh + boff + ks * 32);
            ldsm4(bf[1], sKh + boff + (16 * PQ_ * 2) + ks * 32);
            uint32_t af[4][4];
            #pragma unroll
            for (int mi = 0; mi < 4; ++mi)
                ldsm4(af[mi], sQh + aoff + mi * (16 * PQ_ * 2) + ks * 32);
            #pragma unroll
            for (int mi = 0; mi < 4; ++mi) {
                mma16816(acc[mi][0], af[mi], bf[0][0], bf[0][1]);
                mma16816(acc[mi][1], af[mi], bf[0][2], bf[0][3]);
                mma16816(acc[mi][2], af[mi], bf[1][0], bf[1][1]);
                mma16816(acc[mi][3], af[mi], bf[1][2], bf[1][3]);
            }
            #pragma unroll
            for (int mi = 0; mi < 4; ++mi)
                ldsm4(af[mi], sQl + aoff + mi * (16 * PQ_ * 2) + ks * 32);
            #pragma unroll
            for (int mi = 0; mi < 4; ++mi) {
                mma16816(acc[mi][0], af[mi], bf[0][0], bf[0][1]);
                mma16816(acc[mi][1], af[mi], bf[0][2], bf[0][3]);
                mma16816(acc[mi][2], af[mi], bf[1][0], bf[1][1]);
                mma16816(acc[mi][3], af[mi], bf[1][2], bf[1][3]);
            }
        }

        // exp epilogue -> scratch, row sums
        #pragma unroll
        for (int mi = 0; mi < 4; ++mi) {
            #pragma unroll
            for (int ni = 0; ni < 4; ++ni) {
                float e0 = __expf(acc[mi][ni][0] * 0.125f);
                float e1 = __expf(acc[mi][ni][1] * 0.125f);
                float e2 = __expf(acc[mi][ni][2] * 0.125f);
                float e3 = __expf(acc[mi][ni][3] * 0.125f);
                lsum[mi * 2 + 0] += e0 + e1;
                lsum[mi * 2 + 1] += e2 + e3;
                int col = k0 + wn + ni * 8 + ((lane & 3) << 1);
                int r0  = wm + mi * 16 + g;
                *(float2*)(sc + (size_t)r0 * 1024 + col)       = make_float2(e0, e1);
                *(float2*)(sc + (size_t)(r0 + 8) * 1024 + col) = make_float2(e2, e3);
            }
        }
    }

    #pragma unroll
    for (int i = 0; i < 8; i++) {
        float v = lsum[i];
        v += __shfl_xor_sync(0xFFFFFFFFu, v, 1);
        v += __shfl_xor_sync(0xFFFFFFFFu, v, 2);
        if ((lane & 3) == 0) {
            int row = wm + (i >> 1) * 16 + g + (i & 1) * 8;
            atomicAdd(&sm.l_red[row], v);
        }
    }
    __syncthreads();
    if (tid < 128) sm.l_inv[tid] = 1.0f / sm.l_red[tid];

    // ---- pass 2
    const int wm2 = (wid & 1) << 6;
    const int wn2 = (wid >> 1) << 4;
    const uint32_t sPh = smem_u32(sm.u.p2.Ph), sPl = smem_u32(sm.u.p2.Pl);
    const uint32_t sVh = smem_u32(sm.u.p2.Vh);
    const uint32_t aoff2 = (uint32_t)((wm2 + (lane & 15)) * PQ_ + (lane >> 4) * 8) * 2;
    const uint32_t boff2 = (uint32_t)((wn2 + (lane & 7) + ((lane >> 4) << 3)) * PQ_
                                      + ((lane >> 3) & 1) * 8) * 2;

    float accy[4][2][4];
    #pragma unroll
    for (int i = 0; i < 4; i++)
        #pragma unroll
        for (int j = 0; j < 2; j++)
            #pragma unroll
            for (int k = 0; k < 4; k++) accy[i][j][k] = 0.0f;

    for (int kc = 0; kc < T_; kc += 64) {
        __syncthreads();
        // stage P split (128 q x 64 k)
        #pragma unroll
        for (int l = 0; l < 8; ++l) {
            int idx = tid + (l << 8);
            int r   = idx >> 4;
            int c4  = (idx & 15) << 2;
            float4 e = *(const float4*)(sc + (size_t)r * 1024 + kc + c4);
            float iv = sm.l_inv[r];
            float p0 = fmaxf(fmaf(e.x, iv, -TH_), 0.0f);
            float p1 = fmaxf(fmaf(e.y, iv, -TH_), 0.0f);
            float p2 = fmaxf(fmaf(e.z, iv, -TH_), 0.0f);
            float p3 = fmaxf(fmaf(e.w, iv, -TH_), 0.0f);
            ushort4 hv, lv;
            fp16split(p0, hv.x, lv.x); fp16split(p1, hv.y, lv.y);
            fp16split(p2, hv.z, lv.z); fp16split(p3, hv.w, lv.w);
            *(ushort4*)&sm.u.p2.Ph[r * PQ_ + c4] = hv;
            *(ushort4*)&sm.u.p2.Pl[r * PQ_ + c4] = lv;
        }
        // stage V transposed Vh[d][k] (64 x 64), hi only
        #pragma unroll
        for (int l = 0; l < 4; ++l) {
            int idx = tid + (l << 8);
            int r   = idx >> 4;            // key within chunk
            int c4  = (idx & 15) << 2;     // d
            float4 v = *(const float4*)(vbase + (size_t)(kc + r) * C3_ + c4);
            sm.u.p2.Vh[(c4 + 0) * PQ_ + r] = fp16hi(v.x);
            sm.u.p2.Vh[(c4 + 1) * PQ_ + r] = fp16hi(v.y);
            sm.u.p2.Vh[(c4 + 2) * PQ_ + r] = fp16hi(v.z);
            sm.u.p2.Vh[(c4 + 3) * PQ_ + r] = fp16hi(v.w);
        }
        __syncthreads();

        #pragma unroll
        for (int ks = 0; ks < 4; ++ks) {
            uint32_t bf[4];
            ldsm4(bf, sVh + boff2 + ks * 32);
            uint32_t af[4][4];
            #pragma unroll
            for (int mi = 0; mi < 4; ++mi)
                ldsm4(af[mi], sPh + aoff2 + mi * (16 * PQ_ * 2) + ks * 32);
            #pragma unroll
            for (int mi = 0; mi < 4; ++mi) {
                mma16816(accy[mi][0], af[mi], bf[0], bf[1]);
                mma16816(accy[mi][1], af[mi], bf[2], bf[3]);
            }
            #pragma unroll
            for (int mi = 0; mi < 4; ++mi)
                ldsm4(af[mi], sPl + aoff2 + mi * (16 * PQ_ * 2) + ks * 32);
            #pragma unroll
            for (int mi = 0; mi < 4; ++mi) {
                mma16816(accy[mi][0], af[mi], bf[0], bf[1]);
                mma16816(accy[mi][1], af[mi], bf[2], bf[3]);
            }
        }
    }

    // epilogue: Y -> g_ys in [hi | lo] split layout
    #pragma unroll
    for (int mi = 0; mi < 4; ++mi) {
        #pragma unroll
        for (int ni = 0; ni < 2; ++ni) {
            int ch = h * HD_ + wn2 + ni * 8 + ((lane & 3) << 1);
            #pragma unroll
            for (int hv = 0; hv < 2; ++hv) {
                int rq = q0 + wm2 + mi * 16 + g + hv * 8;
                size_t rg = ((size_t)b * T_ + rq) * KSP_;
                ushort2 hp, lp;
                fp16split(accy[mi][ni][hv * 2 + 0], hp.x, lp.x);
                fp16split(accy[mi][ni][hv * 2 + 1], hp.y, lp.y);
                *(ushort2*)&Ys[rg + ch]        = hp;
                *(ushort2*)&Ys[rg + 1024 + ch] = lp;
            }
        }
    }
}

// ---------------------------------------------------------------------------
extern "C" void kernel_launch(void* const* d_in, const int* in_sizes, int n_in,
                              void* d_out, int out_size)
{
    const float* x      = (const float*)d_in[0];
    const float* w_attn = (const float*)d_in[1];
    const float* b_attn = (const float*)d_in[2];
    const float* w_proj = (const float*)d_in[3];
    const float* b_proj = (const float*)d_in[4];
    float* out = (float*)d_out;

    float *qkv, *S;
    ushort_t *xs, *ys, *wa, *wp;
    cudaGetSymbolAddress((void**)&qkv, g_qkv);
    cudaGetSymbolAddress((void**)&S,   g_S);
    cudaGetSymbolAddress((void**)&xs,  g_xs);
    cudaGetSymbolAddress((void**)&ys,  g_ys);
    cudaGetSymbolAddress((void**)&wa,  g_wa);
    cudaGetSymbolAddress((void**)&wp,  g_wp);

    const int gemm_smem = 6 * ABUF * 2;              // 61440 B
    cudaFuncSetAttribute(gemm_mma_kernel,
                         cudaFuncAttributeMaxDynamicSharedMemorySize, gemm_smem);
    cudaFuncSetAttribute(fused_attn_mma_kernel,
                         cudaFuncAttributeMaxDynamicSharedMemorySize,
                         (int)sizeof(SmemAttn2));

    // prep
    prep_split_kernel<<<B_ * T_, 256>>>(x, xs);
    prep_wt_kernel<<<dim3(C3_ / 32, C_ / 32), 256>>>(w_attn, wa, C3_);
    prep_wt_kernel<<<dim3(C_ / 32, C_ / 32), 256>>>(w_proj, wp, C_);

    // 1) QKV projection
    gemm_mma_kernel<<<dim3(C3_ / 128, (B_ * T_) / 128), 256, gemm_smem>>>(
        xs, wa, b_attn, qkv, C3_);

    // 2) fused attention
    fused_attn_mma_kernel<<<dim3(T_ / 128, BH_), 256, sizeof(SmemAttn2)>>>(
        qkv, S, ys);

    // 3) output projection
    gemm_mma_kernel<<<dim3(C_ / 128, (B_ * T_) / 128), 256, gemm_smem>>>(
        ys, wp, b_proj, out, C_);
}

// round 8
// speedup vs baseline: 3.6705x; 1.0785x over previous
#include <cuda_runtime.h>
#include <cuda_fp16.h>
#include <cstddef>
#include <cstdint>

#define B_   8
#define T_   1024
#define C_   1024
#define H_   16
#define HD_  64
#define BH_  (B_ * H_)          // 128
#define C3_  (3 * C_)           // 3072
#define KSP_ 2048               // split-K' = 2*1024 ([hi | lo])
#define KW_  1024               // weight hi-only K
#define TH_  0.001f
#define PQ_  72                 // pass1 smem pitch (halves)
#define PV_  136                // pass2 smem pitch (halves), 272B rows

using ushort_t = unsigned short;

// ---------------- scratch (static device globals) ----------------
__device__ __align__(16) float g_qkv[(size_t)B_ * T_ * C3_];            // 96 MB
__device__ __align__(16) ushort_t g_S[(size_t)BH_ * T_ * T_];           // 256 MB fp16 exp
__device__ __align__(16) ushort_t g_xs[(size_t)B_ * T_ * KSP_];         // x  [hi|lo] fp16
__device__ __align__(16) ushort_t g_ys[(size_t)B_ * T_ * KSP_];         // Y  [hi|lo] fp16
__device__ __align__(16) ushort_t g_wa[(size_t)C3_ * KW_];              // w_attn^T hi
__device__ __align__(16) ushort_t g_wp[(size_t)C_ * KW_];               // w_proj^T hi

// ---------------- helpers ----------------
__device__ __forceinline__ uint32_t smem_u32(const void* p) {
    uint32_t a;
    asm("{ .reg .u64 t; cvta.to.shared.u64 t, %1; cvt.u32.u64 %0, t; }"
        : "=r"(a) : "l"(p));
    return a;
}
__device__ __forceinline__ void ldsm4(uint32_t (&r)[4], uint32_t addr) {
    asm volatile("ldmatrix.sync.aligned.m8n8.x4.shared.b16 {%0,%1,%2,%3}, [%4];"
        : "=r"(r[0]), "=r"(r[1]), "=r"(r[2]), "=r"(r[3]) : "r"(addr));
}
__device__ __forceinline__ void mma16816(float (&d)[4], const uint32_t (&a)[4],
                                         uint32_t b0, uint32_t b1) {
    asm volatile(
        "mma.sync.aligned.m16n8k16.row.col.f32.f16.f16.f32 "
        "{%0,%1,%2,%3}, {%4,%5,%6,%7}, {%8,%9}, {%0,%1,%2,%3};"
        : "+f"(d[0]), "+f"(d[1]), "+f"(d[2]), "+f"(d[3])
        : "r"(a[0]), "r"(a[1]), "r"(a[2]), "r"(a[3]), "r"(b0), "r"(b1));
}
__device__ __forceinline__ void fp16split(float v, ushort_t &h, ushort_t &l) {
    __half hb = __float2half_rn(v);
    __half lb = __float2half_rn(v - __half2float(hb));
    h = __half_as_ushort(hb);
    l = __half_as_ushort(lb);
}
__device__ __forceinline__ ushort_t fp16hi(float v) {
    return __half_as_ushort(__float2half_rn(v));
}
__device__ __forceinline__ float fp16f(ushort_t u) {
    return __half2float(__ushort_as_half(u));
}

// ---------------------------------------------------------------------------
// prep: fp32 [M][1024] -> fp16 [M][2048] = [hi | lo]
// ---------------------------------------------------------------------------
__global__ __launch_bounds__(256) void prep_split_kernel(
    const float* __restrict__ X, ushort_t* __restrict__ Xs)
{
    const size_t r = blockIdx.x;
    const int c4 = threadIdx.x << 2;
    float4 v = *(const float4*)(X + r * 1024 + c4);
    ushort4 hv, lv;
    fp16split(v.x, hv.x, lv.x); fp16split(v.y, hv.y, lv.y);
    fp16split(v.z, hv.z, lv.z); fp16split(v.w, hv.w, lv.w);
    ushort_t* row = Xs + r * KSP_;
    *(ushort4*)(row + c4)        = hv;
    *(ushort4*)(row + 1024 + c4) = lv;
}

// ---------------------------------------------------------------------------
// prep: W [1024 k][N] fp32 -> Wh [N][1024] fp16 (hi only, transposed)
// ---------------------------------------------------------------------------
__global__ __launch_bounds__(256) void prep_wt_kernel(
    const float* __restrict__ W, ushort_t* __restrict__ Wt, int N)
{
    __shared__ float t[32][33];
    const int n0 = blockIdx.x << 5;
    const int k0 = blockIdx.y << 5;
    const int row = threadIdx.x >> 5;
    const int col = threadIdx.x & 31;
    #pragma unroll
    for (int p = 0; p < 4; ++p)
        t[row + p * 8][col] = W[(size_t)(k0 + row + p * 8) * N + n0 + col];
    __syncthreads();
    #pragma unroll
    for (int p = 0; p < 4; ++p) {
        int n = row + p * 8, k = col;
        Wt[(size_t)(n0 + n) * KW_ + k0 + k] = fp16hi(t[k][n]);
    }
}

// ---------------------------------------------------------------------------
// HMMA GEMM (unchanged from R7): C = (Ah+Al)[M][1024] x Wh[N][1024]^T + bias
// ---------------------------------------------------------------------------
#define PITCH 40
#define ABUF  (128 * PITCH)

__global__ __launch_bounds__(256, 2) void gemm_mma_kernel(
    const ushort_t* __restrict__ A,
    const ushort_t* __restrict__ Bh,
    const float* __restrict__ bias, float* __restrict__ C, int N)
{
    extern __shared__ ushort_t gs[];
    ushort_t* sAh = gs;
    ushort_t* sAl = gs + 2 * ABUF;
    ushort_t* sBs = gs + 4 * ABUF;

    const int tid  = threadIdx.x;
    const int lane = tid & 31, wid = tid >> 5;
    const int m0 = blockIdx.y << 7, n0 = blockIdx.x << 7;
    const int wm = (wid & 1) << 6;
    const int wn = (wid >> 1) << 5;

    float acc[4][4][4];
    #pragma unroll
    for (int i = 0; i < 4; i++)
        #pragma unroll
        for (int j = 0; j < 4; j++)
            #pragma unroll
            for (int k = 0; k < 4; k++) acc[i][j][k] = 0.0f;

    const int r0s = tid >> 2;
    const int r1s = r0s + 64;
    const int js  = (tid & 3) << 3;
    const ushort_t* gAh0 = A + (size_t)(m0 + r0s) * KSP_ + js;
    const ushort_t* gAh1 = A + (size_t)(m0 + r1s) * KSP_ + js;
    const ushort_t* gB0  = Bh + (size_t)(n0 + r0s) * KW_ + js;
    const ushort_t* gB1  = Bh + (size_t)(n0 + r1s) * KW_ + js;
    const int so0 = r0s * PITCH + js;
    const int so1 = r1s * PITCH + js;

    const uint32_t uAh = smem_u32(sAh), uAl = smem_u32(sAl), uBs = smem_u32(sBs);
    const uint32_t aoff = (uint32_t)((wm + (lane & 15)) * PITCH + (lane >> 4) * 8) * 2;
    const uint32_t boff = (uint32_t)((wn + (lane & 7) + ((lane >> 4) << 3)) * PITCH
                                     + ((lane >> 3) & 1) * 8) * 2;

    uint4 ph0 = *(const uint4*)gAh0;
    uint4 ph1 = *(const uint4*)gAh1;
    uint4 pl0 = *(const uint4*)(gAh0 + 1024);
    uint4 pl1 = *(const uint4*)(gAh1 + 1024);
    uint4 pb0 = *(const uint4*)gB0;
    uint4 pb1 = *(const uint4*)gB1;
    *(uint4*)&sAh[so0] = ph0; *(uint4*)&sAh[so1] = ph1;
    *(uint4*)&sAl[so0] = pl0; *(uint4*)&sAl[so1] = pl1;
    *(uint4*)&sBs[so0] = pb0; *(uint4*)&sBs[so1] = pb1;
    __syncthreads();

    for (int c = 0; c < 32; ++c) {
        const int buf = c & 1;
        if (c + 1 < 32) {
            const int kc = (c + 1) << 5;
            ph0 = *(const uint4*)(gAh0 + kc);
            ph1 = *(const uint4*)(gAh1 + kc);
            pl0 = *(const uint4*)(gAh0 + 1024 + kc);
            pl1 = *(const uint4*)(gAh1 + 1024 + kc);
            pb0 = *(const uint4*)(gB0 + kc);
            pb1 = *(const uint4*)(gB1 + kc);
        }
        const uint32_t aHB = uAh + buf * (ABUF * 2) + aoff;
        const uint32_t aLB = uAl + buf * (ABUF * 2) + aoff;
        const uint32_t bBB = uBs + buf * (ABUF * 2) + boff;
        #pragma unroll
        for (int ks = 0; ks < 2; ++ks) {
            uint32_t bf[2][4];
            ldsm4(bf[0], bBB + ks * 32);
            ldsm4(bf[1], bBB + (16 * PITCH * 2) + ks * 32);
            uint32_t af[4][4];
            #pragma unroll
            for (int mi = 0; mi < 4; ++mi)
                ldsm4(af[mi], aHB + mi * (16 * PITCH * 2) + ks * 32);
            #pragma unroll
            for (int mi = 0; mi < 4; ++mi) {
                mma16816(acc[mi][0], af[mi], bf[0][0], bf[0][1]);
                mma16816(acc[mi][1], af[mi], bf[0][2], bf[0][3]);
                mma16816(acc[mi][2], af[mi], bf[1][0], bf[1][1]);
                mma16816(acc[mi][3], af[mi], bf[1][2], bf[1][3]);
            }
            #pragma unroll
            for (int mi = 0; mi < 4; ++mi)
                ldsm4(af[mi], aLB + mi * (16 * PITCH * 2) + ks * 32);
            #pragma unroll
            for (int mi = 0; mi < 4; ++mi) {
                mma16816(acc[mi][0], af[mi], bf[0][0], bf[0][1]);
                mma16816(acc[mi][1], af[mi], bf[0][2], bf[0][3]);
                mma16816(acc[mi][2], af[mi], bf[1][0], bf[1][1]);
                mma16816(acc[mi][3], af[mi], bf[1][2], bf[1][3]);
            }
        }
        if (c + 1 < 32) {
            __syncthreads();
            *(uint4*)&sAh[(1 - buf) * ABUF + so0] = ph0;
            *(uint4*)&sAh[(1 - buf) * ABUF + so1] = ph1;
            *(uint4*)&sAl[(1 - buf) * ABUF + so0] = pl0;
            *(uint4*)&sAl[(1 - buf) * ABUF + so1] = pl1;
            *(uint4*)&sBs[(1 - buf) * ABUF + so0] = pb0;
            *(uint4*)&sBs[(1 - buf) * ABUF + so1] = pb1;
            __syncthreads();
        }
    }

    const int g  = lane >> 2;
    const int tg = (lane & 3) << 1;
    #pragma unroll
    for (int ni = 0; ni < 4; ++ni) {
        int col = n0 + wn + ni * 8 + tg;
        float2 bv = *(const float2*)(bias + col);
        #pragma unroll
        for (int mi = 0; mi < 4; ++mi) {
            int r0 = m0 + wm + mi * 16 + g;
            float2 v0 = make_float2(acc[mi][ni][0] + bv.x, acc[mi][ni][1] + bv.y);
            float2 v1 = make_float2(acc[mi][ni][2] + bv.x, acc[mi][ni][3] + bv.y);
            *(float2*)&C[(size_t)r0 * N + col]       = v0;
            *(float2*)&C[(size_t)(r0 + 8) * N + col] = v1;
        }
    }
}

// ---------------------------------------------------------------------------
// Fused attention.
// pass1: S = exp((Qh+Ql)·Kh /8) -> scratch fp16; fp32 row sums.
// pass2 (k-chunks 128): P = relu(e*linv - TH) fp16 (single term); Y = P·Vh.
// ---------------------------------------------------------------------------
struct SmemAttn2 {
    float l_red[128];
    float l_inv[128];
    union {
        struct { ushort_t Qh[128 * PQ_], Ql[128 * PQ_], Kh[128 * PQ_]; } p1; // 54 KB
        struct { ushort_t Ph[128 * PV_], Vh[64 * PV_]; } p2;                 // 51 KB
    } u;
};

__global__ __launch_bounds__(256, 2) void fused_attn_mma_kernel(
    const float* __restrict__ qkv, ushort_t* __restrict__ scratch,
    ushort_t* __restrict__ Ys)
{
    extern __shared__ char smem_raw[];
    SmemAttn2& sm = *reinterpret_cast<SmemAttn2*>(smem_raw);

    const int qb = blockIdx.x;       // 0..7
    const int bh = blockIdx.y;       // 0..127
    const int b  = bh >> 4;
    const int h  = bh & 15;
    const float* qbase = qkv + (size_t)b * T_ * C3_ + h * HD_;
    const float* kbase = qbase + C_;
    const float* vbase = qbase + 2 * C_;
    ushort_t* sc = scratch + (((size_t)bh * 8 + qb) << 17);  // [128 q][1024 k] fp16

    const int tid  = threadIdx.x;
    const int lane = tid & 31, wid = tid >> 5;
    const int q0   = qb << 7;
    const int g    = lane >> 2;

    if (tid < 128) sm.l_red[tid] = 0.0f;

    // ---- stage Q (128 x 64) split
    #pragma unroll
    for (int l = 0; l < 8; ++l) {
        int idx = tid + (l << 8);
        int r   = idx >> 4;
        int c4  = (idx & 15) << 2;
        float4 v = *(const float4*)(qbase + (size_t)(q0 + r) * C3_ + c4);
        ushort4 hv, lv;
        fp16split(v.x, hv.x, lv.x); fp16split(v.y, hv.y, lv.y);
        fp16split(v.z, hv.z, lv.z); fp16split(v.w, hv.w, lv.w);
        *(ushort4*)&sm.u.p1.Qh[r * PQ_ + c4] = hv;
        *(ushort4*)&sm.u.p1.Ql[r * PQ_ + c4] = lv;
    }

    const int wm = (wid & 1) << 6;
    const int wn = (wid >> 1) << 5;
    const uint32_t sQh = smem_u32(sm.u.p1.Qh), sQl = smem_u32(sm.u.p1.Ql);
    const uint32_t sKh = smem_u32(sm.u.p1.Kh);
    const uint32_t aoff = (uint32_t)((wm + (lane & 15)) * PQ_ + (lane >> 4) * 8) * 2;
    const uint32_t boff = (uint32_t)((wn + (lane & 7) + ((lane >> 4) << 3)) * PQ_
                                     + ((lane >> 3) & 1) * 8) * 2;

    float lsum[8];
    #pragma unroll
    for (int i = 0; i < 8; i++) lsum[i] = 0.0f;

    for (int k0 = 0; k0 < T_; k0 += 128) {
        __syncthreads();
        #pragma unroll
        for (int l = 0; l < 8; ++l) {
            int idx = tid + (l << 8);
            int r   = idx >> 4;
            int c4  = (idx & 15) << 2;
            float4 v = *(const float4*)(kbase + (size_t)(k0 + r) * C3_ + c4);
            ushort4 hv;
            hv.x = fp16hi(v.x); hv.y = fp16hi(v.y);
            hv.z = fp16hi(v.z); hv.w = fp16hi(v.w);
            *(ushort4*)&sm.u.p1.Kh[r * PQ_ + c4] = hv;
        }
        __syncthreads();

        float acc[4][4][4];
        #pragma unroll
        for (int i = 0; i < 4; i++)
            #pragma unroll
            for (int j = 0; j < 4; j++)
                #pragma unroll
                for (int k = 0; k < 4; k++) acc[i][j][k] = 0.0f;

        #pragma unroll
        for (int ks = 0; ks < 4; ++ks) {
            uint32_t bf[2][4];
            ldsm4(bf[0], sKh + boff + ks * 32);
            ldsm4(bf[1], sKh + boff + (16 * PQ_ * 2) + ks * 32);
            uint32_t af[4][4];
            #pragma unroll
            for (int mi = 0; mi < 4; ++mi)
                ldsm4(af[mi], sQh + aoff + mi * (16 * PQ_ * 2) + ks * 32);
            #pragma unroll
            for (int mi = 0; mi < 4; ++mi) {
                mma16816(acc[mi][0], af[mi], bf[0][0], bf[0][1]);
                mma16816(acc[mi][1], af[mi], bf[0][2], bf[0][3]);
                mma16816(acc[mi][2], af[mi], bf[1][0], bf[1][1]);
                mma16816(acc[mi][3], af[mi], bf[1][2], bf[1][3]);
            }
            #pragma unroll
            for (int mi = 0; mi < 4; ++mi)
                ldsm4(af[mi], sQl + aoff + mi * (16 * PQ_ * 2) + ks * 32);
            #pragma unroll
            for (int mi = 0; mi < 4; ++mi) {
                mma16816(acc[mi][0], af[mi], bf[0][0], bf[0][1]);
                mma16816(acc[mi][1], af[mi], bf[0][2], bf[0][3]);
                mma16816(acc[mi][2], af[mi], bf[1][0], bf[1][1]);
                mma16816(acc[mi][3], af[mi], bf[1][2], bf[1][3]);
            }
        }

        // exp epilogue -> fp16 scratch; fp32 row sums
        #pragma unroll
        for (int mi = 0; mi < 4; ++mi) {
            #pragma unroll
            for (int ni = 0; ni < 4; ++ni) {
                float e0 = __expf(acc[mi][ni][0] * 0.125f);
                float e1 = __expf(acc[mi][ni][1] * 0.125f);
                float e2 = __expf(acc[mi][ni][2] * 0.125f);
                float e3 = __expf(acc[mi][ni][3] * 0.125f);
                lsum[mi * 2 + 0] += e0 + e1;
                lsum[mi * 2 + 1] += e2 + e3;
                int col = k0 + wn + ni * 8 + ((lane & 3) << 1);
                int r0  = wm + mi * 16 + g;
                ushort2 u01 = make_ushort2(fp16hi(e0), fp16hi(e1));
                ushort2 u23 = make_ushort2(fp16hi(e2), fp16hi(e3));
                *(ushort2*)(sc + (size_t)r0 * 1024 + col)       = u01;
                *(ushort2*)(sc + (size_t)(r0 + 8) * 1024 + col) = u23;
            }
        }
    }

    #pragma unroll
    for (int i = 0; i < 8; i++) {
        float v = lsum[i];
        v += __shfl_xor_sync(0xFFFFFFFFu, v, 1);
        v += __shfl_xor_sync(0xFFFFFFFFu, v, 2);
        if ((lane & 3) == 0) {
            int row = wm + (i >> 1) * 16 + g + (i & 1) * 8;
            atomicAdd(&sm.l_red[row], v);
        }
    }
    __syncthreads();
    if (tid < 128) sm.l_inv[tid] = 1.0f / sm.l_red[tid];

    // ---- pass 2: k-chunks of 128, single-term P·Vh
    const int wm2 = (wid & 1) << 6;
    const int wn2 = (wid >> 1) << 4;
    const uint32_t sPh = smem_u32(sm.u.p2.Ph);
    const uint32_t sVh = smem_u32(sm.u.p2.Vh);
    const uint32_t aoff2 = (uint32_t)((wm2 + (lane & 15)) * PV_ + (lane >> 4) * 8) * 2;
    const uint32_t boff2 = (uint32_t)((wn2 + (lane & 7) + ((lane >> 4) << 3)) * PV_
                                      + ((lane >> 3) & 1) * 8) * 2;

    float accy[4][2][4];
    #pragma unroll
    for (int i = 0; i < 4; i++)
        #pragma unroll
        for (int j = 0; j < 2; j++)
            #pragma unroll
            for (int k = 0; k < 4; k++) accy[i][j][k] = 0.0f;

    for (int kc = 0; kc < T_; kc += 128) {
        __syncthreads();
        // stage P = relu(e * linv - TH) fp16 (128 q x 128 k)
        #pragma unroll
        for (int l = 0; l < 16; ++l) {
            int idx = tid + (l << 8);
            int r   = idx >> 5;            // 0..127 (q)
            int c4  = (idx & 31) << 2;     // 0..124 (k within chunk)
            ushort4 eu = *(const ushort4*)(sc + (size_t)r * 1024 + kc + c4);
            float iv = sm.l_inv[r];
            ushort4 pv;
            pv.x = fp16hi(fmaxf(fmaf(fp16f(eu.x), iv, -TH_), 0.0f));
            pv.y = fp16hi(fmaxf(fmaf(fp16f(eu.y), iv, -TH_), 0.0f));
            pv.z = fp16hi(fmaxf(fmaf(fp16f(eu.z), iv, -TH_), 0.0f));
            pv.w = fp16hi(fmaxf(fmaf(fp16f(eu.w), iv, -TH_), 0.0f));
            *(ushort4*)&sm.u.p2.Ph[r * PV_ + c4] = pv;
        }
        // stage V transposed Vh[d][k] (64 x 128), hi only
        #pragma unroll
        for (int l = 0; l < 8; ++l) {
            int idx = tid + (l << 8);
            int r   = idx >> 4;            // 0..127 (key within chunk)
            int c4  = (idx & 15) << 2;     // 0..60 (d)
            float4 v = *(const float4*)(vbase + (size_t)(kc + r) * C3_ + c4);
            sm.u.p2.Vh[(c4 + 0) * PV_ + r] = fp16hi(v.x);
            sm.u.p2.Vh[(c4 + 1) * PV_ + r] = fp16hi(v.y);
            sm.u.p2.Vh[(c4 + 2) * PV_ + r] = fp16hi(v.z);
            sm.u.p2.Vh[(c4 + 3) * PV_ + r] = fp16hi(v.w);
        }
        __syncthreads();

        #pragma unroll
        for (int ks = 0; ks < 8; ++ks) {
            uint32_t bf[4];
            ldsm4(bf, sVh + boff2 + ks * 32);
            uint32_t af[4][4];
            #pragma unroll
            for (int mi = 0; mi < 4; ++mi)
                ldsm4(af[mi], sPh + aoff2 + mi * (16 * PV_ * 2) + ks * 32);
            #pragma unroll
            for (int mi = 0; mi < 4; ++mi) {
                mma16816(accy[mi][0], af[mi], bf[0], bf[1]);
                mma16816(accy[mi][1], af[mi], bf[2], bf[3]);
            }
        }
    }

    // epilogue: Y -> g_ys in [hi | lo] split layout
    #pragma unroll
    for (int mi = 0; mi < 4; ++mi) {
        #pragma unroll
        for (int ni = 0; ni < 2; ++ni) {
            int ch = h * HD_ + wn2 + ni * 8 + ((lane & 3) << 1);
            #pragma unroll
            for (int hv = 0; hv < 2; ++hv) {
                int rq = q0 + wm2 + mi * 16 + g + hv * 8;
                size_t rg = ((size_t)b * T_ + rq) * KSP_;
                ushort2 hp, lp;
                fp16split(accy[mi][ni][hv * 2 + 0], hp.x, lp.x);
                fp16split(accy[mi][ni][hv * 2 + 1], hp.y, lp.y);
                *(ushort2*)&Ys[rg + ch]        = hp;
                *(ushort2*)&Ys[rg + 1024 + ch] = lp;
            }
        }
    }
}

// ---------------------------------------------------------------------------
extern "C" void kernel_launch(void* const* d_in, const int* in_sizes, int n_in,
                              void* d_out, int out_size)
{
    const float* x      = (const float*)d_in[0];
    const float* w_attn = (const float*)d_in[1];
    const float* b_attn = (const float*)d_in[2];
    const float* w_proj = (const float*)d_in[3];
    const float* b_proj = (const float*)d_in[4];
    float* out = (float*)d_out;

    float *qkv;
    ushort_t *S, *xs, *ys, *wa, *wp;
    cudaGetSymbolAddress((void**)&qkv, g_qkv);
    cudaGetSymbolAddress((void**)&S,   g_S);
    cudaGetSymbolAddress((void**)&xs,  g_xs);
    cudaGetSymbolAddress((void**)&ys,  g_ys);
    cudaGetSymbolAddress((void**)&wa,  g_wa);
    cudaGetSymbolAddress((void**)&wp,  g_wp);

    const int gemm_smem = 6 * ABUF * 2;              // 61440 B
    cudaFuncSetAttribute(gemm_mma_kernel,
                         cudaFuncAttributeMaxDynamicSharedMemorySize, gemm_smem);
    cudaFuncSetAttribute(fused_attn_mma_kernel,
                         cudaFuncAttributeMaxDynamicSharedMemorySize,
                         (int)sizeof(SmemAttn2));

    // prep
    prep_split_kernel<<<B_ * T_, 256>>>(x, xs);
    prep_wt_kernel<<<dim3(C3_ / 32, C_ / 32), 256>>>(w_attn, wa, C3_);
    prep_wt_kernel<<<dim3(C_ / 32, C_ / 32), 256>>>(w_proj, wp, C_);

    // 1) QKV projection
    gemm_mma_kernel<<<dim3(C3_ / 128, (B_ * T_) / 128), 256, gemm_smem>>>(
        xs, wa, b_attn, qkv, C3_);

    // 2) fused attention
    fused_attn_mma_kernel<<<dim3(T_ / 128, BH_), 256, sizeof(SmemAttn2)>>>(
        qkv, S, ys);

    // 3) output projection
    gemm_mma_kernel<<<dim3(C_ / 128, (B_ * T_) / 128), 256, gemm_smem>>>(
        ys, wp, b_proj, out, C_);
}

// round 9
// speedup vs baseline: 4.1624x; 1.1340x over previous
#include <cuda_runtime.h>
#include <cuda_fp16.h>
#include <cstddef>
#include <cstdint>

#define B_   8
#define T_   1024
#define C_   1024
#define H_   16
#define HD_  64
#define BH_  (B_ * H_)          // 128
#define C3_  (3 * C_)           // 3072
#define KSP_ 2048               // x/Y split: [hi | lo]
#define KW_  1024               // weight hi-only K
#define TH_  0.001f
#define PQ_  72                 // pass1 smem pitch (halves)
#define PV_  136                // pass2 smem pitch (halves)

using ushort_t = unsigned short;

// ---------------- scratch (static device globals) ----------------
__device__ __align__(16) float g_qkv[(size_t)B_ * T_ * C3_];            // 96 MB
__device__ __align__(16) ushort_t g_S[(size_t)BH_ * T_ * T_];           // 256 MB fp16 exp
__device__ __align__(16) ushort_t g_xs[(size_t)B_ * T_ * KSP_];         // x  [hi|lo] fp16
__device__ __align__(16) ushort_t g_ys[(size_t)B_ * T_ * KSP_];         // Y  [hi|lo] fp16
__device__ __align__(16) ushort_t g_wa[(size_t)C3_ * KW_];              // w_attn^T hi
__device__ __align__(16) ushort_t g_wp[(size_t)C_ * KW_];               // w_proj^T hi

// ---------------- helpers ----------------
__device__ __forceinline__ uint32_t smem_u32(const void* p) {
    uint32_t a;
    asm("{ .reg .u64 t; cvta.to.shared.u64 t, %1; cvt.u32.u64 %0, t; }"
        : "=r"(a) : "l"(p));
    return a;
}
__device__ __forceinline__ void ldsm4(uint32_t (&r)[4], uint32_t addr) {
    asm volatile("ldmatrix.sync.aligned.m8n8.x4.shared.b16 {%0,%1,%2,%3}, [%4];"
        : "=r"(r[0]), "=r"(r[1]), "=r"(r[2]), "=r"(r[3]) : "r"(addr));
}
__device__ __forceinline__ void mma16816(float (&d)[4], const uint32_t (&a)[4],
                                         uint32_t b0, uint32_t b1) {
    asm volatile(
        "mma.sync.aligned.m16n8k16.row.col.f32.f16.f16.f32 "
        "{%0,%1,%2,%3}, {%4,%5,%6,%7}, {%8,%9}, {%0,%1,%2,%3};"
        : "+f"(d[0]), "+f"(d[1]), "+f"(d[2]), "+f"(d[3])
        : "r"(a[0]), "r"(a[1]), "r"(a[2]), "r"(a[3]), "r"(b0), "r"(b1));
}
__device__ __forceinline__ void cp16(uint32_t dst, const void* src) {
    asm volatile("cp.async.cg.shared.global [%0], [%1], 16;"
                 :: "r"(dst), "l"(src) : "memory");
}
#define CP_COMMIT() asm volatile("cp.async.commit_group;" ::: "memory")
#define CP_WAIT0()  asm volatile("cp.async.wait_group 0;" ::: "memory")

__device__ __forceinline__ void fp16split(float v, ushort_t &h, ushort_t &l) {
    __half hb = __float2half_rn(v);
    __half lb = __float2half_rn(v - __half2float(hb));
    h = __half_as_ushort(hb);
    l = __half_as_ushort(lb);
}
__device__ __forceinline__ ushort_t fp16hi(float v) {
    return __half_as_ushort(__float2half_rn(v));
}
__device__ __forceinline__ float fp16f(ushort_t u) {
    return __half2float(__ushort_as_half(u));
}

// ---------------------------------------------------------------------------
// prep kernels
// ---------------------------------------------------------------------------
__global__ __launch_bounds__(256) void prep_split_kernel(
    const float* __restrict__ X, ushort_t* __restrict__ Xs)
{
    const size_t r = blockIdx.x;
    const int c4 = threadIdx.x << 2;
    float4 v = *(const float4*)(X + r * 1024 + c4);
    ushort4 hv, lv;
    fp16split(v.x, hv.x, lv.x); fp16split(v.y, hv.y, lv.y);
    fp16split(v.z, hv.z, lv.z); fp16split(v.w, hv.w, lv.w);
    ushort_t* row = Xs + r * KSP_;
    *(ushort4*)(row + c4)        = hv;
    *(ushort4*)(row + 1024 + c4) = lv;
}

__global__ __launch_bounds__(256) void prep_wt_kernel(
    const float* __restrict__ W, ushort_t* __restrict__ Wt, int N)
{
    __shared__ float t[32][33];
    const int n0 = blockIdx.x << 5;
    const int k0 = blockIdx.y << 5;
    const int row = threadIdx.x >> 5;
    const int col = threadIdx.x & 31;
    #pragma unroll
    for (int p = 0; p < 4; ++p)
        t[row + p * 8][col] = W[(size_t)(k0 + row + p * 8) * N + n0 + col];
    __syncthreads();
    #pragma unroll
    for (int p = 0; p < 4; ++p) {
        int n = row + p * 8, k = col;
        Wt[(size_t)(n0 + n) * KW_ + k0 + k] = fp16hi(t[k][n]);
    }
}

// ---------------------------------------------------------------------------
// HMMA GEMM, cp.async staging + phase-pipelined fragments.
// TERMS=2: C = (Ah+Al) x Wh^T + bias ; TERMS=1: C = Ah x Wh^T + bias
// ---------------------------------------------------------------------------
#define PITCH 40
#define ABUF  (128 * PITCH)        // halves per buffer
#define ROWBLK (16 * PITCH * 2)    // bytes per 16-row block

template<int TERMS>
__global__ __launch_bounds__(256, 2) void gemm_mma_kernel(
    const ushort_t* __restrict__ A, const ushort_t* __restrict__ Bh,
    const float* __restrict__ bias, float* __restrict__ C, int N, int n_base)
{
    extern __shared__ ushort_t gs[];
    ushort_t* sAh = gs;
    ushort_t* sAl = gs + 2 * ABUF;                       // TERMS==2 only
    ushort_t* sBs = gs + (TERMS == 2 ? 4 : 2) * ABUF;

    const int tid  = threadIdx.x;
    const int lane = tid & 31, wid = tid >> 5;
    const int m0 = blockIdx.y << 7;
    const int n0 = n_base + (blockIdx.x << 7);
    const int wm = (wid & 1) << 6;
    const int wn = (wid >> 1) << 5;

    float acc[4][4][4];
    #pragma unroll
    for (int i = 0; i < 4; i++)
        #pragma unroll
        for (int j = 0; j < 4; j++)
            #pragma unroll
            for (int k = 0; k < 4; k++) acc[i][j][k] = 0.0f;

    const int r0s = tid >> 2, r1s = r0s + 64;
    const int js  = (tid & 3) << 3;
    const ushort_t* gA0 = A + (size_t)(m0 + r0s) * KSP_ + js;
    const ushort_t* gA1 = A + (size_t)(m0 + r1s) * KSP_ + js;
    const ushort_t* gB0 = Bh + (size_t)(n0 + r0s) * KW_ + js;
    const ushort_t* gB1 = Bh + (size_t)(n0 + r1s) * KW_ + js;
    const uint32_t so0b = (uint32_t)(r0s * PITCH + js) * 2;
    const uint32_t so1b = (uint32_t)(r1s * PITCH + js) * 2;

    const uint32_t uAh = smem_u32(sAh), uAl = smem_u32(sAl), uBs = smem_u32(sBs);
    const uint32_t AB2 = ABUF * 2;
    const uint32_t aoff = (uint32_t)((wm + (lane & 15)) * PITCH + (lane >> 4) * 8) * 2;
    const uint32_t boff = (uint32_t)((wn + (lane & 7) + ((lane >> 4) << 3)) * PITCH
                                     + ((lane >> 3) & 1) * 8) * 2;

    // stage chunk 0
    {
        cp16(uAh + so0b, gA0); cp16(uAh + so1b, gA1);
        if (TERMS == 2) { cp16(uAl + so0b, gA0 + 1024); cp16(uAl + so1b, gA1 + 1024); }
        cp16(uBs + so0b, gB0); cp16(uBs + so1b, gB1);
        CP_COMMIT();
    }
    CP_WAIT0();
    __syncthreads();

    for (int c = 0; c < 32; ++c) {
        const int buf = c & 1;
        if (c + 1 < 32) {
            const int kc = (c + 1) << 5;
            const uint32_t nb = (uint32_t)(1 - buf) * AB2;
            cp16(uAh + nb + so0b, gA0 + kc);
            cp16(uAh + nb + so1b, gA1 + kc);
            if (TERMS == 2) {
                cp16(uAl + nb + so0b, gA0 + 1024 + kc);
                cp16(uAl + nb + so1b, gA1 + 1024 + kc);
            }
            cp16(uBs + nb + so0b, gB0 + kc);
            cp16(uBs + nb + so1b, gB1 + kc);
            CP_COMMIT();
        }

        const uint32_t aHB = uAh + buf * AB2 + aoff;
        const uint32_t aLB = uAl + buf * AB2 + aoff;
        const uint32_t bBB = uBs + buf * AB2 + boff;

        uint32_t af[2][4][4], bf[2][2][4];
        ldsm4(bf[0][0], bBB);
        ldsm4(bf[0][1], bBB + ROWBLK);
        #pragma unroll
        for (int mi = 0; mi < 4; ++mi)
            ldsm4(af[0][mi], aHB + mi * ROWBLK);

        const int NPH = 2 * TERMS;
        #pragma unroll
        for (int ph = 0; ph < NPH; ++ph) {
            // prefetch next phase's fragments before this phase's mma chain
            if (TERMS == 2) {
                if (ph == 0) {
                    #pragma unroll
                    for (int mi = 0; mi < 4; ++mi)
                        ldsm4(af[1][mi], aLB + mi * ROWBLK);
                } else if (ph == 1) {
                    ldsm4(bf[1][0], bBB + 32);
                    ldsm4(bf[1][1], bBB + ROWBLK + 32);
                    #pragma unroll
                    for (int mi = 0; mi < 4; ++mi)
                        ldsm4(af[0][mi], aHB + mi * ROWBLK + 32);
                } else if (ph == 2) {
                    #pragma unroll
                    for (int mi = 0; mi < 4; ++mi)
                        ldsm4(af[1][mi], aLB + mi * ROWBLK + 32);
                }
            } else {
                if (ph == 0) {
                    ldsm4(bf[1][0], bBB + 32);
                    ldsm4(bf[1][1], bBB + ROWBLK + 32);
                    #pragma unroll
                    for (int mi = 0; mi < 4; ++mi)
                        ldsm4(af[1][mi], aHB + mi * ROWBLK + 32);
                }
            }
            const int ai = ph & 1;
            const int bi = (TERMS == 2) ? (ph >> 1) : ph;
            #pragma unroll
            for (int mi = 0; mi < 4; ++mi) {
                mma16816(acc[mi][0], af[ai][mi], bf[bi][0][0], bf[bi][0][1]);
                mma16816(acc[mi][1], af[ai][mi], bf[bi][0][2], bf[bi][0][3]);
                mma16816(acc[mi][2], af[ai][mi], bf[bi][1][0], bf[bi][1][1]);
                mma16816(acc[mi][3], af[ai][mi], bf[bi][1][2], bf[bi][1][3]);
            }
        }

        if (c + 1 < 32) CP_WAIT0();
        __syncthreads();
    }

    const int g  = lane >> 2;
    const int tg = (lane & 3) << 1;
    #pragma unroll
    for (int ni = 0; ni < 4; ++ni) {
        int col = n0 + wn + ni * 8 + tg;
        float2 bv = *(const float2*)(bias + col);
        #pragma unroll
        for (int mi = 0; mi < 4; ++mi) {
            int r0 = m0 + wm + mi * 16 + g;
            float2 v0 = make_float2(acc[mi][ni][0] + bv.x, acc[mi][ni][1] + bv.y);
            float2 v1 = make_float2(acc[mi][ni][2] + bv.x, acc[mi][ni][3] + bv.y);
            *(float2*)&C[(size_t)r0 * N + col]       = v0;
            *(float2*)&C[(size_t)(r0 + 8) * N + col] = v1;
        }
    }
}

// ---------------------------------------------------------------------------
// Fused attention (unchanged from R8)
// ---------------------------------------------------------------------------
struct SmemAttn2 {
    float l_red[128];
    float l_inv[128];
    union {
        struct { ushort_t Qh[128 * PQ_], Ql[128 * PQ_], Kh[128 * PQ_]; } p1;
        struct { ushort_t Ph[128 * PV_], Vh[64 * PV_]; } p2;
    } u;
};

__global__ __launch_bounds__(256, 2) void fused_attn_mma_kernel(
    const float* __restrict__ qkv, ushort_t* __restrict__ scratch,
    ushort_t* __restrict__ Ys)
{
    extern __shared__ char smem_raw[];
    SmemAttn2& sm = *reinterpret_cast<SmemAttn2*>(smem_raw);

    const int qb = blockIdx.x;
    const int bh = blockIdx.y;
    const int b  = bh >> 4;
    const int h  = bh & 15;
    const float* qbase = qkv + (size_t)b * T_ * C3_ + h * HD_;
    const float* kbase = qbase + C_;
    const float* vbase = qbase + 2 * C_;
    ushort_t* sc = scratch + (((size_t)bh * 8 + qb) << 17);

    const int tid  = threadIdx.x;
    const int lane = tid & 31, wid = tid >> 5;
    const int q0   = qb << 7;
    const int g    = lane >> 2;

    if (tid < 128) sm.l_red[tid] = 0.0f;

    #pragma unroll
    for (int l = 0; l < 8; ++l) {
        int idx = tid + (l << 8);
        int r   = idx >> 4;
        int c4  = (idx & 15) << 2;
        float4 v = *(const float4*)(qbase + (size_t)(q0 + r) * C3_ + c4);
        ushort4 hv, lv;
        fp16split(v.x, hv.x, lv.x); fp16split(v.y, hv.y, lv.y);
        fp16split(v.z, hv.z, lv.z); fp16split(v.w, hv.w, lv.w);
        *(ushort4*)&sm.u.p1.Qh[r * PQ_ + c4] = hv;
        *(ushort4*)&sm.u.p1.Ql[r * PQ_ + c4] = lv;
    }

    const int wm = (wid & 1) << 6;
    const int wn = (wid >> 1) << 5;
    const uint32_t sQh = smem_u32(sm.u.p1.Qh), sQl = smem_u32(sm.u.p1.Ql);
    const uint32_t sKh = smem_u32(sm.u.p1.Kh);
    const uint32_t aoff = (uint32_t)((wm + (lane & 15)) * PQ_ + (lane >> 4) * 8) * 2;
    const uint32_t boff = (uint32_t)((wn + (lane & 7) + ((lane >> 4) << 3)) * PQ_
                                     + ((lane >> 3) & 1) * 8) * 2;

    float lsum[8];
    #pragma unroll
    for (int i = 0; i < 8; i++) lsum[i] = 0.0f;

    for (int k0 = 0; k0 < T_; k0 += 128) {
        __syncthreads();
        #pragma unroll
        for (int l = 0; l < 8; ++l) {
            int idx = tid + (l << 8);
            int r   = idx >> 4;
            int c4  = (idx & 15) << 2;
            float4 v = *(const float4*)(kbase + (size_t)(k0 + r) * C3_ + c4);
            ushort4 hv;
            hv.x = fp16hi(v.x); hv.y = fp16hi(v.y);
            hv.z = fp16hi(v.z); hv.w = fp16hi(v.w);
            *(ushort4*)&sm.u.p1.Kh[r * PQ_ + c4] = hv;
        }
        __syncthreads();

        float acc[4][4][4];
        #pragma unroll
        for (int i = 0; i < 4; i++)
            #pragma unroll
            for (int j = 0; j < 4; j++)
                #pragma unroll
                for (int k = 0; k < 4; k++) acc[i][j][k] = 0.0f;

        #pragma unroll
        for (int ks = 0; ks < 4; ++ks) {
            uint32_t bf[2][4];
            ldsm4(bf[0], sKh + boff + ks * 32);
            ldsm4(bf[1], sKh + boff + (16 * PQ_ * 2) + ks * 32);
            uint32_t af[4][4];
            #pragma unroll
            for (int mi = 0; mi < 4; ++mi)
                ldsm4(af[mi], sQh + aoff + mi * (16 * PQ_ * 2) + ks * 32);
            #pragma unroll
            for (int mi = 0; mi < 4; ++mi) {
                mma16816(acc[mi][0], af[mi], bf[0][0], bf[0][1]);
                mma16816(acc[mi][1], af[mi], bf[0][2], bf[0][3]);
                mma16816(acc[mi][2], af[mi], bf[1][0], bf[1][1]);
                mma16816(acc[mi][3], af[mi], bf[1][2], bf[1][3]);
            }
            #pragma unroll
            for (int mi = 0; mi < 4; ++mi)
                ldsm4(af[mi], sQl + aoff + mi * (16 * PQ_ * 2) + ks * 32);
            #pragma unroll
            for (int mi = 0; mi < 4; ++mi) {
                mma16816(acc[mi][0], af[mi], bf[0][0], bf[0][1]);
                mma16816(acc[mi][1], af[mi], bf[0][2], bf[0][3]);
                mma16816(acc[mi][2], af[mi], bf[1][0], bf[1][1]);
                mma16816(acc[mi][3], af[mi], bf[1][2], bf[1][3]);
            }
        }

        #pragma unroll
        for (int mi = 0; mi < 4; ++mi) {
            #pragma unroll
            for (int ni = 0; ni < 4; ++ni) {
                float e0 = __expf(acc[mi][ni][0] * 0.125f);
                float e1 = __expf(acc[mi][ni][1] * 0.125f);
                float e2 = __expf(acc[mi][ni][2] * 0.125f);
                float e3 = __expf(acc[mi][ni][3] * 0.125f);
                lsum[mi * 2 + 0] += e0 + e1;
                lsum[mi * 2 + 1] += e2 + e3;
                int col = k0 + wn + ni * 8 + ((lane & 3) << 1);
                int r0  = wm + mi * 16 + g;
                ushort2 u01 = make_ushort2(fp16hi(e0), fp16hi(e1));
                ushort2 u23 = make_ushort2(fp16hi(e2), fp16hi(e3));
                *(ushort2*)(sc + (size_t)r0 * 1024 + col)       = u01;
                *(ushort2*)(sc + (size_t)(r0 + 8) * 1024 + col) = u23;
            }
        }
    }

    #pragma unroll
    for (int i = 0; i < 8; i++) {
        float v = lsum[i];
        v += __shfl_xor_sync(0xFFFFFFFFu, v, 1);
        v += __shfl_xor_sync(0xFFFFFFFFu, v, 2);
        if ((lane & 3) == 0) {
            int row = wm + (i >> 1) * 16 + g + (i & 1) * 8;
            atomicAdd(&sm.l_red[row], v);
        }
    }
    __syncthreads();
    if (tid < 128) sm.l_inv[tid] = 1.0f / sm.l_red[tid];

    const int wm2 = (wid & 1) << 6;
    const int wn2 = (wid >> 1) << 4;
    const uint32_t sPh = smem_u32(sm.u.p2.Ph);
    const uint32_t sVh = smem_u32(sm.u.p2.Vh);
    const uint32_t aoff2 = (uint32_t)((wm2 + (lane & 15)) * PV_ + (lane >> 4) * 8) * 2;
    const uint32_t boff2 = (uint32_t)((wn2 + (lane & 7) + ((lane >> 4) << 3)) * PV_
                                      + ((lane >> 3) & 1) * 8) * 2;

    float accy[4][2][4];
    #pragma unroll
    for (int i = 0; i < 4; i++)
        #pragma unroll
        for (int j = 0; j < 2; j++)
            #pragma unroll
            for (int k = 0; k < 4; k++) accy[i][j][k] = 0.0f;

    for (int kc = 0; kc < T_; kc += 128) {
        __syncthreads();
        #pragma unroll
        for (int l = 0; l < 16; ++l) {
            int idx = tid + (l << 8);
            int r   = idx >> 5;
            int c4  = (idx & 31) << 2;
            ushort4 eu = *(const ushort4*)(sc + (size_t)r * 1024 + kc + c4);
            float iv = sm.l_inv[r];
            ushort4 pv;
            pv.x = fp16hi(fmaxf(fmaf(fp16f(eu.x), iv, -TH_), 0.0f));
            pv.y = fp16hi(fmaxf(fmaf(fp16f(eu.y), iv, -TH_), 0.0f));
            pv.z = fp16hi(fmaxf(fmaf(fp16f(eu.z), iv, -TH_), 0.0f));
            pv.w = fp16hi(fmaxf(fmaf(fp16f(eu.w), iv, -TH_), 0.0f));
            *(ushort4*)&sm.u.p2.Ph[r * PV_ + c4] = pv;
        }
        #pragma unroll
        for (int l = 0; l < 8; ++l) {
            int idx = tid + (l << 8);
            int r   = idx >> 4;
            int c4  = (idx & 15) << 2;
            float4 v = *(const float4*)(vbase + (size_t)(kc + r) * C3_ + c4);
            sm.u.p2.Vh[(c4 + 0) * PV_ + r] = fp16hi(v.x);
            sm.u.p2.Vh[(c4 + 1) * PV_ + r] = fp16hi(v.y);
            sm.u.p2.Vh[(c4 + 2) * PV_ + r] = fp16hi(v.z);
            sm.u.p2.Vh[(c4 + 3) * PV_ + r] = fp16hi(v.w);
        }
        __syncthreads();

        #pragma unroll
        for (int ks = 0; ks < 8; ++ks) {
            uint32_t bf[4];
            ldsm4(bf, sVh + boff2 + ks * 32);
            uint32_t af[4][4];
            #pragma unroll
            for (int mi = 0; mi < 4; ++mi)
                ldsm4(af[mi], sPh + aoff2 + mi * (16 * PV_ * 2) + ks * 32);
            #pragma unroll
            for (int mi = 0; mi < 4; ++mi) {
                mma16816(accy[mi][0], af[mi], bf[0], bf[1]);
                mma16816(accy[mi][1], af[mi], bf[2], bf[3]);
            }
        }
    }

    #pragma unroll
    for (int mi = 0; mi < 4; ++mi) {
        #pragma unroll
        for (int ni = 0; ni < 2; ++ni) {
            int ch = h * HD_ + wn2 + ni * 8 + ((lane & 3) << 1);
            #pragma unroll
            for (int hv = 0; hv < 2; ++hv) {
                int rq = q0 + wm2 + mi * 16 + g + hv * 8;
                size_t rg = ((size_t)b * T_ + rq) * KSP_;
                ushort2 hp, lp;
                fp16split(accy[mi][ni][hv * 2 + 0], hp.x, lp.x);
                fp16split(accy[mi][ni][hv * 2 + 1], hp.y, lp.y);
                *(ushort2*)&Ys[rg + ch]        = hp;
                *(ushort2*)&Ys[rg + 1024 + ch] = lp;
            }
        }
    }
}

// ---------------------------------------------------------------------------
extern "C" void kernel_launch(void* const* d_in, const int* in_sizes, int n_in,
                              void* d_out, int out_size)
{
    const float* x      = (const float*)d_in[0];
    const float* w_attn = (const float*)d_in[1];
    const float* b_attn = (const float*)d_in[2];
    const float* w_proj = (const float*)d_in[3];
    const float* b_proj = (const float*)d_in[4];
    float* out = (float*)d_out;

    float *qkv;
    ushort_t *S, *xs, *ys, *wa, *wp;
    cudaGetSymbolAddress((void**)&qkv, g_qkv);
    cudaGetSymbolAddress((void**)&S,   g_S);
    cudaGetSymbolAddress((void**)&xs,  g_xs);
    cudaGetSymbolAddress((void**)&ys,  g_ys);
    cudaGetSymbolAddress((void**)&wa,  g_wa);
    cudaGetSymbolAddress((void**)&wp,  g_wp);

    const int smem2 = 6 * ABUF * 2;   // 61440 B (TERMS=2)
    const int smem1 = 4 * ABUF * 2;   // 40960 B (TERMS=1)
    cudaFuncSetAttribute(gemm_mma_kernel<2>,
                         cudaFuncAttributeMaxDynamicSharedMemorySize, smem2);
    cudaFuncSetAttribute(gemm_mma_kernel<1>,
                         cudaFuncAttributeMaxDynamicSharedMemorySize, smem1);
    cudaFuncSetAttribute(fused_attn_mma_kernel,
                         cudaFuncAttributeMaxDynamicSharedMemorySize,
                         (int)sizeof(SmemAttn2));

    // prep
    prep_split_kernel<<<B_ * T_, 256>>>(x, xs);
    prep_wt_kernel<<<dim3(C3_ / 32, C_ / 32), 256>>>(w_attn, wa, C3_);
    prep_wt_kernel<<<dim3(C_ / 32, C_ / 32), 256>>>(w_proj, wp, C_);

    // 1) QKV projection: Q cols 2-term, K/V cols 1-term
    gemm_mma_kernel<2><<<dim3(8, 64), 256, smem2>>>(xs, wa, b_attn, qkv, C3_, 0);
    gemm_mma_kernel<1><<<dim3(16, 64), 256, smem1>>>(xs, wa, b_attn, qkv, C3_, 1024);

    // 2) fused attention
    fused_attn_mma_kernel<<<dim3(T_ / 128, BH_), 256, sizeof(SmemAttn2)>>>(
        qkv, S, ys);

    // 3) output projection (2-term)
    gemm_mma_kernel<2><<<dim3(8, 64), 256, smem2>>>(ys, wp, b_proj, out, C_, 0);
}

// round 10
// speedup vs baseline: 4.7061x; 1.1306x over previous
#include <cuda_runtime.h>
#include <cuda_fp16.h>
#include <cstddef>
#include <cstdint>

#define B_   8
#define T_   1024
#define C_   1024
#define H_   16
#define HD_  64
#define BH_  (B_ * H_)          // 128
#define C3_  (3 * C_)           // 3072
#define KSP_ 2048               // x/Y split: [hi | lo]
#define KW_  1024               // weight hi-only K
#define TH_  0.001f
#define PQ_  72                 // smem pitch (halves) for 64-wide tiles
#define PV_  136                // smem pitch (halves) for 128-wide tiles

using ushort_t = unsigned short;

// ---------------- scratch (static device globals) ----------------
__device__ __align__(16) ushort_t g_qs[(size_t)B_ * T_ * 2048];         // Q [hi|lo] fp16
__device__ __align__(16) ushort_t g_kvh[(size_t)B_ * T_ * 2048];        // [K hi | V hi]
__device__ __align__(16) ushort_t g_S[(size_t)BH_ * T_ * T_];           // 256 MB fp16 exp
__device__ __align__(16) ushort_t g_xs[(size_t)B_ * T_ * KSP_];         // x  [hi|lo]
__device__ __align__(16) ushort_t g_ys[(size_t)B_ * T_ * KSP_];         // Y  [hi|lo]
__device__ __align__(16) ushort_t g_wa[(size_t)C3_ * KW_];              // w_attn^T hi
__device__ __align__(16) ushort_t g_wp[(size_t)C_ * KW_];               // w_proj^T hi

// ---------------- helpers ----------------
__device__ __forceinline__ uint32_t smem_u32(const void* p) {
    uint32_t a;
    asm("{ .reg .u64 t; cvta.to.shared.u64 t, %1; cvt.u32.u64 %0, t; }"
        : "=r"(a) : "l"(p));
    return a;
}
__device__ __forceinline__ void ldsm4(uint32_t (&r)[4], uint32_t addr) {
    asm volatile("ldmatrix.sync.aligned.m8n8.x4.shared.b16 {%0,%1,%2,%3}, [%4];"
        : "=r"(r[0]), "=r"(r[1]), "=r"(r[2]), "=r"(r[3]) : "r"(addr));
}
__device__ __forceinline__ void ldsm4t(uint32_t (&r)[4], uint32_t addr) {
    asm volatile("ldmatrix.sync.aligned.m8n8.x4.trans.shared.b16 {%0,%1,%2,%3}, [%4];"
        : "=r"(r[0]), "=r"(r[1]), "=r"(r[2]), "=r"(r[3]) : "r"(addr));
}
__device__ __forceinline__ void mma16816(float (&d)[4], const uint32_t (&a)[4],
                                         uint32_t b0, uint32_t b1) {
    asm volatile(
        "mma.sync.aligned.m16n8k16.row.col.f32.f16.f16.f32 "
        "{%0,%1,%2,%3}, {%4,%5,%6,%7}, {%8,%9}, {%0,%1,%2,%3};"
        : "+f"(d[0]), "+f"(d[1]), "+f"(d[2]), "+f"(d[3])
        : "r"(a[0]), "r"(a[1]), "r"(a[2]), "r"(a[3]), "r"(b0), "r"(b1));
}
__device__ __forceinline__ void cp16(uint32_t dst, const void* src) {
    asm volatile("cp.async.cg.shared.global [%0], [%1], 16;"
                 :: "r"(dst), "l"(src) : "memory");
}
#define CP_COMMIT() asm volatile("cp.async.commit_group;" ::: "memory")
#define CP_WAIT0()  asm volatile("cp.async.wait_group 0;" ::: "memory")

__device__ __forceinline__ void fp16split(float v, ushort_t &h, ushort_t &l) {
    __half hb = __float2half_rn(v);
    __half lb = __float2half_rn(v - __half2float(hb));
    h = __half_as_ushort(hb);
    l = __half_as_ushort(lb);
}
__device__ __forceinline__ ushort_t fp16hi(float v) {
    return __half_as_ushort(__float2half_rn(v));
}
__device__ __forceinline__ float fp16f(ushort_t u) {
    return __half2float(__ushort_as_half(u));
}

// ---------------------------------------------------------------------------
// prep kernels
// ---------------------------------------------------------------------------
__global__ __launch_bounds__(256) void prep_split_kernel(
    const float* __restrict__ X, ushort_t* __restrict__ Xs)
{
    const size_t r = blockIdx.x;
    const int c4 = threadIdx.x << 2;
    float4 v = *(const float4*)(X + r * 1024 + c4);
    ushort4 hv, lv;
    fp16split(v.x, hv.x, lv.x); fp16split(v.y, hv.y, lv.y);
    fp16split(v.z, hv.z, lv.z); fp16split(v.w, hv.w, lv.w);
    ushort_t* row = Xs + r * KSP_;
    *(ushort4*)(row + c4)        = hv;
    *(ushort4*)(row + 1024 + c4) = lv;
}

__global__ __launch_bounds__(256) void prep_wt_kernel(
    const float* __restrict__ W, ushort_t* __restrict__ Wt, int N)
{
    __shared__ float t[32][33];
    const int n0 = blockIdx.x << 5;
    const int k0 = blockIdx.y << 5;
    const int row = threadIdx.x >> 5;
    const int col = threadIdx.x & 31;
    #pragma unroll
    for (int p = 0; p < 4; ++p)
        t[row + p * 8][col] = W[(size_t)(k0 + row + p * 8) * N + n0 + col];
    __syncthreads();
    #pragma unroll
    for (int p = 0; p < 4; ++p) {
        int n = row + p * 8, k = col;
        Wt[(size_t)(n0 + n) * KW_ + k0 + k] = fp16hi(t[k][n]);
    }
}

// ---------------------------------------------------------------------------
// HMMA GEMM, cp.async staging + phase-pipelined fragments.
// TERMS: 2 -> (Ah+Al)xWh^T ; 1 -> Ah x Wh^T
// EPI: 0 -> fp32 C[M][N]+bias ; 1 -> fp16 split [hi|lo] rows 2048 (+bias)
//      2 -> fp16 hi rows 2048 at col-1024 (+bias)
// ---------------------------------------------------------------------------
#define PITCH 40
#define ABUF  (128 * PITCH)
#define ROWBLK (16 * PITCH * 2)

template<int TERMS, int EPI>
__global__ __launch_bounds__(256, 2) void gemm_mma_kernel(
    const ushort_t* __restrict__ A, const ushort_t* __restrict__ Bh,
    const float* __restrict__ bias, void* __restrict__ Cout, int N, int n_base)
{
    extern __shared__ ushort_t gs[];
    ushort_t* sAh = gs;
    ushort_t* sAl = gs + 2 * ABUF;
    ushort_t* sBs = gs + (TERMS == 2 ? 4 : 2) * ABUF;

    const int tid  = threadIdx.x;
    const int lane = tid & 31, wid = tid >> 5;
    const int m0 = blockIdx.y << 7;
    const int n0 = n_base + (blockIdx.x << 7);
    const int wm = (wid & 1) << 6;
    const int wn = (wid >> 1) << 5;

    float acc[4][4][4];
    #pragma unroll
    for (int i = 0; i < 4; i++)
        #pragma unroll
        for (int j = 0; j < 4; j++)
            #pragma unroll
            for (int k = 0; k < 4; k++) acc[i][j][k] = 0.0f;

    const int r0s = tid >> 2, r1s = r0s + 64;
    const int js  = (tid & 3) << 3;
    const ushort_t* gA0 = A + (size_t)(m0 + r0s) * KSP_ + js;
    const ushort_t* gA1 = A + (size_t)(m0 + r1s) * KSP_ + js;
    const ushort_t* gB0 = Bh + (size_t)(n0 + r0s) * KW_ + js;
    const ushort_t* gB1 = Bh + (size_t)(n0 + r1s) * KW_ + js;
    const uint32_t so0b = (uint32_t)(r0s * PITCH + js) * 2;
    const uint32_t so1b = (uint32_t)(r1s * PITCH + js) * 2;

    const uint32_t uAh = smem_u32(sAh), uAl = smem_u32(sAl), uBs = smem_u32(sBs);
    const uint32_t AB2 = ABUF * 2;
    const uint32_t aoff = (uint32_t)((wm + (lane & 15)) * PITCH + (lane >> 4) * 8) * 2;
    const uint32_t boff = (uint32_t)((wn + (lane & 7) + ((lane >> 4) << 3)) * PITCH
                                     + ((lane >> 3) & 1) * 8) * 2;

    cp16(uAh + so0b, gA0); cp16(uAh + so1b, gA1);
    if (TERMS == 2) { cp16(uAl + so0b, gA0 + 1024); cp16(uAl + so1b, gA1 + 1024); }
    cp16(uBs + so0b, gB0); cp16(uBs + so1b, gB1);
    CP_COMMIT();
    CP_WAIT0();
    __syncthreads();

    for (int c = 0; c < 32; ++c) {
        const int buf = c & 1;
        if (c + 1 < 32) {
            const int kc = (c + 1) << 5;
            const uint32_t nb = (uint32_t)(1 - buf) * AB2;
            cp16(uAh + nb + so0b, gA0 + kc);
            cp16(uAh + nb + so1b, gA1 + kc);
            if (TERMS == 2) {
                cp16(uAl + nb + so0b, gA0 + 1024 + kc);
                cp16(uAl + nb + so1b, gA1 + 1024 + kc);
            }
            cp16(uBs + nb + so0b, gB0 + kc);
            cp16(uBs + nb + so1b, gB1 + kc);
            CP_COMMIT();
        }

        const uint32_t aHB = uAh + buf * AB2 + aoff;
        const uint32_t aLB = uAl + buf * AB2 + aoff;
        const uint32_t bBB = uBs + buf * AB2 + boff;

        uint32_t af[2][4][4], bf[2][2][4];
        ldsm4(bf[0][0], bBB);
        ldsm4(bf[0][1], bBB + ROWBLK);
        #pragma unroll
        for (int mi = 0; mi < 4; ++mi)
            ldsm4(af[0][mi], aHB + mi * ROWBLK);

        const int NPH = 2 * TERMS;
        #pragma unroll
        for (int ph = 0; ph < NPH; ++ph) {
            if (TERMS == 2) {
                if (ph == 0) {
                    #pragma unroll
                    for (int mi = 0; mi < 4; ++mi)
                        ldsm4(af[1][mi], aLB + mi * ROWBLK);
                } else if (ph == 1) {
                    ldsm4(bf[1][0], bBB + 32);
                    ldsm4(bf[1][1], bBB + ROWBLK + 32);
                    #pragma unroll
                    for (int mi = 0; mi < 4; ++mi)
                        ldsm4(af[0][mi], aHB + mi * ROWBLK + 32);
                } else if (ph == 2) {
                    #pragma unroll
                    for (int mi = 0; mi < 4; ++mi)
                        ldsm4(af[1][mi], aLB + mi * ROWBLK + 32);
                }
            } else {
                if (ph == 0) {
                    ldsm4(bf[1][0], bBB + 32);
                    ldsm4(bf[1][1], bBB + ROWBLK + 32);
                    #pragma unroll
                    for (int mi = 0; mi < 4; ++mi)
                        ldsm4(af[1][mi], aHB + mi * ROWBLK + 32);
                }
            }
            const int ai = ph & 1;
            const int bi = (TERMS == 2) ? (ph >> 1) : ph;
            #pragma unroll
            for (int mi = 0; mi < 4; ++mi) {
                mma16816(acc[mi][0], af[ai][mi], bf[bi][0][0], bf[bi][0][1]);
                mma16816(acc[mi][1], af[ai][mi], bf[bi][0][2], bf[bi][0][3]);
                mma16816(acc[mi][2], af[ai][mi], bf[bi][1][0], bf[bi][1][1]);
                mma16816(acc[mi][3], af[ai][mi], bf[bi][1][2], bf[bi][1][3]);
            }
        }

        if (c + 1 < 32) CP_WAIT0();
        __syncthreads();
    }

    const int g  = lane >> 2;
    const int tg = (lane & 3) << 1;
    #pragma unroll
    for (int ni = 0; ni < 4; ++ni) {
        int col = n0 + wn + ni * 8 + tg;
        float2 bv = *(const float2*)(bias + col);
        #pragma unroll
        for (int mi = 0; mi < 4; ++mi) {
            int r0 = m0 + wm + mi * 16 + g;
            float a0 = acc[mi][ni][0] + bv.x, a1 = acc[mi][ni][1] + bv.y;
            float a2 = acc[mi][ni][2] + bv.x, a3 = acc[mi][ni][3] + bv.y;
            if (EPI == 0) {
                float* C = (float*)Cout;
                *(float2*)&C[(size_t)r0 * N + col]       = make_float2(a0, a1);
                *(float2*)&C[(size_t)(r0 + 8) * N + col] = make_float2(a2, a3);
            } else if (EPI == 1) {
                ushort_t* C = (ushort_t*)Cout;
                ushort2 h0, l0, h1, l1;
                fp16split(a0, h0.x, l0.x); fp16split(a1, h0.y, l0.y);
                fp16split(a2, h1.x, l1.x); fp16split(a3, h1.y, l1.y);
                *(ushort2*)&C[(size_t)r0 * 2048 + col]              = h0;
                *(ushort2*)&C[(size_t)r0 * 2048 + 1024 + col]       = l0;
                *(ushort2*)&C[(size_t)(r0 + 8) * 2048 + col]        = h1;
                *(ushort2*)&C[(size_t)(r0 + 8) * 2048 + 1024 + col] = l1;
            } else {
                ushort_t* C = (ushort_t*)Cout;
                int cl = col - 1024;
                *(ushort2*)&C[(size_t)r0 * 2048 + cl] =
                    make_ushort2(fp16hi(a0), fp16hi(a1));
                *(ushort2*)&C[(size_t)(r0 + 8) * 2048 + cl] =
                    make_ushort2(fp16hi(a2), fp16hi(a3));
            }
        }
    }
}

// ---------------------------------------------------------------------------
// Fused attention: all staging via cp.async from fp16 Q/K/V.
// pass1: S = exp((Qh+Ql)·Kh /8) -> fp16 scratch; K double-buffered.
// pass2: P=relu(e*linv-TH) fp16; V staged [k][d], B-frags via ldmatrix.trans.
// ---------------------------------------------------------------------------
struct SmemAttn3 {
    float l_red[128];
    float l_inv[128];
    union {
        struct { ushort_t Qh[128 * PQ_], Ql[128 * PQ_], Kh[2][128 * PQ_]; } p1;
        struct { ushort_t Ph[128 * PV_], Vs[128 * PQ_]; } p2;
    } u;
};

__global__ __launch_bounds__(256, 2) void fused_attn_mma_kernel(
    const ushort_t* __restrict__ Qs, const ushort_t* __restrict__ KVh,
    ushort_t* __restrict__ scratch, ushort_t* __restrict__ Ys)
{
    extern __shared__ char smem_raw[];
    SmemAttn3& sm = *reinterpret_cast<SmemAttn3*>(smem_raw);

    const int qb = blockIdx.x;
    const int bh = blockIdx.y;
    const int b  = bh >> 4;
    const int h  = bh & 15;
    const int hc = h * HD_;
    const ushort_t* qrow = Qs  + (size_t)b * T_ * 2048;
    const ushort_t* kvrow = KVh + (size_t)b * T_ * 2048;
    ushort_t* sc = scratch + (((size_t)bh * 8 + qb) << 17);

    const int tid  = threadIdx.x;
    const int lane = tid & 31, wid = tid >> 5;
    const int q0   = qb << 7;
    const int g    = lane >> 2;

    if (tid < 128) sm.l_red[tid] = 0.0f;

    const uint32_t sQh = smem_u32(sm.u.p1.Qh), sQl = smem_u32(sm.u.p1.Ql);
    const uint32_t sK0 = smem_u32(sm.u.p1.Kh[0]);
    const uint32_t KBUF = 128 * PQ_ * 2;    // bytes per K buffer

    // stage Q hi/lo (128 rows x 8 chunks each) + K tile 0 via cp.async
    #pragma unroll
    for (int l = 0; l < 4; ++l) {
        int c = tid + (l << 8);           // 0..1023
        int r = c >> 3, j = c & 7;
        const ushort_t* src = qrow + (size_t)(q0 + r) * 2048 + hc + (j << 3);
        uint32_t d = (uint32_t)(r * PQ_ + (j << 3)) * 2;
        cp16(sQh + d, src);
        cp16(sQl + d, src + 1024);
        cp16(sK0 + d, kvrow + (size_t)r * 2048 + hc + (j << 3));
    }
    CP_COMMIT();
    CP_WAIT0();
    __syncthreads();

    const int wm = (wid & 1) << 6;
    const int wn = (wid >> 1) << 5;
    const uint32_t aoff = (uint32_t)((wm + (lane & 15)) * PQ_ + (lane >> 4) * 8) * 2;
    const uint32_t boff = (uint32_t)((wn + (lane & 7) + ((lane >> 4) << 3)) * PQ_
                                     + ((lane >> 3) & 1) * 8) * 2;

    float lsum[8];
    #pragma unroll
    for (int i = 0; i < 8; i++) lsum[i] = 0.0f;

    for (int t = 0; t < 8; ++t) {
        const int k0 = t << 7;
        const int buf = t & 1;
        if (t + 1 < 8) {
            const uint32_t dstK = sK0 + (uint32_t)(1 - buf) * KBUF;
            #pragma unroll
            for (int l = 0; l < 4; ++l) {
                int c = tid + (l << 8);
                int r = c >> 3, j = c & 7;
                cp16(dstK + (uint32_t)(r * PQ_ + (j << 3)) * 2,
                     kvrow + (size_t)(k0 + 128 + r) * 2048 + hc + (j << 3));
            }
            CP_COMMIT();
        }

        const uint32_t sKb = sK0 + (uint32_t)buf * KBUF;

        float acc[4][4][4];
        #pragma unroll
        for (int i = 0; i < 4; i++)
            #pragma unroll
            for (int j = 0; j < 4; j++)
                #pragma unroll
                for (int k = 0; k < 4; k++) acc[i][j][k] = 0.0f;

        #pragma unroll
        for (int ks = 0; ks < 4; ++ks) {
            uint32_t bf[2][4];
            ldsm4(bf[0], sKb + boff + ks * 32);
            ldsm4(bf[1], sKb + boff + (16 * PQ_ * 2) + ks * 32);
            uint32_t af[4][4];
            #pragma unroll
            for (int mi = 0; mi < 4; ++mi)
                ldsm4(af[mi], sQh + aoff + mi * (16 * PQ_ * 2) + ks * 32);
            #pragma unroll
            for (int mi = 0; mi < 4; ++mi) {
                mma16816(acc[mi][0], af[mi], bf[0][0], bf[0][1]);
                mma16816(acc[mi][1], af[mi], bf[0][2], bf[0][3]);
                mma16816(acc[mi][2], af[mi], bf[1][0], bf[1][1]);
                mma16816(acc[mi][3], af[mi], bf[1][2], bf[1][3]);
            }
            #pragma unroll
            for (int mi = 0; mi < 4; ++mi)
                ldsm4(af[mi], sQl + aoff + mi * (16 * PQ_ * 2) + ks * 32);
            #pragma unroll
            for (int mi = 0; mi < 4; ++mi) {
                mma16816(acc[mi][0], af[mi], bf[0][0], bf[0][1]);
                mma16816(acc[mi][1], af[mi], bf[0][2], bf[0][3]);
                mma16816(acc[mi][2], af[mi], bf[1][0], bf[1][1]);
                mma16816(acc[mi][3], af[mi], bf[1][2], bf[1][3]);
            }
        }

        #pragma unroll
        for (int mi = 0; mi < 4; ++mi) {
            #pragma unroll
            for (int ni = 0; ni < 4; ++ni) {
                float e0 = __expf(acc[mi][ni][0] * 0.125f);
                float e1 = __expf(acc[mi][ni][1] * 0.125f);
                float e2 = __expf(acc[mi][ni][2] * 0.125f);
                float e3 = __expf(acc[mi][ni][3] * 0.125f);
                lsum[mi * 2 + 0] += e0 + e1;
                lsum[mi * 2 + 1] += e2 + e3;
                int col = k0 + wn + ni * 8 + ((lane & 3) << 1);
                int r0  = wm + mi * 16 + g;
                *(ushort2*)(sc + (size_t)r0 * 1024 + col) =
                    make_ushort2(fp16hi(e0), fp16hi(e1));
                *(ushort2*)(sc + (size_t)(r0 + 8) * 1024 + col) =
                    make_ushort2(fp16hi(e2), fp16hi(e3));
            }
        }

        if (t + 1 < 8) CP_WAIT0();
        __syncthreads();
    }

    #pragma unroll
    for (int i = 0; i < 8; i++) {
        float v = lsum[i];
        v += __shfl_xor_sync(0xFFFFFFFFu, v, 1);
        v += __shfl_xor_sync(0xFFFFFFFFu, v, 2);
        if ((lane & 3) == 0) {
            int row = wm + (i >> 1) * 16 + g + (i & 1) * 8;
            atomicAdd(&sm.l_red[row], v);
        }
    }
    __syncthreads();
    if (tid < 128) sm.l_inv[tid] = 1.0f / sm.l_red[tid];

    // ---- pass 2: k-chunks of 128; V [k][d] via cp.async; B frags via ldsm.trans
    const int wm2 = (wid & 1) << 6;
    const int wn2 = (wid >> 1) << 4;
    const uint32_t sPh = smem_u32(sm.u.p2.Ph);
    const uint32_t sVs = smem_u32(sm.u.p2.Vs);
    const uint32_t aoff2 = (uint32_t)((wm2 + (lane & 15)) * PV_ + (lane >> 4) * 8) * 2;
    const uint32_t boff2t = (uint32_t)((lane & 15) * PQ_ + wn2 + ((lane >> 4) << 3)) * 2;

    float accy[4][2][4];
    #pragma unroll
    for (int i = 0; i < 4; i++)
        #pragma unroll
        for (int j = 0; j < 2; j++)
            #pragma unroll
            for (int k = 0; k < 4; k++) accy[i][j][k] = 0.0f;

    for (int kc = 0; kc < T_; kc += 128) {
        __syncthreads();
        // V chunk (128 k x 64 d) via cp.async, straight [k][d]
        #pragma unroll
        for (int l = 0; l < 4; ++l) {
            int c = tid + (l << 8);
            int r = c >> 3, j = c & 7;
            cp16(sVs + (uint32_t)(r * PQ_ + (j << 3)) * 2,
                 kvrow + (size_t)(kc + r) * 2048 + 1024 + hc + (j << 3));
        }
        CP_COMMIT();
        // P = relu(e*linv - TH) fp16 (compute overlaps cp.async)
        #pragma unroll
        for (int l = 0; l < 16; ++l) {
            int idx = tid + (l << 8);
            int r   = idx >> 5;
            int c4  = (idx & 31) << 2;
            ushort4 eu = *(const ushort4*)(sc + (size_t)r * 1024 + kc + c4);
            float iv = sm.l_inv[r];
            ushort4 pv;
            pv.x = fp16hi(fmaxf(fmaf(fp16f(eu.x), iv, -TH_), 0.0f));
            pv.y = fp16hi(fmaxf(fmaf(fp16f(eu.y), iv, -TH_), 0.0f));
            pv.z = fp16hi(fmaxf(fmaf(fp16f(eu.z), iv, -TH_), 0.0f));
            pv.w = fp16hi(fmaxf(fmaf(fp16f(eu.w), iv, -TH_), 0.0f));
            *(ushort4*)&sm.u.p2.Ph[r * PV_ + c4] = pv;
        }
        CP_WAIT0();
        __syncthreads();

        #pragma unroll
        for (int ks = 0; ks < 8; ++ks) {
            uint32_t bf[4];
            ldsm4t(bf, sVs + boff2t + ks * (16 * PQ_ * 2));
            uint32_t af[4][4];
            #pragma unroll
            for (int mi = 0; mi < 4; ++mi)
                ldsm4(af[mi], sPh + aoff2 + mi * (16 * PV_ * 2) + ks * 32);
            #pragma unroll
            for (int mi = 0; mi < 4; ++mi) {
                mma16816(accy[mi][0], af[mi], bf[0], bf[1]);
                mma16816(accy[mi][1], af[mi], bf[2], bf[3]);
            }
        }
    }

    // epilogue: Y -> g_ys in [hi | lo] split layout
    #pragma unroll
    for (int mi = 0; mi < 4; ++mi) {
        #pragma unroll
        for (int ni = 0; ni < 2; ++ni) {
            int ch = hc + wn2 + ni * 8 + ((lane & 3) << 1);
            #pragma unroll
            for (int hv = 0; hv < 2; ++hv) {
                int rq = q0 + wm2 + mi * 16 + g + hv * 8;
                size_t rg = ((size_t)b * T_ + rq) * KSP_;
                ushort2 hp, lp;
                fp16split(accy[mi][ni][hv * 2 + 0], hp.x, lp.x);
                fp16split(accy[mi][ni][hv * 2 + 1], hp.y, lp.y);
                *(ushort2*)&Ys[rg + ch]        = hp;
                *(ushort2*)&Ys[rg + 1024 + ch] = lp;
            }
        }
    }
}

// ---------------------------------------------------------------------------
extern "C" void kernel_launch(void* const* d_in, const int* in_sizes, int n_in,
                              void* d_out, int out_size)
{
    const float* x      = (const float*)d_in[0];
    const float* w_attn = (const float*)d_in[1];
    const float* b_attn = (const float*)d_in[2];
    const float* w_proj = (const float*)d_in[3];
    const float* b_proj = (const float*)d_in[4];
    float* out = (float*)d_out;

    ushort_t *qs, *kvh, *S, *xs, *ys, *wa, *wp;
    cudaGetSymbolAddress((void**)&qs,  g_qs);
    cudaGetSymbolAddress((void**)&kvh, g_kvh);
    cudaGetSymbolAddress((void**)&S,   g_S);
    cudaGetSymbolAddress((void**)&xs,  g_xs);
    cudaGetSymbolAddress((void**)&ys,  g_ys);
    cudaGetSymbolAddress((void**)&wa,  g_wa);
    cudaGetSymbolAddress((void**)&wp,  g_wp);

    const int smem2 = 6 * ABUF * 2;   // 61440 B
    const int smem1 = 4 * ABUF * 2;   // 40960 B
    cudaFuncSetAttribute(gemm_mma_kernel<2, 1>,
                         cudaFuncAttributeMaxDynamicSharedMemorySize, smem2);
    cudaFuncSetAttribute(gemm_mma_kernel<1, 2>,
                         cudaFuncAttributeMaxDynamicSharedMemorySize, smem1);
    cudaFuncSetAttribute(gemm_mma_kernel<2, 0>,
                         cudaFuncAttributeMaxDynamicSharedMemorySize, smem2);
    cudaFuncSetAttribute(fused_attn_mma_kernel,
                         cudaFuncAttributeMaxDynamicSharedMemorySize,
                         (int)sizeof(SmemAttn3));

    // prep
    prep_split_kernel<<<B_ * T_, 256>>>(x, xs);
    prep_wt_kernel<<<dim3(C3_ / 32, C_ / 32), 256>>>(w_attn, wa, C3_);
    prep_wt_kernel<<<dim3(C_ / 32, C_ / 32), 256>>>(w_proj, wp, C_);

    // 1) QKV projection: Q -> fp16 split (2-term), K/V -> fp16 hi (1-term)
    gemm_mma_kernel<2, 1><<<dim3(8, 64), 256, smem2>>>(
        xs, wa, b_attn, qs, C3_, 0);
    gemm_mma_kernel<1, 2><<<dim3(16, 64), 256, smem1>>>(
        xs, wa, b_attn, kvh, C3_, 1024);

    // 2) fused attention
    fused_attn_mma_kernel<<<dim3(T_ / 128, BH_), 256, sizeof(SmemAttn3)>>>(
        qs, kvh, S, ys);

    // 3) output projection (fp32 out)
    gemm_mma_kernel<2, 0><<<dim3(8, 64), 256, smem2>>>(
        ys, wp, b_proj, out, C_, 0);
}

// round 11
// speedup vs baseline: 5.4689x; 1.1621x over previous
#include <cuda_runtime.h>
#include <cuda_fp16.h>
#include <cstddef>
#include <cstdint>

#define B_   8
#define T_   1024
#define C_   1024
#define H_   16
#define HD_  64
#define BH_  (B_ * H_)          // 128
#define C3_  (3 * C_)           // 3072
#define KSP_ 2048               // x split: [hi | lo]
#define KW_  1024               // weight hi-only K
#define TH_  0.001f
#define PQ_  72                 // smem pitch (halves) for 64-wide tiles
#define PV_  136                // smem pitch (halves) for 128-wide tiles

using ushort_t = unsigned short;

// ---------------- scratch (static device globals) ----------------
__device__ __align__(16) ushort_t g_qkvh[(size_t)B_ * T_ * C3_];        // fp16 hi QKV
__device__ __align__(16) ushort_t g_yh[(size_t)B_ * T_ * C_];           // fp16 hi Y
__device__ __align__(16) ushort_t g_S[(size_t)BH_ * T_ * T_];           // fp16 exp
__device__ __align__(16) ushort_t g_xs[(size_t)B_ * T_ * KSP_];         // x [hi|lo]
__device__ __align__(16) ushort_t g_wa[(size_t)C3_ * KW_];              // w_attn^T hi
__device__ __align__(16) ushort_t g_wp[(size_t)C_ * KW_];               // w_proj^T hi

// ---------------- helpers ----------------
__device__ __forceinline__ uint32_t smem_u32(const void* p) {
    uint32_t a;
    asm("{ .reg .u64 t; cvta.to.shared.u64 t, %1; cvt.u32.u64 %0, t; }"
        : "=r"(a) : "l"(p));
    return a;
}
__device__ __forceinline__ void ldsm4(uint32_t (&r)[4], uint32_t addr) {
    asm volatile("ldmatrix.sync.aligned.m8n8.x4.shared.b16 {%0,%1,%2,%3}, [%4];"
        : "=r"(r[0]), "=r"(r[1]), "=r"(r[2]), "=r"(r[3]) : "r"(addr));
}
__device__ __forceinline__ void ldsm4t(uint32_t (&r)[4], uint32_t addr) {
    asm volatile("ldmatrix.sync.aligned.m8n8.x4.trans.shared.b16 {%0,%1,%2,%3}, [%4];"
        : "=r"(r[0]), "=r"(r[1]), "=r"(r[2]), "=r"(r[3]) : "r"(addr));
}
__device__ __forceinline__ void mma16816(float (&d)[4], const uint32_t (&a)[4],
                                         uint32_t b0, uint32_t b1) {
    asm volatile(
        "mma.sync.aligned.m16n8k16.row.col.f32.f16.f16.f32 "
        "{%0,%1,%2,%3}, {%4,%5,%6,%7}, {%8,%9}, {%0,%1,%2,%3};"
        : "+f"(d[0]), "+f"(d[1]), "+f"(d[2]), "+f"(d[3])
        : "r"(a[0]), "r"(a[1]), "r"(a[2]), "r"(a[3]), "r"(b0), "r"(b1));
}
__device__ __forceinline__ void cp16(uint32_t dst, const void* src) {
    asm volatile("cp.async.cg.shared.global [%0], [%1], 16;"
                 :: "r"(dst), "l"(src) : "memory");
}
#define CP_COMMIT() asm volatile("cp.async.commit_group;" ::: "memory")
#define CP_WAIT0()  asm volatile("cp.async.wait_group 0;" ::: "memory")

__device__ __forceinline__ void fp16split(float v, ushort_t &h, ushort_t &l) {
    __half hb = __float2half_rn(v);
    __half lb = __float2half_rn(v - __half2float(hb));
    h = __half_as_ushort(hb);
    l = __half_as_ushort(lb);
}
__device__ __forceinline__ ushort_t fp16hi(float v) {
    return __half_as_ushort(__float2half_rn(v));
}
__device__ __forceinline__ float fp16f(ushort_t u) {
    return __half2float(__ushort_as_half(u));
}

// ---------------------------------------------------------------------------
// prep kernels
// ---------------------------------------------------------------------------
__global__ __launch_bounds__(256) void prep_split_kernel(
    const float* __restrict__ X, ushort_t* __restrict__ Xs)
{
    const size_t r = blockIdx.x;
    const int c4 = threadIdx.x << 2;
    float4 v = *(const float4*)(X + r * 1024 + c4);
    ushort4 hv, lv;
    fp16split(v.x, hv.x, lv.x); fp16split(v.y, hv.y, lv.y);
    fp16split(v.z, hv.z, lv.z); fp16split(v.w, hv.w, lv.w);
    ushort_t* row = Xs + r * KSP_;
    *(ushort4*)(row + c4)        = hv;
    *(ushort4*)(row + 1024 + c4) = lv;
}

__global__ __launch_bounds__(256) void prep_wt_kernel(
    const float* __restrict__ W, ushort_t* __restrict__ Wt, int N)
{
    __shared__ float t[32][33];
    const int n0 = blockIdx.x << 5;
    const int k0 = blockIdx.y << 5;
    const int row = threadIdx.x >> 5;
    const int col = threadIdx.x & 31;
    #pragma unroll
    for (int p = 0; p < 4; ++p)
        t[row + p * 8][col] = W[(size_t)(k0 + row + p * 8) * N + n0 + col];
    __syncthreads();
    #pragma unroll
    for (int p = 0; p < 4; ++p) {
        int n = row + p * 8, k = col;
        Wt[(size_t)(n0 + n) * KW_ + k0 + k] = fp16hi(t[k][n]);
    }
}

// ---------------------------------------------------------------------------
// HMMA GEMM, cp.async staging + phase-pipelined fragments.
// TERMS: 2 -> (Ah+Al)xWh^T ; 1 -> Ah x Wh^T      (A row stride = astride; lo @ +1024)
// EPI: 0 -> fp32 C[M][N]+bias ; 2 -> fp16 hi, row stride 3072, at column col
// ---------------------------------------------------------------------------
#define PITCH 40
#define ABUF  (128 * PITCH)
#define ROWBLK (16 * PITCH * 2)

template<int TERMS, int EPI>
__global__ __launch_bounds__(256, 2) void gemm_mma_kernel(
    const ushort_t* __restrict__ A, const ushort_t* __restrict__ Bh,
    const float* __restrict__ bias, void* __restrict__ Cout, int N, int n_base,
    int astride)
{
    extern __shared__ ushort_t gs[];
    ushort_t* sAh = gs;
    ushort_t* sAl = gs + 2 * ABUF;
    ushort_t* sBs = gs + (TERMS == 2 ? 4 : 2) * ABUF;

    const int tid  = threadIdx.x;
    const int lane = tid & 31, wid = tid >> 5;
    const int m0 = blockIdx.y << 7;
    const int n0 = n_base + (blockIdx.x << 7);
    const int wm = (wid & 1) << 6;
    const int wn = (wid >> 1) << 5;

    float acc[4][4][4];
    #pragma unroll
    for (int i = 0; i < 4; i++)
        #pragma unroll
        for (int j = 0; j < 4; j++)
            #pragma unroll
            for (int k = 0; k < 4; k++) acc[i][j][k] = 0.0f;

    const int r0s = tid >> 2, r1s = r0s + 64;
    const int js  = (tid & 3) << 3;
    const ushort_t* gA0 = A + (size_t)(m0 + r0s) * astride + js;
    const ushort_t* gA1 = A + (size_t)(m0 + r1s) * astride + js;
    const ushort_t* gB0 = Bh + (size_t)(n0 + r0s) * KW_ + js;
    const ushort_t* gB1 = Bh + (size_t)(n0 + r1s) * KW_ + js;
    const uint32_t so0b = (uint32_t)(r0s * PITCH + js) * 2;
    const uint32_t so1b = (uint32_t)(r1s * PITCH + js) * 2;

    const uint32_t uAh = smem_u32(sAh), uAl = smem_u32(sAl), uBs = smem_u32(sBs);
    const uint32_t AB2 = ABUF * 2;
    const uint32_t aoff = (uint32_t)((wm + (lane & 15)) * PITCH + (lane >> 4) * 8) * 2;
    const uint32_t boff = (uint32_t)((wn + (lane & 7) + ((lane >> 4) << 3)) * PITCH
                                     + ((lane >> 3) & 1) * 8) * 2;

    cp16(uAh + so0b, gA0); cp16(uAh + so1b, gA1);
    if (TERMS == 2) { cp16(uAl + so0b, gA0 + 1024); cp16(uAl + so1b, gA1 + 1024); }
    cp16(uBs + so0b, gB0); cp16(uBs + so1b, gB1);
    CP_COMMIT();
    CP_WAIT0();
    __syncthreads();

    for (int c = 0; c < 32; ++c) {
        const int buf = c & 1;
        if (c + 1 < 32) {
            const int kc = (c + 1) << 5;
            const uint32_t nb = (uint32_t)(1 - buf) * AB2;
            cp16(uAh + nb + so0b, gA0 + kc);
            cp16(uAh + nb + so1b, gA1 + kc);
            if (TERMS == 2) {
                cp16(uAl + nb + so0b, gA0 + 1024 + kc);
                cp16(uAl + nb + so1b, gA1 + 1024 + kc);
            }
            cp16(uBs + nb + so0b, gB0 + kc);
            cp16(uBs + nb + so1b, gB1 + kc);
            CP_COMMIT();
        }

        const uint32_t aHB = uAh + buf * AB2 + aoff;
        const uint32_t aLB = uAl + buf * AB2 + aoff;
        const uint32_t bBB = uBs + buf * AB2 + boff;

        uint32_t af[2][4][4], bf[2][2][4];
        ldsm4(bf[0][0], bBB);
        ldsm4(bf[0][1], bBB + ROWBLK);
        #pragma unroll
        for (int mi = 0; mi < 4; ++mi)
            ldsm4(af[0][mi], aHB + mi * ROWBLK);

        const int NPH = 2 * TERMS;
        #pragma unroll
        for (int ph = 0; ph < NPH; ++ph) {
            if (TERMS == 2) {
                if (ph == 0) {
                    #pragma unroll
                    for (int mi = 0; mi < 4; ++mi)
                        ldsm4(af[1][mi], aLB + mi * ROWBLK);
                } else if (ph == 1) {
                    ldsm4(bf[1][0], bBB + 32);
                    ldsm4(bf[1][1], bBB + ROWBLK + 32);
                    #pragma unroll
                    for (int mi = 0; mi < 4; ++mi)
                        ldsm4(af[0][mi], aHB + mi * ROWBLK + 32);
                } else if (ph == 2) {
                    #pragma unroll
                    for (int mi = 0; mi < 4; ++mi)
                        ldsm4(af[1][mi], aLB + mi * ROWBLK + 32);
                }
            } else {
                if (ph == 0) {
                    ldsm4(bf[1][0], bBB + 32);
                    ldsm4(bf[1][1], bBB + ROWBLK + 32);
                    #pragma unroll
                    for (int mi = 0; mi < 4; ++mi)
                        ldsm4(af[1][mi], aHB + mi * ROWBLK + 32);
                }
            }
            const int ai = ph & 1;
            const int bi = (TERMS == 2) ? (ph >> 1) : ph;
            #pragma unroll
            for (int mi = 0; mi < 4; ++mi) {
                mma16816(acc[mi][0], af[ai][mi], bf[bi][0][0], bf[bi][0][1]);
                mma16816(acc[mi][1], af[ai][mi], bf[bi][0][2], bf[bi][0][3]);
                mma16816(acc[mi][2], af[ai][mi], bf[bi][1][0], bf[bi][1][1]);
                mma16816(acc[mi][3], af[ai][mi], bf[bi][1][2], bf[bi][1][3]);
            }
        }

        if (c + 1 < 32) CP_WAIT0();
        __syncthreads();
    }

    const int g  = lane >> 2;
    const int tg = (lane & 3) << 1;
    #pragma unroll
    for (int ni = 0; ni < 4; ++ni) {
        int col = n0 + wn + ni * 8 + tg;
        float2 bv = *(const float2*)(bias + col);
        #pragma unroll
        for (int mi = 0; mi < 4; ++mi) {
            int r0 = m0 + wm + mi * 16 + g;
            float a0 = acc[mi][ni][0] + bv.x, a1 = acc[mi][ni][1] + bv.y;
            float a2 = acc[mi][ni][2] + bv.x, a3 = acc[mi][ni][3] + bv.y;
            if (EPI == 0) {
                float* C = (float*)Cout;
                *(float2*)&C[(size_t)r0 * N + col]       = make_float2(a0, a1);
                *(float2*)&C[(size_t)(r0 + 8) * N + col] = make_float2(a2, a3);
            } else {
                ushort_t* C = (ushort_t*)Cout;
                *(ushort2*)&C[(size_t)r0 * C3_ + col] =
                    make_ushort2(fp16hi(a0), fp16hi(a1));
                *(ushort2*)&C[(size_t)(r0 + 8) * C3_ + col] =
                    make_ushort2(fp16hi(a2), fp16hi(a3));
            }
        }
    }
}

// ---------------------------------------------------------------------------
// Fused attention (1-term QK): all staging cp.async from fp16 QKV-hi buffer.
// pass1: S = exp(Qh·Kh /8) -> fp16 scratch; K double-buffered.
// pass2: P=relu(e*linv-TH) fp16; V [k][d] via cp.async, B-frags ldmatrix.trans.
// Y -> fp16 hi (stride 1024).
// ---------------------------------------------------------------------------
struct SmemAttn4 {
    float l_red[128];
    float l_inv[128];
    union {
        struct { ushort_t Qh[128 * PQ_], Kh[2][128 * PQ_]; } p1;   // 54 KB
        struct { ushort_t Ph[128 * PV_], Vs[128 * PQ_]; } p2;      // 52 KB
    } u;
};

__global__ __launch_bounds__(256, 2) void fused_attn_mma_kernel(
    const ushort_t* __restrict__ QKVh, ushort_t* __restrict__ scratch,
    ushort_t* __restrict__ Yh)
{
    extern __shared__ char smem_raw[];
    SmemAttn4& sm = *reinterpret_cast<SmemAttn4*>(smem_raw);

    const int qb = blockIdx.x;
    const int bh = blockIdx.y;
    const int b  = bh >> 4;
    const int h  = bh & 15;
    const int hc = h * HD_;
    const ushort_t* base = QKVh + (size_t)b * T_ * C3_;
    ushort_t* sc = scratch + (((size_t)bh * 8 + qb) << 17);

    const int tid  = threadIdx.x;
    const int lane = tid & 31, wid = tid >> 5;
    const int q0   = qb << 7;
    const int g    = lane >> 2;

    if (tid < 128) sm.l_red[tid] = 0.0f;

    const uint32_t sQh = smem_u32(sm.u.p1.Qh);
    const uint32_t sK0 = smem_u32(sm.u.p1.Kh[0]);
    const uint32_t KBUF = 128 * PQ_ * 2;

    // stage Q-hi (128 x 64) + K tile 0 via cp.async
    #pragma unroll
    for (int l = 0; l < 4; ++l) {
        int c = tid + (l << 8);           // 0..1023
        int r = c >> 3, j = c & 7;
        uint32_t d = (uint32_t)(r * PQ_ + (j << 3)) * 2;
        cp16(sQh + d, base + (size_t)(q0 + r) * C3_ + hc + (j << 3));
        cp16(sK0 + d, base + (size_t)r * C3_ + 1024 + hc + (j << 3));
    }
    CP_COMMIT();
    CP_WAIT0();
    __syncthreads();

    const int wm = (wid & 1) << 6;
    const int wn = (wid >> 1) << 5;
    const uint32_t aoff = (uint32_t)((wm + (lane & 15)) * PQ_ + (lane >> 4) * 8) * 2;
    const uint32_t boff = (uint32_t)((wn + (lane & 7) + ((lane >> 4) << 3)) * PQ_
                                     + ((lane >> 3) & 1) * 8) * 2;

    float lsum[8];
    #pragma unroll
    for (int i = 0; i < 8; i++) lsum[i] = 0.0f;

    for (int t = 0; t < 8; ++t) {
        const int k0 = t << 7;
        const int buf = t & 1;
        if (t + 1 < 8) {
            const uint32_t dstK = sK0 + (uint32_t)(1 - buf) * KBUF;
            #pragma unroll
            for (int l = 0; l < 4; ++l) {
                int c = tid + (l << 8);
                int r = c >> 3, j = c & 7;
                cp16(dstK + (uint32_t)(r * PQ_ + (j << 3)) * 2,
                     base + (size_t)(k0 + 128 + r) * C3_ + 1024 + hc + (j << 3));
            }
            CP_COMMIT();
        }

        const uint32_t sKb = sK0 + (uint32_t)buf * KBUF;

        float acc[4][4][4];
        #pragma unroll
        for (int i = 0; i < 4; i++)
            #pragma unroll
            for (int j = 0; j < 4; j++)
                #pragma unroll
                for (int k = 0; k < 4; k++) acc[i][j][k] = 0.0f;

        #pragma unroll
        for (int ks = 0; ks < 4; ++ks) {
            uint32_t bf[2][4];
            ldsm4(bf[0], sKb + boff + ks * 32);
            ldsm4(bf[1], sKb + boff + (16 * PQ_ * 2) + ks * 32);
            uint32_t af[4][4];
            #pragma unroll
            for (int mi = 0; mi < 4; ++mi)
                ldsm4(af[mi], sQh + aoff + mi * (16 * PQ_ * 2) + ks * 32);
            #pragma unroll
            for (int mi = 0; mi < 4; ++mi) {
                mma16816(acc[mi][0], af[mi], bf[0][0], bf[0][1]);
                mma16816(acc[mi][1], af[mi], bf[0][2], bf[0][3]);
                mma16816(acc[mi][2], af[mi], bf[1][0], bf[1][1]);
                mma16816(acc[mi][3], af[mi], bf[1][2], bf[1][3]);
            }
        }

        #pragma unroll
        for (int mi = 0; mi < 4; ++mi) {
            #pragma unroll
            for (int ni = 0; ni < 4; ++ni) {
                float e0 = __expf(acc[mi][ni][0] * 0.125f);
                float e1 = __expf(acc[mi][ni][1] * 0.125f);
                float e2 = __expf(acc[mi][ni][2] * 0.125f);
                float e3 = __expf(acc[mi][ni][3] * 0.125f);
                lsum[mi * 2 + 0] += e0 + e1;
                lsum[mi * 2 + 1] += e2 + e3;
                int col = k0 + wn + ni * 8 + ((lane & 3) << 1);
                int r0  = wm + mi * 16 + g;
                *(ushort2*)(sc + (size_t)r0 * 1024 + col) =
                    make_ushort2(fp16hi(e0), fp16hi(e1));
                *(ushort2*)(sc + (size_t)(r0 + 8) * 1024 + col) =
                    make_ushort2(fp16hi(e2), fp16hi(e3));
            }
        }

        if (t + 1 < 8) CP_WAIT0();
        __syncthreads();
    }

    #pragma unroll
    for (int i = 0; i < 8; i++) {
        float v = lsum[i];
        v += __shfl_xor_sync(0xFFFFFFFFu, v, 1);
        v += __shfl_xor_sync(0xFFFFFFFFu, v, 2);
        if ((lane & 3) == 0) {
            int row = wm + (i >> 1) * 16 + g + (i & 1) * 8;
            atomicAdd(&sm.l_red[row], v);
        }
    }
    __syncthreads();
    if (tid < 128) sm.l_inv[tid] = 1.0f / sm.l_red[tid];

    // ---- pass 2
    const int wm2 = (wid & 1) << 6;
    const int wn2 = (wid >> 1) << 4;
    const uint32_t sPh = smem_u32(sm.u.p2.Ph);
    const uint32_t sVs = smem_u32(sm.u.p2.Vs);
    const uint32_t aoff2 = (uint32_t)((wm2 + (lane & 15)) * PV_ + (lane >> 4) * 8) * 2;
    const uint32_t boff2t = (uint32_t)((lane & 15) * PQ_ + wn2 + ((lane >> 4) << 3)) * 2;

    float accy[4][2][4];
    #pragma unroll
    for (int i = 0; i < 4; i++)
        #pragma unroll
        for (int j = 0; j < 2; j++)
            #pragma unroll
            for (int k = 0; k < 4; k++) accy[i][j][k] = 0.0f;

    for (int kc = 0; kc < T_; kc += 128) {
        __syncthreads();
        #pragma unroll
        for (int l = 0; l < 4; ++l) {
            int c = tid + (l << 8);
            int r = c >> 3, j = c & 7;
            cp16(sVs + (uint32_t)(r * PQ_ + (j << 3)) * 2,
                 base + (size_t)(kc + r) * C3_ + 2048 + hc + (j << 3));
        }
        CP_COMMIT();
        #pragma unroll
        for (int l = 0; l < 16; ++l) {
            int idx = tid + (l << 8);
            int r   = idx >> 5;
            int c4  = (idx & 31) << 2;
            ushort4 eu = *(const ushort4*)(sc + (size_t)r * 1024 + kc + c4);
            float iv = sm.l_inv[r];
            ushort4 pv;
            pv.x = fp16hi(fmaxf(fmaf(fp16f(eu.x), iv, -TH_), 0.0f));
            pv.y = fp16hi(fmaxf(fmaf(fp16f(eu.y), iv, -TH_), 0.0f));
            pv.z = fp16hi(fmaxf(fmaf(fp16f(eu.z), iv, -TH_), 0.0f));
            pv.w = fp16hi(fmaxf(fmaf(fp16f(eu.w), iv, -TH_), 0.0f));
            *(ushort4*)&sm.u.p2.Ph[r * PV_ + c4] = pv;
        }
        CP_WAIT0();
        __syncthreads();

        #pragma unroll
        for (int ks = 0; ks < 8; ++ks) {
            uint32_t bf[4];
            ldsm4t(bf, sVs + boff2t + ks * (16 * PQ_ * 2));
            uint32_t af[4][4];
            #pragma unroll
            for (int mi = 0; mi < 4; ++mi)
                ldsm4(af[mi], sPh + aoff2 + mi * (16 * PV_ * 2) + ks * 32);
            #pragma unroll
            for (int mi = 0; mi < 4; ++mi) {
                mma16816(accy[mi][0], af[mi], bf[0], bf[1]);
                mma16816(accy[mi][1], af[mi], bf[2], bf[3]);
            }
        }
    }

    // epilogue: Y -> fp16 hi (stride 1024)
    #pragma unroll
    for (int mi = 0; mi < 4; ++mi) {
        #pragma unroll
        for (int ni = 0; ni < 2; ++ni) {
            int ch = hc + wn2 + ni * 8 + ((lane & 3) << 1);
            #pragma unroll
            for (int hv = 0; hv < 2; ++hv) {
                int rq = q0 + wm2 + mi * 16 + g + hv * 8;
                size_t rg = ((size_t)b * T_ + rq) * C_;
                *(ushort2*)&Yh[rg + ch] =
                    make_ushort2(fp16hi(accy[mi][ni][hv * 2 + 0]),
                                 fp16hi(accy[mi][ni][hv * 2 + 1]));
            }
        }
    }
}

// ---------------------------------------------------------------------------
extern "C" void kernel_launch(void* const* d_in, const int* in_sizes, int n_in,
                              void* d_out, int out_size)
{
    const float* x      = (const float*)d_in[0];
    const float* w_attn = (const float*)d_in[1];
    const float* b_attn = (const float*)d_in[2];
    const float* w_proj = (const float*)d_in[3];
    const float* b_proj = (const float*)d_in[4];
    float* out = (float*)d_out;

    ushort_t *qkvh, *yh, *S, *xs, *wa, *wp;
    cudaGetSymbolAddress((void**)&qkvh, g_qkvh);
    cudaGetSymbolAddress((void**)&yh,   g_yh);
    cudaGetSymbolAddress((void**)&S,    g_S);
    cudaGetSymbolAddress((void**)&xs,   g_xs);
    cudaGetSymbolAddress((void**)&wa,   g_wa);
    cudaGetSymbolAddress((void**)&wp,   g_wp);

    const int smem2 = 6 * ABUF * 2;   // 61440 B
    const int smem1 = 4 * ABUF * 2;   // 40960 B
    cudaFuncSetAttribute(gemm_mma_kernel<2, 2>,
                         cudaFuncAttributeMaxDynamicSharedMemorySize, smem2);
    cudaFuncSetAttribute(gemm_mma_kernel<1, 2>,
                         cudaFuncAttributeMaxDynamicSharedMemorySize, smem1);
    cudaFuncSetAttribute(gemm_mma_kernel<1, 0>,
                         cudaFuncAttributeMaxDynamicSharedMemorySize, smem1);
    cudaFuncSetAttribute(fused_attn_mma_kernel,
                         cudaFuncAttributeMaxDynamicSharedMemorySize,
                         (int)sizeof(SmemAttn4));

    // prep
    prep_split_kernel<<<B_ * T_, 256>>>(x, xs);
    prep_wt_kernel<<<dim3(C3_ / 32, C_ / 32), 256>>>(w_attn, wa, C3_);
    prep_wt_kernel<<<dim3(C_ / 32, C_ / 32), 256>>>(w_proj, wp, C_);

    // 1) QKV projection: Q (2-term) + K/V (1-term) -> unified fp16-hi buffer
    gemm_mma_kernel<2, 2><<<dim3(8, 64), 256, smem2>>>(
        xs, wa, b_attn, qkvh, C3_, 0, KSP_);
    gemm_mma_kernel<1, 2><<<dim3(16, 64), 256, smem1>>>(
        xs, wa, b_attn, qkvh, C3_, 1024, KSP_);

    // 2) fused attention (1-term QK), Y -> fp16 hi
    fused_attn_mma_kernel<<<dim3(T_ / 128, BH_), 256, sizeof(SmemAttn4)>>>(
        qkvh, S, yh);

    // 3) output projection (1-term, fp32 out)
    gemm_mma_kernel<1, 0><<<dim3(8, 64), 256, smem1>>>(
        yh, wp, b_proj, out, C_, 0, C_);
}

// round 12
// speedup vs baseline: 6.0994x; 1.1153x over previous
#include <cuda_runtime.h>
#include <cuda_fp16.h>
#include <cstddef>
#include <cstdint>

#define B_   8
#define T_   1024
#define C_   1024
#define H_   16
#define HD_  64
#define BH_  (B_ * H_)          // 128
#define C3_  (3 * C_)           // 3072
#define KW_  1024               // K for all GEMMs (hi-only)
#define TH_  0.001f
#define PQ_  72                 // staging pitch (halves) for 64-wide tiles
#define PS_  1032               // S panel pitch (halves): 2064 B rows

using ushort_t = unsigned short;

// ---------------- scratch (static device globals) ----------------
__device__ __align__(16) ushort_t g_qkvh[(size_t)B_ * T_ * C3_];        // fp16 hi QKV
__device__ __align__(16) ushort_t g_yh[(size_t)B_ * T_ * C_];           // fp16 hi Y
__device__ __align__(16) ushort_t g_xh[(size_t)B_ * T_ * C_];           // fp16 hi x
__device__ __align__(16) ushort_t g_wa[(size_t)C3_ * KW_];              // w_attn^T hi
__device__ __align__(16) ushort_t g_wp[(size_t)C_ * KW_];               // w_proj^T hi

// ---------------- helpers ----------------
__device__ __forceinline__ uint32_t smem_u32(const void* p) {
    uint32_t a;
    asm("{ .reg .u64 t; cvta.to.shared.u64 t, %1; cvt.u32.u64 %0, t; }"
        : "=r"(a) : "l"(p));
    return a;
}
__device__ __forceinline__ void ldsm4(uint32_t (&r)[4], uint32_t addr) {
    asm volatile("ldmatrix.sync.aligned.m8n8.x4.shared.b16 {%0,%1,%2,%3}, [%4];"
        : "=r"(r[0]), "=r"(r[1]), "=r"(r[2]), "=r"(r[3]) : "r"(addr));
}
__device__ __forceinline__ void ldsm4t(uint32_t (&r)[4], uint32_t addr) {
    asm volatile("ldmatrix.sync.aligned.m8n8.x4.trans.shared.b16 {%0,%1,%2,%3}, [%4];"
        : "=r"(r[0]), "=r"(r[1]), "=r"(r[2]), "=r"(r[3]) : "r"(addr));
}
__device__ __forceinline__ void mma16816(float (&d)[4], const uint32_t (&a)[4],
                                         uint32_t b0, uint32_t b1) {
    asm volatile(
        "mma.sync.aligned.m16n8k16.row.col.f32.f16.f16.f32 "
        "{%0,%1,%2,%3}, {%4,%5,%6,%7}, {%8,%9}, {%0,%1,%2,%3};"
        : "+f"(d[0]), "+f"(d[1]), "+f"(d[2]), "+f"(d[3])
        : "r"(a[0]), "r"(a[1]), "r"(a[2]), "r"(a[3]), "r"(b0), "r"(b1));
}
__device__ __forceinline__ void cp16(uint32_t dst, const void* src) {
    asm volatile("cp.async.cg.shared.global [%0], [%1], 16;"
                 :: "r"(dst), "l"(src) : "memory");
}
#define CP_COMMIT() asm volatile("cp.async.commit_group;" ::: "memory")
#define CP_WAIT0()  asm volatile("cp.async.wait_group 0;" ::: "memory")

__device__ __forceinline__ ushort_t fp16hi(float v) {
    return __half_as_ushort(__float2half_rn(v));
}
__device__ __forceinline__ float fp16f(ushort_t u) {
    return __half2float(__ushort_as_half(u));
}

// ---------------------------------------------------------------------------
// prep: fp32 [M][1024] -> fp16 hi [M][1024]
// ---------------------------------------------------------------------------
__global__ __launch_bounds__(256) void prep_xh_kernel(
    const float* __restrict__ X, ushort_t* __restrict__ Xh)
{
    const size_t r = blockIdx.x;
    const int c4 = threadIdx.x << 2;
    float4 v = *(const float4*)(X + r * 1024 + c4);
    *(ushort4*)(Xh + r * 1024 + c4) =
        make_ushort4(fp16hi(v.x), fp16hi(v.y), fp16hi(v.z), fp16hi(v.w));
}

// ---------------------------------------------------------------------------
// prep: W [1024 k][N] fp32 -> Wh [N][1024] fp16 hi, transposed
// ---------------------------------------------------------------------------
__global__ __launch_bounds__(256) void prep_wt_kernel(
    const float* __restrict__ W, ushort_t* __restrict__ Wt, int N)
{
    __shared__ float t[32][33];
    const int n0 = blockIdx.x << 5;
    const int k0 = blockIdx.y << 5;
    const int row = threadIdx.x >> 5;
    const int col = threadIdx.x & 31;
    #pragma unroll
    for (int p = 0; p < 4; ++p)
        t[row + p * 8][col] = W[(size_t)(k0 + row + p * 8) * N + n0 + col];
    __syncthreads();
    #pragma unroll
    for (int p = 0; p < 4; ++p) {
        int n = row + p * 8, k = col;
        Wt[(size_t)(n0 + n) * KW_ + k0 + k] = fp16hi(t[k][n]);
    }
}

// ---------------------------------------------------------------------------
// 1-term HMMA GEMM: C = Ah[M][1024] x Wh[N][1024]^T + bias
// EPI: 0 -> fp32 C[M][N] ; 2 -> fp16 hi, row stride 3072
// ---------------------------------------------------------------------------
#define PITCH 40
#define ABUF  (128 * PITCH)
#define ROWBLK (16 * PITCH * 2)

template<int EPI>
__global__ __launch_bounds__(256, 2) void gemm_mma_kernel(
    const ushort_t* __restrict__ A, const ushort_t* __restrict__ Bh,
    const float* __restrict__ bias, void* __restrict__ Cout, int N, int n_base,
    int astride)
{
    extern __shared__ ushort_t gs[];
    ushort_t* sAh = gs;
    ushort_t* sBs = gs + 2 * ABUF;

    const int tid  = threadIdx.x;
    const int lane = tid & 31, wid = tid >> 5;
    const int m0 = blockIdx.y << 7;
    const int n0 = n_base + (blockIdx.x << 7);
    const int wm = (wid & 1) << 6;
    const int wn = (wid >> 1) << 5;

    float acc[4][4][4];
    #pragma unroll
    for (int i = 0; i < 4; i++)
        #pragma unroll
        for (int j = 0; j < 4; j++)
            #pragma unroll
            for (int k = 0; k < 4; k++) acc[i][j][k] = 0.0f;

    const int r0s = tid >> 2, r1s = r0s + 64;
    const int js  = (tid & 3) << 3;
    const ushort_t* gA0 = A + (size_t)(m0 + r0s) * astride + js;
    const ushort_t* gA1 = A + (size_t)(m0 + r1s) * astride + js;
    const ushort_t* gB0 = Bh + (size_t)(n0 + r0s) * KW_ + js;
    const ushort_t* gB1 = Bh + (size_t)(n0 + r1s) * KW_ + js;
    const uint32_t so0b = (uint32_t)(r0s * PITCH + js) * 2;
    const uint32_t so1b = (uint32_t)(r1s * PITCH + js) * 2;

    const uint32_t uAh = smem_u32(sAh), uBs = smem_u32(sBs);
    const uint32_t AB2 = ABUF * 2;
    const uint32_t aoff = (uint32_t)((wm + (lane & 15)) * PITCH + (lane >> 4) * 8) * 2;
    const uint32_t boff = (uint32_t)((wn + (lane & 7) + ((lane >> 4) << 3)) * PITCH
                                     + ((lane >> 3) & 1) * 8) * 2;

    cp16(uAh + so0b, gA0); cp16(uAh + so1b, gA1);
    cp16(uBs + so0b, gB0); cp16(uBs + so1b, gB1);
    CP_COMMIT();
    CP_WAIT0();
    __syncthreads();

    for (int c = 0; c < 32; ++c) {
        const int buf = c & 1;
        if (c + 1 < 32) {
            const int kc = (c + 1) << 5;
            const uint32_t nb = (uint32_t)(1 - buf) * AB2;
            cp16(uAh + nb + so0b, gA0 + kc);
            cp16(uAh + nb + so1b, gA1 + kc);
            cp16(uBs + nb + so0b, gB0 + kc);
            cp16(uBs + nb + so1b, gB1 + kc);
            CP_COMMIT();
        }

        const uint32_t aHB = uAh + buf * AB2 + aoff;
        const uint32_t bBB = uBs + buf * AB2 + boff;

        uint32_t af[2][4][4], bf[2][2][4];
        ldsm4(bf[0][0], bBB);
        ldsm4(bf[0][1], bBB + ROWBLK);
        #pragma unroll
        for (int mi = 0; mi < 4; ++mi)
            ldsm4(af[0][mi], aHB + mi * ROWBLK);

        #pragma unroll
        for (int ph = 0; ph < 2; ++ph) {
            if (ph == 0) {
                ldsm4(bf[1][0], bBB + 32);
                ldsm4(bf[1][1], bBB + ROWBLK + 32);
                #pragma unroll
                for (int mi = 0; mi < 4; ++mi)
                    ldsm4(af[1][mi], aHB + mi * ROWBLK + 32);
            }
            #pragma unroll
            for (int mi = 0; mi < 4; ++mi) {
                mma16816(acc[mi][0], af[ph][mi], bf[ph][0][0], bf[ph][0][1]);
                mma16816(acc[mi][1], af[ph][mi], bf[ph][0][2], bf[ph][0][3]);
                mma16816(acc[mi][2], af[ph][mi], bf[ph][1][0], bf[ph][1][1]);
                mma16816(acc[mi][3], af[ph][mi], bf[ph][1][2], bf[ph][1][3]);
            }
        }

        if (c + 1 < 32) CP_WAIT0();
        __syncthreads();
    }

    const int g  = lane >> 2;
    const int tg = (lane & 3) << 1;
    #pragma unroll
    for (int ni = 0; ni < 4; ++ni) {
        int col = n0 + wn + ni * 8 + tg;
        float2 bv = *(const float2*)(bias + col);
        #pragma unroll
        for (int mi = 0; mi < 4; ++mi) {
            int r0 = m0 + wm + mi * 16 + g;
            float a0 = acc[mi][ni][0] + bv.x, a1 = acc[mi][ni][1] + bv.y;
            float a2 = acc[mi][ni][2] + bv.x, a3 = acc[mi][ni][3] + bv.y;
            if (EPI == 0) {
                float* C = (float*)Cout;
                *(float2*)&C[(size_t)r0 * N + col]       = make_float2(a0, a1);
                *(float2*)&C[(size_t)(r0 + 8) * N + col] = make_float2(a2, a3);
            } else {
                ushort_t* C = (ushort_t*)Cout;
                *(ushort2*)&C[(size_t)r0 * C3_ + col] =
                    make_ushort2(fp16hi(a0), fp16hi(a1));
                *(ushort2*)&C[(size_t)(r0 + 8) * C3_ + col] =
                    make_ushort2(fp16hi(a2), fp16hi(a3));
            }
        }
    }
}

// ---------------------------------------------------------------------------
// Fused attention, S resident in smem. q-block = 64 rows, 1 CTA/SM.
// pass1: S = exp(Qh·Kh /8) -> smem panel [64][1024] fp16 (pitch 1032).
// transform: P = relu(S*linv - TH) in place.
// pass2: Y = P·Vh, V double-buffered cp.async, B-frags ldmatrix.trans.
// ---------------------------------------------------------------------------
struct SmemAttn5 {
    float l_red[64];
    float l_inv[64];
    ushort_t S[64 * PS_];                                 // 132096 B
    union {
        struct { ushort_t Qh[64 * PQ_]; ushort_t Kh[2][128 * PQ_]; } p1;
        struct { ushort_t Vs[2][128 * PQ_]; } p2;
    } u;
};

__global__ __launch_bounds__(256, 1) void fused_attn_mma_kernel(
    const ushort_t* __restrict__ QKVh, ushort_t* __restrict__ Yh)
{
    extern __shared__ char smem_raw[];
    SmemAttn5& sm = *reinterpret_cast<SmemAttn5*>(smem_raw);

    const int qb = blockIdx.x;       // 0..15
    const int bh = blockIdx.y;       // 0..127
    const int b  = bh >> 4;
    const int h  = bh & 15;
    const int hc = h * HD_;
    const ushort_t* base = QKVh + (size_t)b * T_ * C3_;

    const int tid  = threadIdx.x;
    const int lane = tid & 31, wid = tid >> 5;
    const int q0   = qb << 6;
    const int g    = lane >> 2;

    if (tid < 64) sm.l_red[tid] = 0.0f;

    const uint32_t sQh = smem_u32(sm.u.p1.Qh);
    const uint32_t sK0 = smem_u32(sm.u.p1.Kh[0]);
    const uint32_t sS  = smem_u32(sm.S);
    const uint32_t KBUF = 128 * PQ_ * 2;

    // stage Q-hi (64 x 64) + K tile 0 (128 x 64) via cp.async
    #pragma unroll
    for (int l = 0; l < 2; ++l) {
        int c = tid + (l << 8);           // 0..511
        int r = c >> 3, j = c & 7;
        cp16(sQh + (uint32_t)(r * PQ_ + (j << 3)) * 2,
             base + (size_t)(q0 + r) * C3_ + hc + (j << 3));
    }
    #pragma unroll
    for (int l = 0; l < 4; ++l) {
        int c = tid + (l << 8);           // 0..1023
        int r = c >> 3, j = c & 7;
        cp16(sK0 + (uint32_t)(r * PQ_ + (j << 3)) * 2,
             base + (size_t)r * C3_ + 1024 + hc + (j << 3));
    }
    CP_COMMIT();
    CP_WAIT0();
    __syncthreads();

    // pass1 warp layout: 2(m:32) x 4(n-keys:32)
    const int wm = (wid & 1) << 5;
    const int wn = (wid >> 1) << 5;
    const uint32_t aoff = (uint32_t)((wm + (lane & 15)) * PQ_ + (lane >> 4) * 8) * 2;
    const uint32_t boff = (uint32_t)((wn + (lane & 7) + ((lane >> 4) << 3)) * PQ_
                                     + ((lane >> 3) & 1) * 8) * 2;

    float lsum[4];
    #pragma unroll
    for (int i = 0; i < 4; i++) lsum[i] = 0.0f;

    for (int t = 0; t < 8; ++t) {
        const int k0 = t << 7;
        const int buf = t & 1;
        if (t + 1 < 8) {
            const uint32_t dstK = sK0 + (uint32_t)(1 - buf) * KBUF;
            #pragma unroll
            for (int l = 0; l < 4; ++l) {
                int c = tid + (l << 8);
                int r = c >> 3, j = c & 7;
                cp16(dstK + (uint32_t)(r * PQ_ + (j << 3)) * 2,
                     base + (size_t)(k0 + 128 + r) * C3_ + 1024 + hc + (j << 3));
            }
            CP_COMMIT();
        }

        const uint32_t sKb = sK0 + (uint32_t)buf * KBUF;

        float acc[2][4][4];
        #pragma unroll
        for (int i = 0; i < 2; i++)
            #pragma unroll
            for (int j = 0; j < 4; j++)
                #pragma unroll
                for (int k = 0; k < 4; k++) acc[i][j][k] = 0.0f;

        #pragma unroll
        for (int ks = 0; ks < 4; ++ks) {
            uint32_t bf[2][4];
            ldsm4(bf[0], sKb + boff + ks * 32);
            ldsm4(bf[1], sKb + boff + (16 * PQ_ * 2) + ks * 32);
            uint32_t af[2][4];
            #pragma unroll
            for (int mi = 0; mi < 2; ++mi)
                ldsm4(af[mi], sQh + aoff + mi * (16 * PQ_ * 2) + ks * 32);
            #pragma unroll
            for (int mi = 0; mi < 2; ++mi) {
                mma16816(acc[mi][0], af[mi], bf[0][0], bf[0][1]);
                mma16816(acc[mi][1], af[mi], bf[0][2], bf[0][3]);
                mma16816(acc[mi][2], af[mi], bf[1][0], bf[1][1]);
                mma16816(acc[mi][3], af[mi], bf[1][2], bf[1][3]);
            }
        }

        // exp epilogue -> smem S panel, fp32 row sums
        #pragma unroll
        for (int mi = 0; mi < 2; ++mi) {
            #pragma unroll
            for (int ni = 0; ni < 4; ++ni) {
                float e0 = __expf(acc[mi][ni][0] * 0.125f);
                float e1 = __expf(acc[mi][ni][1] * 0.125f);
                float e2 = __expf(acc[mi][ni][2] * 0.125f);
                float e3 = __expf(acc[mi][ni][3] * 0.125f);
                lsum[mi * 2 + 0] += e0 + e1;
                lsum[mi * 2 + 1] += e2 + e3;
                int col = k0 + wn + ni * 8 + ((lane & 3) << 1);
                int r0  = wm + mi * 16 + g;
                *(ushort2*)&sm.S[(size_t)r0 * PS_ + col] =
                    make_ushort2(fp16hi(e0), fp16hi(e1));
                *(ushort2*)&sm.S[(size_t)(r0 + 8) * PS_ + col] =
                    make_ushort2(fp16hi(e2), fp16hi(e3));
            }
        }

        if (t + 1 < 8) CP_WAIT0();
        __syncthreads();
    }

    #pragma unroll
    for (int i = 0; i < 4; i++) {
        float v = lsum[i];
        v += __shfl_xor_sync(0xFFFFFFFFu, v, 1);
        v += __shfl_xor_sync(0xFFFFFFFFu, v, 2);
        if ((lane & 3) == 0) {
            int row = wm + (i >> 1) * 16 + g + (i & 1) * 8;
            atomicAdd(&sm.l_red[row], v);
        }
    }
    __syncthreads();
    if (tid < 64) sm.l_inv[tid] = 1.0f / sm.l_red[tid];
    __syncthreads();

    // in-place transform: P = relu(e * linv - TH)
    #pragma unroll
    for (int l = 0; l < 32; ++l) {
        int idx = tid + (l << 8);          // 0..8191
        int r   = idx >> 7;                // 0..63
        int c8  = (idx & 127) << 3;        // 0..1016
        ushort_t* p = &sm.S[(size_t)r * PS_ + c8];
        uint4 eu = *(uint4*)p;
        float iv = sm.l_inv[r];
        ushort_t* ep = (ushort_t*)&eu;
        #pragma unroll
        for (int i = 0; i < 8; ++i)
            ep[i] = fp16hi(fmaxf(fmaf(fp16f(ep[i]), iv, -TH_), 0.0f));
        *(uint4*)p = eu;
    }

    // stage V chunk 0 while transform finishes elsewhere
    const uint32_t sV0 = smem_u32(sm.u.p2.Vs[0]);
    #pragma unroll
    for (int l = 0; l < 4; ++l) {
        int c = tid + (l << 8);
        int r = c >> 3, j = c & 7;
        cp16(sV0 + (uint32_t)(r * PQ_ + (j << 3)) * 2,
             base + (size_t)r * C3_ + 2048 + hc + (j << 3));
    }
    CP_COMMIT();
    CP_WAIT0();
    __syncthreads();

    // pass2: 2(m:32) x 4(n-dims:16); k-chunks of 128
    const int wm2 = (wid & 1) << 5;
    const int wn2 = (wid >> 1) << 4;
    const uint32_t aoff2 = (uint32_t)((wm2 + (lane & 15)) * PS_ + (lane >> 4) * 8) * 2;
    const uint32_t boff2t = (uint32_t)((lane & 15) * PQ_ + wn2 + ((lane >> 4) << 3)) * 2;

    float accy[2][2][4];
    #pragma unroll
    for (int i = 0; i < 2; i++)
        #pragma unroll
        for (int j = 0; j < 2; j++)
            #pragma unroll
            for (int k = 0; k < 4; k++) accy[i][j][k] = 0.0f;

    for (int t = 0; t < 8; ++t) {
        const int kc = t << 7;
        const int buf = t & 1;
        if (t + 1 < 8) {
            const uint32_t dstV = sV0 + (uint32_t)(1 - buf) * KBUF;
            #pragma unroll
            for (int l = 0; l < 4; ++l) {
                int c = tid + (l << 8);
                int r = c >> 3, j = c & 7;
                cp16(dstV + (uint32_t)(r * PQ_ + (j << 3)) * 2,
                     base + (size_t)(kc + 128 + r) * C3_ + 2048 + hc + (j << 3));
            }
            CP_COMMIT();
        }

        const uint32_t sVb = sV0 + (uint32_t)buf * KBUF;

        #pragma unroll
        for (int ks = 0; ks < 8; ++ks) {
            uint32_t bf[4];
            ldsm4t(bf, sVb + boff2t + ks * (16 * PQ_ * 2));
            uint32_t af[2][4];
            #pragma unroll
            for (int mi = 0; mi < 2; ++mi)
                ldsm4(af[mi], sS + aoff2 + (uint32_t)kc * 2
                              + mi * (16 * PS_ * 2) + ks * 32);
            #pragma unroll
            for (int mi = 0; mi < 2; ++mi) {
                mma16816(accy[mi][0], af[mi], bf[0], bf[1]);
                mma16816(accy[mi][1], af[mi], bf[2], bf[3]);
            }
        }

        if (t + 1 < 8) CP_WAIT0();
        __syncthreads();
    }

    // epilogue: Y -> fp16 hi (stride 1024)
    #pragma unroll
    for (int mi = 0; mi < 2; ++mi) {
        #pragma unroll
        for (int ni = 0; ni < 2; ++ni) {
            int ch = hc + wn2 + ni * 8 + ((lane & 3) << 1);
            #pragma unroll
            for (int hv = 0; hv < 2; ++hv) {
                int rq = q0 + wm2 + mi * 16 + g + hv * 8;
                size_t rg = ((size_t)b * T_ + rq) * C_;
                *(ushort2*)&Yh[rg + ch] =
                    make_ushort2(fp16hi(accy[mi][ni][hv * 2 + 0]),
                                 fp16hi(accy[mi][ni][hv * 2 + 1]));
            }
        }
    }
}

// ---------------------------------------------------------------------------
extern "C" void kernel_launch(void* const* d_in, const int* in_sizes, int n_in,
                              void* d_out, int out_size)
{
    const float* x      = (const float*)d_in[0];
    const float* w_attn = (const float*)d_in[1];
    const float* b_attn = (const float*)d_in[2];
    const float* w_proj = (const float*)d_in[3];
    const float* b_proj = (const float*)d_in[4];
    float* out = (float*)d_out;

    ushort_t *qkvh, *yh, *xh, *wa, *wp;
    cudaGetSymbolAddress((void**)&qkvh, g_qkvh);
    cudaGetSymbolAddress((void**)&yh,   g_yh);
    cudaGetSymbolAddress((void**)&xh,   g_xh);
    cudaGetSymbolAddress((void**)&wa,   g_wa);
    cudaGetSymbolAddress((void**)&wp,   g_wp);

    const int smem1 = 4 * ABUF * 2;   // 40960 B
    cudaFuncSetAttribute(gemm_mma_kernel<2>,
                         cudaFuncAttributeMaxDynamicSharedMemorySize, smem1);
    cudaFuncSetAttribute(gemm_mma_kernel<0>,
                         cudaFuncAttributeMaxDynamicSharedMemorySize, smem1);
    cudaFuncSetAttribute(fused_attn_mma_kernel,
                         cudaFuncAttributeMaxDynamicSharedMemorySize,
                         (int)sizeof(SmemAttn5));

    // prep
    prep_xh_kernel<<<B_ * T_, 256>>>(x, xh);
    prep_wt_kernel<<<dim3(C3_ / 32, C_ / 32), 256>>>(w_attn, wa, C3_);
    prep_wt_kernel<<<dim3(C_ / 32, C_ / 32), 256>>>(w_proj, wp, C_);

    // 1) QKV projection: single 1-term launch -> fp16 hi
    gemm_mma_kernel<2><<<dim3(24, 64), 256, smem1>>>(
        xh, wa, b_attn, qkvh, C3_, 0, C_);

    // 2) fused attention (smem-resident S), Y -> fp16 hi
    fused_attn_mma_kernel<<<dim3(16, 128), 256, sizeof(SmemAttn5)>>>(qkvh, yh);

    // 3) output projection (fp32 out)
    gemm_mma_kernel<0><<<dim3(8, 64), 256, smem1>>>(
        yh, wp, b_proj, out, C_, 0, C_);
}